// round 8
// baseline (speedup 1.0000x reference)
#include <cuda_runtime.h>
#include <math.h>
#include <stdint.h>

// ============================================================================
// EventTransformer — ragged formulation; tf32 mma.sync GEMMs (128x256 CTA,
// 64x64 warp tiles, LN fused into DM-wide epilogues); tf32 mma attention.
// ============================================================================

#define D_INP 128
#define DM    256
#define NH    4
#define HDIM  64
#define NL    4
#define DFF   1024
#define NMAXD 65536
#define BMAXD 128
#define NTMAX (NMAXD + BMAXD)

__device__ float g_tok[(size_t)NTMAX * DM];      // residual h (fp32)
__device__ float g_buf[(size_t)NTMAX * DM];      // LN out / posenc / cls (tf32 bits)
__device__ float g_qkv[(size_t)NTMAX * 3 * DM];  // QKV (tf32 bits)
__device__ float g_att[(size_t)NTMAX * DM];      // attn out (tf32) / embed acc
__device__ float g_ff [(size_t)NTMAX * DFF];     // FF hidden (tf32) / embed stage
__device__ int   g_start[BMAXD + 1];

// converted weights scratch (tf32 bit patterns)
#define W_IN   0
#define W_GEO  (W_IN   + DM * D_INP)
#define W_QKV  (W_GEO  + DM * DM)
#define W_OUT  (W_QKV  + NL * 3 * DM * DM)
#define W_FF1  (W_OUT  + NL * DM * DM)
#define W_FF2  (W_FF1  + NL * DFF * DM)
#define W_HEAD (W_FF2  + NL * DM * DFF)
#define W_TOT  (W_HEAD + DM * DM)
__device__ float g_wts[W_TOT];

// ---------------------------------------------------------------------------
__device__ __forceinline__ uint32_t smem_u32(const void* p) {
    uint32_t a;
    asm("{ .reg .u64 t; cvta.to.shared.u64 t, %1; cvt.u32.u64 %0, t; }" : "=r"(a) : "l"(p));
    return a;
}
__device__ __forceinline__ unsigned f2tf(float x) {
    unsigned u;
    asm("cvt.rna.tf32.f32 %0, %1;" : "=r"(u) : "f"(x));
    return u;
}
__device__ __forceinline__ float f2tff(float x) {
    return __uint_as_float(f2tf(x));
}
__device__ __forceinline__ void mma_tf32(float c[4], const unsigned a[4], const unsigned b[2]) {
    asm volatile(
        "mma.sync.aligned.m16n8k8.row.col.f32.tf32.tf32.f32 "
        "{%0,%1,%2,%3}, {%4,%5,%6,%7}, {%8,%9}, {%0,%1,%2,%3};"
        : "+f"(c[0]), "+f"(c[1]), "+f"(c[2]), "+f"(c[3])
        : "r"(a[0]), "r"(a[1]), "r"(a[2]), "r"(a[3]), "r"(b[0]), "r"(b[1]));
}
#define CPA16(dst, src) \
    asm volatile("cp.async.cg.shared.global [%0], [%1], 16;" \
                 :: "r"(dst), "l"(src) : "memory")
#define CPA_COMMIT() asm volatile("cp.async.commit_group;" ::: "memory")
#define CPA_WAIT1()  asm volatile("cp.async.wait_group 1;" ::: "memory")

// ---------------------------------------------------------------------------
__global__ void cvt_kernel(const float* __restrict__ src, float* __restrict__ dst, int n) {
    int i = blockIdx.x * 256 + threadIdx.x;
    if (i < n) dst[i] = f2tff(src[i]);
}

__global__ void starts_kernel(const int* __restrict__ ev, int N, int B) {
    int b = blockIdx.x * blockDim.x + threadIdx.x;
    if (b > B) return;
    if (b == B) { g_start[B] = N; return; }
    int lo = 0, hi = N;
    while (lo < hi) {
        int mid = (lo + hi) >> 1;
        if (ev[mid] < b) lo = mid + 1; else hi = mid;
    }
    g_start[b] = lo;
}

__global__ void posenc_kernel(const float* __restrict__ geom) {
    int i = blockIdx.x;
    int c = threadIdx.x;
    float val = 0.f;
    if (c < 252) {
        int dax  = c / 84;
        int rem  = c % 84;
        int band = rem >> 1;
        int s    = rem & 1;
        float f   = exp2f((float)band * 0.08102263646065820f); // log2(10)/41
        float ang = 6.283185307179586f * geom[i * 3 + dax] * f;
        val = s ? cosf(ang) : sinf(ang);
    }
    g_buf[(size_t)i * DM + c] = f2tff(val);
}

// ---------------------------------------------------------------------------
// tf32 GEMM v4: C[M,N] = (RES?C:0) + A[M,K] @ W[N,K]^T + bias[N].
// BM=128, BN=256, BK=32; 8 warps, warp tile 64x64 (2x4). 3-stage cp.async
// pipeline (wait_group(1) + barrier before compute — cp.async data from other
// threads is only visible after a barrier that FOLLOWS the wait).
// LNF: fused LayerNorm over the full N=256 row (requires grid.x==1):
//   h = value (stored to C), Y = tf32(LN(h; lnw, lnb)).
// M%128==0, N%256==0, K%32==0 required.
// ---------------------------------------------------------------------------
#define G4STRIDE 36
#define G4ROWS   384                       // 128 A rows + 256 W rows
#define G4STAGEF (G4ROWS * G4STRIDE)       // floats per stage
#define G4SMEM   (3 * G4STAGEF * 4)        // bytes

template<bool RELU, bool RES, bool CVT, bool LNF>
__global__ void __launch_bounds__(256) gemm4(
        const float* __restrict__ A, const float* __restrict__ W,
        const float* __restrict__ bias, float* __restrict__ C,
        const float* __restrict__ lnw, const float* __restrict__ lnb,
        float* __restrict__ Y,
        int M, int N, int K) {
    extern __shared__ float sm[];
    const uint32_t sb = smem_u32(sm);

    const int t = threadIdx.x;
    const int lane = t & 31, gid = lane >> 2, tig = lane & 3;
    const int wid = t >> 5;
    const int wm = (wid & 1) * 64;
    const int wn = (wid >> 1) * 64;
    const int wcol = wid >> 1;
    const int m0 = blockIdx.y * 128, n0 = blockIdx.x * 256;
    const int nc = K >> 5;

    auto load_chunk = [&](int c, int s) {
        int k0 = c * 32;
        uint32_t base = sb + (s * G4STAGEF) * 4;
#pragma unroll
        for (int i = 0; i < 12; i++) {
            int u = i * 256 + t;
            int r = u >> 3, q = u & 7;          // r 0..383, q 0..7
            const float* src = (r < 128)
                ? (A + (size_t)(m0 + r) * K + k0 + q * 4)
                : (W + (size_t)(n0 + r - 128) * K + k0 + q * 4);
            CPA16(base + (r * G4STRIDE + q * 4) * 4, src);
        }
    };

    load_chunk(0, 0); CPA_COMMIT();
    load_chunk(1, 1); CPA_COMMIT();   // K >= 64 always

    float acc[4][8][4];
#pragma unroll
    for (int mi = 0; mi < 4; mi++)
#pragma unroll
        for (int ni = 0; ni < 8; ni++)
#pragma unroll
            for (int j = 0; j < 4; j++) acc[mi][ni][j] = 0.f;

    for (int c = 0; c < nc; c++) {
        CPA_WAIT1();                     // chunk c complete (this thread)
        __syncthreads();                 // ...and visible CTA-wide

        const float* Ab = sm + (c % 3) * G4STAGEF;
        const float* Wb = Ab + 128 * G4STRIDE;
#pragma unroll
        for (int ks = 0; ks < 4; ks++) {
            unsigned a[4][4], b[8][2];
#pragma unroll
            for (int mi = 0; mi < 4; mi++) {
                const float* p = Ab + (wm + mi * 16 + gid) * G4STRIDE + ks * 8 + tig;
                a[mi][0] = __float_as_uint(p[0]);
                a[mi][1] = __float_as_uint(p[8 * G4STRIDE]);
                a[mi][2] = __float_as_uint(p[4]);
                a[mi][3] = __float_as_uint(p[8 * G4STRIDE + 4]);
            }
#pragma unroll
            for (int ni = 0; ni < 8; ni++) {
                const float* p = Wb + (wn + ni * 8 + gid) * G4STRIDE + ks * 8 + tig;
                b[ni][0] = __float_as_uint(p[0]);
                b[ni][1] = __float_as_uint(p[4]);
            }
#pragma unroll
            for (int mi = 0; mi < 4; mi++)
#pragma unroll
                for (int ni = 0; ni < 8; ni++)
                    mma_tf32(acc[mi][ni], a[mi], b[ni]);
        }

        if (c + 2 < nc) load_chunk(c + 2, (c + 2) % 3);
        CPA_COMMIT();                    // unconditional: keeps wait_group(1) valid
    }

    if (!LNF) {
#pragma unroll
        for (int mi = 0; mi < 4; mi++) {
#pragma unroll
            for (int ni = 0; ni < 8; ni++) {
                int r  = m0 + wm + mi * 16 + gid;
                int cn = n0 + wn + ni * 8 + 2 * tig;
                float b0 = bias[cn], b1 = bias[cn + 1];
                {
                    float v0 = acc[mi][ni][0] + b0;
                    float v1 = acc[mi][ni][1] + b1;
                    float* cp = C + (size_t)r * N + cn;
                    if (RES) { v0 += cp[0]; v1 += cp[1]; }
                    if (RELU) { v0 = fmaxf(v0, 0.f); v1 = fmaxf(v1, 0.f); }
                    if (CVT) { v0 = f2tff(v0); v1 = f2tff(v1); }
                    cp[0] = v0; cp[1] = v1;
                }
                {
                    float v0 = acc[mi][ni][2] + b0;
                    float v1 = acc[mi][ni][3] + b1;
                    float* cp = C + (size_t)(r + 8) * N + cn;
                    if (RES) { v0 += cp[0]; v1 += cp[1]; }
                    if (RELU) { v0 = fmaxf(v0, 0.f); v1 = fmaxf(v1, 0.f); }
                    if (CVT) { v0 = f2tff(v0); v1 = f2tff(v1); }
                    cp[0] = v0; cp[1] = v1;
                }
            }
        }
    } else {
        // ---- fused LayerNorm epilogue (N == 256, grid.x == 1) ----
        __syncthreads();                       // smem reuse after mainloop
        float* red = sm;                       // [128 rows][4 warps][2]
        float s[4][2], q[4][2];
#pragma unroll
        for (int mi = 0; mi < 4; mi++) { s[mi][0] = s[mi][1] = q[mi][0] = q[mi][1] = 0.f; }

#pragma unroll
        for (int mi = 0; mi < 4; mi++) {
#pragma unroll
            for (int ni = 0; ni < 8; ni++) {
                int r  = m0 + wm + mi * 16 + gid;
                int cn = wn + ni * 8 + 2 * tig;
                float b0 = bias[cn], b1 = bias[cn + 1];
                float* cp0 = C + (size_t)r * N + cn;
                float* cp1 = C + (size_t)(r + 8) * N + cn;
                float v0 = acc[mi][ni][0] + b0 + (RES ? cp0[0] : 0.f);
                float v1 = acc[mi][ni][1] + b1 + (RES ? cp0[1] : 0.f);
                float v2 = acc[mi][ni][2] + b0 + (RES ? cp1[0] : 0.f);
                float v3 = acc[mi][ni][3] + b1 + (RES ? cp1[1] : 0.f);
                cp0[0] = v0; cp0[1] = v1;
                cp1[0] = v2; cp1[1] = v3;
                acc[mi][ni][0] = v0; acc[mi][ni][1] = v1;
                acc[mi][ni][2] = v2; acc[mi][ni][3] = v3;
                s[mi][0] += v0 + v1;            q[mi][0] += v0 * v0 + v1 * v1;
                s[mi][1] += v2 + v3;            q[mi][1] += v2 * v2 + v3 * v3;
            }
        }
#pragma unroll
        for (int mi = 0; mi < 4; mi++)
#pragma unroll
            for (int hf = 0; hf < 2; hf++) {
                s[mi][hf] += __shfl_xor_sync(0xffffffffu, s[mi][hf], 1);
                s[mi][hf] += __shfl_xor_sync(0xffffffffu, s[mi][hf], 2);
                q[mi][hf] += __shfl_xor_sync(0xffffffffu, q[mi][hf], 1);
                q[mi][hf] += __shfl_xor_sync(0xffffffffu, q[mi][hf], 2);
            }
        if (tig == 0) {
#pragma unroll
            for (int mi = 0; mi < 4; mi++)
#pragma unroll
                for (int hf = 0; hf < 2; hf++) {
                    int rl = wm + mi * 16 + gid + hf * 8;
                    red[rl * 8 + wcol * 2 + 0] = s[mi][hf];
                    red[rl * 8 + wcol * 2 + 1] = q[mi][hf];
                }
        }
        __syncthreads();
#pragma unroll
        for (int mi = 0; mi < 4; mi++) {
#pragma unroll
            for (int hf = 0; hf < 2; hf++) {
                int rl = wm + mi * 16 + gid + hf * 8;
                float su = 0.f, sq = 0.f;
#pragma unroll
                for (int w = 0; w < 4; w++) { su += red[rl * 8 + w * 2]; sq += red[rl * 8 + w * 2 + 1]; }
                float mean = su * (1.f / 256.f);
                float var  = sq * (1.f / 256.f) - mean * mean;
                float rstd = rsqrtf(var + 1e-5f);
                float* yp = Y + (size_t)(m0 + rl) * N;
#pragma unroll
                for (int ni = 0; ni < 8; ni++) {
                    int cn = wn + ni * 8 + 2 * tig;
                    float v0 = acc[mi][ni][hf * 2 + 0];
                    float v1 = acc[mi][ni][hf * 2 + 1];
                    yp[cn]     = f2tff((v0 - mean) * rstd * lnw[cn]     + lnb[cn]);
                    yp[cn + 1] = f2tff((v1 - mean) * rstd * lnw[cn + 1] + lnb[cn + 1]);
                }
            }
        }
    }
}

// ---------------------------------------------------------------------------
__global__ void build_tok(const float* __restrict__ cls, int B) {
    int tk = blockIdx.x;
    __shared__ int sbv;
    if (threadIdx.x == 0) {
        int lo = 0, hi = B - 1;
        while (lo < hi) {
            int mid = (lo + hi + 1) >> 1;
            if (g_start[mid] + mid <= tk) lo = mid; else hi = mid - 1;
        }
        sbv = lo;
    }
    __syncthreads();
    int b = sbv;
    int d = threadIdx.x;
    float v;
    if (tk == g_start[b] + b) v = cls[d];
    else                      v = g_att[(size_t)(tk - b - 1) * DM + d];
    g_tok[(size_t)tk * DM + d] = v;
}

// LN (standalone; used only for layer-0 ln1): fp32 in, tf32 out
__global__ void ln_kernel(const float* __restrict__ x, const float* __restrict__ w,
                          const float* __restrict__ bb, float* __restrict__ y) {
    int row = blockIdx.x;
    int i   = threadIdx.x;
    float v = x[(size_t)row * DM + i];
    __shared__ float red[8];
    float s = v;
#pragma unroll
    for (int o = 16; o; o >>= 1) s += __shfl_xor_sync(0xffffffffu, s, o);
    if ((i & 31) == 0) red[i >> 5] = s;
    __syncthreads();
    float tot = 0.f;
#pragma unroll
    for (int k = 0; k < 8; k++) tot += red[k];
    float mean = tot * (1.f / DM);
    float d = v - mean;
    float s2 = d * d;
#pragma unroll
    for (int o = 16; o; o >>= 1) s2 += __shfl_xor_sync(0xffffffffu, s2, o);
    __syncthreads();
    if ((i & 31) == 0) red[i >> 5] = s2;
    __syncthreads();
    float tv = 0.f;
#pragma unroll
    for (int k = 0; k < 8; k++) tv += red[k];
    float var = tv * (1.f / DM);
    y[(size_t)row * DM + i] = f2tff(d * rsqrtf(var + 1e-5f) * w[i] + bb[i]);
}

// ---------------------------------------------------------------------------
// Ragged flash attention on tf32 mma.sync. grid = (B, NH, MAXQC), 128 threads.
// ---------------------------------------------------------------------------
#define MAXQC 12
#define ASTR  68
#define ATT_SMEM (4 * 64 * ASTR * 4)

__global__ void __launch_bounds__(128) attn_mma() {
    extern __shared__ float asm_[];
    float* Qs = asm_;
    float* Ks = Qs + 64 * ASTR;
    float* Vt = Ks + 64 * ASTR;
    float* Ps = Vt + 64 * ASTR;

    int b  = blockIdx.x, h = blockIdx.y;
    int s0 = g_start[b];
    int L  = g_start[b + 1] - s0 + 1;
    int qc = blockIdx.z * 64;
    if (qc >= L) return;
    int t0 = s0 + b;

    int t = threadIdx.x, lane = t & 31, wid = t >> 5;
    int gid = lane >> 2, tig = lane & 3;
    int wm = wid * 16;
    int lr = t >> 1, lc = (t & 1) * 32;

    {
        bool v = (qc + lr) < L;
        const float* qp = g_qkv + (size_t)(t0 + qc + lr) * 768 + h * HDIM + lc;
        float* d = Qs + lr * ASTR + lc;
#pragma unroll
        for (int u = 0; u < 8; u++) {
            float4 q4 = v ? *(const float4*)(qp + u * 4) : make_float4(0, 0, 0, 0);
            d[u * 4 + 0] = q4.x; d[u * 4 + 1] = q4.y;
            d[u * 4 + 2] = q4.z; d[u * 4 + 3] = q4.w;
        }
    }

    float mr0 = -1e30f, mr1 = -1e30f, l0 = 0.f, l1 = 0.f;
    float O[8][4];
#pragma unroll
    for (int ni = 0; ni < 8; ni++)
#pragma unroll
        for (int j = 0; j < 4; j++) O[ni][j] = 0.f;

    const float scale = 0.125f;

    for (int kc = 0; kc < L; kc += 64) {
        __syncthreads();
        {
            bool v = (kc + lr) < L;
            const float* kp = g_qkv + (size_t)(t0 + kc + lr) * 768 + 256 + h * HDIM + lc;
            const float* vp = kp + 256;
            float* kd = Ks + lr * ASTR + lc;
#pragma unroll
            for (int u = 0; u < 8; u++) {
                float4 k4 = v ? *(const float4*)(kp + u * 4) : make_float4(0, 0, 0, 0);
                kd[u * 4 + 0] = k4.x; kd[u * 4 + 1] = k4.y;
                kd[u * 4 + 2] = k4.z; kd[u * 4 + 3] = k4.w;
                float4 v4 = v ? *(const float4*)(vp + u * 4) : make_float4(0, 0, 0, 0);
                Vt[(lc + u * 4 + 0) * ASTR + lr] = v4.x;
                Vt[(lc + u * 4 + 1) * ASTR + lr] = v4.y;
                Vt[(lc + u * 4 + 2) * ASTR + lr] = v4.z;
                Vt[(lc + u * 4 + 3) * ASTR + lr] = v4.w;
            }
        }
        __syncthreads();

        float S[8][4];
#pragma unroll
        for (int ni = 0; ni < 8; ni++)
#pragma unroll
            for (int j = 0; j < 4; j++) S[ni][j] = 0.f;
#pragma unroll
        for (int ks = 0; ks < 8; ks++) {
            unsigned a[4];
            const float* qb = Qs + (wm + gid) * ASTR + ks * 8 + tig;
            a[0] = __float_as_uint(qb[0]);
            a[1] = __float_as_uint(qb[8 * ASTR]);
            a[2] = __float_as_uint(qb[4]);
            a[3] = __float_as_uint(qb[8 * ASTR + 4]);
#pragma unroll
            for (int ni = 0; ni < 8; ni++) {
                unsigned bb[2];
                const float* kb = Ks + (ni * 8 + gid) * ASTR + ks * 8 + tig;
                bb[0] = __float_as_uint(kb[0]);
                bb[1] = __float_as_uint(kb[4]);
                mma_tf32(S[ni], a, bb);
            }
        }

        float rm0 = -1e30f, rm1 = -1e30f;
#pragma unroll
        for (int ni = 0; ni < 8; ni++) {
            int j0 = kc + ni * 8 + 2 * tig;
            bool v0 = j0 < L, v1 = (j0 + 1) < L;
            S[ni][0] = v0 ? S[ni][0] * scale : -1e30f;
            S[ni][1] = v1 ? S[ni][1] * scale : -1e30f;
            S[ni][2] = v0 ? S[ni][2] * scale : -1e30f;
            S[ni][3] = v1 ? S[ni][3] * scale : -1e30f;
            rm0 = fmaxf(rm0, fmaxf(S[ni][0], S[ni][1]));
            rm1 = fmaxf(rm1, fmaxf(S[ni][2], S[ni][3]));
        }
        rm0 = fmaxf(rm0, __shfl_xor_sync(0xffffffffu, rm0, 1));
        rm0 = fmaxf(rm0, __shfl_xor_sync(0xffffffffu, rm0, 2));
        rm1 = fmaxf(rm1, __shfl_xor_sync(0xffffffffu, rm1, 1));
        rm1 = fmaxf(rm1, __shfl_xor_sync(0xffffffffu, rm1, 2));
        float mn0 = fmaxf(mr0, rm0), mn1 = fmaxf(mr1, rm1);
        float cr0 = expf(mr0 - mn0), cr1 = expf(mr1 - mn1);
        float sum0 = 0.f, sum1 = 0.f;
        float* pr0 = Ps + (wm + gid) * ASTR;
        float* pr1 = Ps + (wm + gid + 8) * ASTR;
#pragma unroll
        for (int ni = 0; ni < 8; ni++) {
            int col = ni * 8 + 2 * tig;
            float p0 = expf(S[ni][0] - mn0);
            float p1 = expf(S[ni][1] - mn0);
            float p2 = expf(S[ni][2] - mn1);
            float p3 = expf(S[ni][3] - mn1);
            sum0 += p0 + p1; sum1 += p2 + p3;
            pr0[col] = f2tff(p0); pr0[col + 1] = f2tff(p1);
            pr1[col] = f2tff(p2); pr1[col + 1] = f2tff(p3);
        }
        sum0 += __shfl_xor_sync(0xffffffffu, sum0, 1);
        sum0 += __shfl_xor_sync(0xffffffffu, sum0, 2);
        sum1 += __shfl_xor_sync(0xffffffffu, sum1, 1);
        sum1 += __shfl_xor_sync(0xffffffffu, sum1, 2);
        l0 = l0 * cr0 + sum0;
        l1 = l1 * cr1 + sum1;
        mr0 = mn0; mr1 = mn1;
#pragma unroll
        for (int ni = 0; ni < 8; ni++) {
            O[ni][0] *= cr0; O[ni][1] *= cr0;
            O[ni][2] *= cr1; O[ni][3] *= cr1;
        }
        __syncwarp();

#pragma unroll
        for (int ks = 0; ks < 8; ks++) {
            unsigned a[4];
            const float* pb = Ps + (wm + gid) * ASTR + ks * 8 + tig;
            a[0] = __float_as_uint(pb[0]);
            a[1] = __float_as_uint(pb[8 * ASTR]);
            a[2] = __float_as_uint(pb[4]);
            a[3] = __float_as_uint(pb[8 * ASTR + 4]);
#pragma unroll
            for (int ni = 0; ni < 8; ni++) {
                unsigned bb[2];
                const float* vb = Vt + (ni * 8 + gid) * ASTR + ks * 8 + tig;
                bb[0] = __float_as_uint(vb[0]);
                bb[1] = __float_as_uint(vb[4]);
                mma_tf32(O[ni], a, bb);
            }
        }
        __syncwarp();
    }

    float inv0 = 1.f / l0, inv1 = 1.f / l1;
    int q0 = qc + wm + gid, q1 = q0 + 8;
#pragma unroll
    for (int ni = 0; ni < 8; ni++) {
        int col = h * HDIM + ni * 8 + 2 * tig;
        if (q0 < L) {
            float* op = g_att + (size_t)(t0 + q0) * DM + col;
            op[0] = f2tff(O[ni][0] * inv0); op[1] = f2tff(O[ni][1] * inv0);
        }
        if (q1 < L) {
            float* op = g_att + (size_t)(t0 + q1) * DM + col;
            op[0] = f2tff(O[ni][2] * inv1); op[1] = f2tff(O[ni][3] * inv1);
        }
    }
}

// ---------------------------------------------------------------------------
__global__ void gather_cls() {
    int b = blockIdx.x, d = threadIdx.x;
    g_buf[(size_t)b * DM + d] = f2tff(g_tok[(size_t)(g_start[b] + b) * DM + d]);
}

__global__ void head2_kernel(const float* __restrict__ hid, const float* __restrict__ w2,
                             const float* __restrict__ b2, float* __restrict__ out, int B) {
    int t = blockIdx.x * blockDim.x + threadIdx.x;
    if (t >= B * 2) return;
    int b = t >> 1, j = t & 1;
    const float* hr = hid + (size_t)b * DM;
    const float* wr = w2 + (size_t)j * DM;
    float s = 0.f;
#pragma unroll 8
    for (int k = 0; k < DM; k++) s += hr[k] * wr[k];
    out[t] = s + b2[j];
}

// ---------------------------------------------------------------------------
extern "C" void kernel_launch(void* const* d_in, const int* in_sizes, int n_in,
                              void* d_out, int out_size) {
    const float* dom_emb = (const float*)d_in[0];
    const int*   ev      = (const int*)  d_in[1];
    const float* geom    = (const float*)d_in[3];
    const float* in_w    = (const float*)d_in[4];
    const float* in_b    = (const float*)d_in[5];
    const float* geo_w   = (const float*)d_in[6];
    const float* geo_b   = (const float*)d_in[7];
    const float* cls     = (const float*)d_in[8];
    const float* qkv_w   = (const float*)d_in[9];
    const float* qkv_b   = (const float*)d_in[10];
    const float* out_w   = (const float*)d_in[11];
    const float* out_b   = (const float*)d_in[12];
    const float* ln1w    = (const float*)d_in[13];
    const float* ln1b    = (const float*)d_in[14];
    const float* ln2w    = (const float*)d_in[15];
    const float* ln2b    = (const float*)d_in[16];
    const float* ffw1    = (const float*)d_in[17];
    const float* ffb1    = (const float*)d_in[18];
    const float* ffw2    = (const float*)d_in[19];
    const float* ffb2    = (const float*)d_in[20];
    const float* hw1     = (const float*)d_in[21];
    const float* hb1     = (const float*)d_in[22];
    const float* hw2     = (const float*)d_in[23];
    const float* hb2     = (const float*)d_in[24];
    float* out = (float*)d_out;

    int N  = in_sizes[0] / D_INP;
    int B  = out_size / 2;
    int NT = N + B;

    float *p_tok, *p_buf, *p_qkv, *p_att, *p_ff, *p_w;
    cudaGetSymbolAddress((void**)&p_tok, g_tok);
    cudaGetSymbolAddress((void**)&p_buf, g_buf);
    cudaGetSymbolAddress((void**)&p_qkv, g_qkv);
    cudaGetSymbolAddress((void**)&p_att, g_att);
    cudaGetSymbolAddress((void**)&p_ff,  g_ff);
    cudaGetSymbolAddress((void**)&p_w,   g_wts);

    static bool attrs_done = false;
    if (!attrs_done) {
        cudaFuncSetAttribute(gemm4<false, false, false, false>, cudaFuncAttributeMaxDynamicSharedMemorySize, G4SMEM);
        cudaFuncSetAttribute(gemm4<false, true,  false, false>, cudaFuncAttributeMaxDynamicSharedMemorySize, G4SMEM);
        cudaFuncSetAttribute(gemm4<false, false, true,  false>, cudaFuncAttributeMaxDynamicSharedMemorySize, G4SMEM);
        cudaFuncSetAttribute(gemm4<false, true,  false, true >, cudaFuncAttributeMaxDynamicSharedMemorySize, G4SMEM);
        cudaFuncSetAttribute(gemm4<true,  false, true,  false>, cudaFuncAttributeMaxDynamicSharedMemorySize, G4SMEM);
        cudaFuncSetAttribute(gemm4<true,  false, false, false>, cudaFuncAttributeMaxDynamicSharedMemorySize, G4SMEM);
        cudaFuncSetAttribute(attn_mma, cudaFuncAttributeMaxDynamicSharedMemorySize, ATT_SMEM);
        attrs_done = true;
    }

    auto cvt = [&](const float* src, float* dst, int n) {
        cvt_kernel<<<(n + 255) / 256, 256>>>(src, dst, n);
    };
    cvt(in_w,  p_w + W_IN,   DM * D_INP);
    cvt(geo_w, p_w + W_GEO,  DM * DM);
    cvt(qkv_w, p_w + W_QKV,  NL * 3 * DM * DM);
    cvt(out_w, p_w + W_OUT,  NL * DM * DM);
    cvt(ffw1,  p_w + W_FF1,  NL * DFF * DM);
    cvt(ffw2,  p_w + W_FF2,  NL * DM * DFF);
    cvt(hw1,   p_w + W_HEAD, DM * DM);
    cvt(dom_emb, p_ff, N * D_INP);   // stage converted embeddings in g_ff

    int mg  = NT / 128;   // NT = 513*128
    int mgN = N / 128;

    starts_kernel<<<1, 256>>>(ev, N, B);
    posenc_kernel<<<N, 256>>>(geom);
    gemm4<false, false, false, false><<<dim3(1, mgN), 256, G4SMEM>>>(
        p_ff,  p_w + W_IN,  in_b,  p_att, nullptr, nullptr, nullptr, N, DM, D_INP);
    gemm4<false, true,  false, false><<<dim3(1, mgN), 256, G4SMEM>>>(
        p_buf, p_w + W_GEO, geo_b, p_att, nullptr, nullptr, nullptr, N, DM, DM);
    build_tok<<<NT, 256>>>(cls, B);
    ln_kernel<<<NT, 256>>>(p_tok, ln1w, ln1b, p_buf);   // layer-0 ln1

    for (int l = 0; l < NL; l++) {
        gemm4<false, false, true, false><<<dim3(3, mg), 256, G4SMEM>>>(
            p_buf, p_w + W_QKV + (size_t)l * 3 * DM * DM, qkv_b + (size_t)l * 3 * DM,
            p_qkv, nullptr, nullptr, nullptr, NT, 3 * DM, DM);
        attn_mma<<<dim3(B, NH, MAXQC), 128, ATT_SMEM>>>();
        // out-proj + residual + fused ln2 -> p_buf
        gemm4<false, true, false, true><<<dim3(1, mg), 256, G4SMEM>>>(
            p_att, p_w + W_OUT + (size_t)l * DM * DM, out_b + (size_t)l * DM,
            p_tok, ln2w + l * DM, ln2b + l * DM, p_buf, NT, DM, DM);
        gemm4<true, false, true, false><<<dim3(DFF / 256, mg), 256, G4SMEM>>>(
            p_buf, p_w + W_FF1 + (size_t)l * DFF * DM, ffb1 + (size_t)l * DFF,
            p_ff, nullptr, nullptr, nullptr, NT, DFF, DM);
        if (l < NL - 1) {
            // ff2 + residual + fused ln1 of next layer -> p_buf
            gemm4<false, true, false, true><<<dim3(1, mg), 256, G4SMEM>>>(
                p_ff, p_w + W_FF2 + (size_t)l * DM * DFF, ffb2 + (size_t)l * DM,
                p_tok, ln1w + (l + 1) * DM, ln1b + (l + 1) * DM, p_buf, NT, DM, DFF);
        } else {
            gemm4<false, true, false, false><<<dim3(1, mg), 256, G4SMEM>>>(
                p_ff, p_w + W_FF2 + (size_t)l * DM * DFF, ffb2 + (size_t)l * DM,
                p_tok, nullptr, nullptr, nullptr, NT, DM, DFF);
        }
    }

    gather_cls<<<B, 256>>>();
    gemm4<true, false, false, false><<<dim3(1, 1), 256, G4SMEM>>>(
        p_buf, p_w + W_HEAD, hb1, p_att, nullptr, nullptr, nullptr, B, DM, DM);
    head2_kernel<<<1, 256>>>(p_att, hw2, hb2, out, B);
}

// round 9
// speedup vs baseline: 1.0344x; 1.0344x over previous
#include <cuda_runtime.h>
#include <math.h>
#include <stdint.h>

// ============================================================================
// EventTransformer — ragged formulation; tf32 mma.sync GEMMs with all inputs
// pre-converted to tf32 (zero cvt in hot loops); tf32 mma flash attention
// with __expf softmax. (R7 GEMM config — best known: occupancy > reuse.)
// ============================================================================

#define D_INP 128
#define DM    256
#define NH    4
#define HDIM  64
#define NL    4
#define DFF   1024
#define NMAXD 65536
#define BMAXD 128
#define NTMAX (NMAXD + BMAXD)

__device__ float g_tok[(size_t)NTMAX * DM];      // residual h (fp32)
__device__ float g_buf[(size_t)NTMAX * DM];      // LN out / posenc / cls (tf32 bits)
__device__ float g_qkv[(size_t)NTMAX * 3 * DM];  // QKV (tf32 bits)
__device__ float g_att[(size_t)NTMAX * DM];      // attn out (tf32) / embed acc
__device__ float g_ff [(size_t)NTMAX * DFF];     // FF hidden (tf32) / embed stage
__device__ int   g_start[BMAXD + 1];

// converted weights scratch (tf32 bit patterns)
#define W_IN   0
#define W_GEO  (W_IN   + DM * D_INP)
#define W_QKV  (W_GEO  + DM * DM)
#define W_OUT  (W_QKV  + NL * 3 * DM * DM)
#define W_FF1  (W_OUT  + NL * DM * DM)
#define W_FF2  (W_FF1  + NL * DFF * DM)
#define W_HEAD (W_FF2  + NL * DM * DFF)
#define W_TOT  (W_HEAD + DM * DM)
__device__ float g_wts[W_TOT];

// ---------------------------------------------------------------------------
__device__ __forceinline__ uint32_t smem_u32(const void* p) {
    uint32_t a;
    asm("{ .reg .u64 t; cvta.to.shared.u64 t, %1; cvt.u32.u64 %0, t; }" : "=r"(a) : "l"(p));
    return a;
}
__device__ __forceinline__ unsigned f2tf(float x) {
    unsigned u;
    asm("cvt.rna.tf32.f32 %0, %1;" : "=r"(u) : "f"(x));
    return u;
}
__device__ __forceinline__ float f2tff(float x) {
    return __uint_as_float(f2tf(x));
}
__device__ __forceinline__ void mma_tf32(float c[4], const unsigned a[4], const unsigned b[2]) {
    asm volatile(
        "mma.sync.aligned.m16n8k8.row.col.f32.tf32.tf32.f32 "
        "{%0,%1,%2,%3}, {%4,%5,%6,%7}, {%8,%9}, {%0,%1,%2,%3};"
        : "+f"(c[0]), "+f"(c[1]), "+f"(c[2]), "+f"(c[3])
        : "r"(a[0]), "r"(a[1]), "r"(a[2]), "r"(a[3]), "r"(b[0]), "r"(b[1]));
}
#define CPA16(dst, src) \
    asm volatile("cp.async.cg.shared.global [%0], [%1], 16;" \
                 :: "r"(dst), "l"(src) : "memory")
#define CPA_COMMIT() asm volatile("cp.async.commit_group;" ::: "memory")
#define CPA_WAIT1()  asm volatile("cp.async.wait_group 1;" ::: "memory")

// ---------------------------------------------------------------------------
__global__ void cvt_kernel(const float* __restrict__ src, float* __restrict__ dst, int n) {
    int i = blockIdx.x * 256 + threadIdx.x;
    if (i < n) dst[i] = f2tff(src[i]);
}

__global__ void starts_kernel(const int* __restrict__ ev, int N, int B) {
    int b = blockIdx.x * blockDim.x + threadIdx.x;
    if (b > B) return;
    if (b == B) { g_start[B] = N; return; }
    int lo = 0, hi = N;
    while (lo < hi) {
        int mid = (lo + hi) >> 1;
        if (ev[mid] < b) lo = mid + 1; else hi = mid;
    }
    g_start[b] = lo;
}

__global__ void posenc_kernel(const float* __restrict__ geom) {
    int i = blockIdx.x;
    int c = threadIdx.x;
    float val = 0.f;
    if (c < 252) {
        int dax  = c / 84;
        int rem  = c % 84;
        int band = rem >> 1;
        int s    = rem & 1;
        float f   = exp2f((float)band * 0.08102263646065820f); // log2(10)/41
        float ang = 6.283185307179586f * geom[i * 3 + dax] * f;
        val = s ? cosf(ang) : sinf(ang);
    }
    g_buf[(size_t)i * DM + c] = f2tff(val);
}

// ---------------------------------------------------------------------------
// tf32 GEMM (R7 config): C[M,N] = (RES?C:0) + A[M,K] @ W[N,K]^T + bias[N].
// BM=BN=128, BK=32; 8 warps (64x32 warp tiles); 3-stage cp.async pipeline.
// wait_group(1) + __syncthreads BEFORE compute: cp.async data copied by other
// threads is only visible after a barrier that follows the wait.
// M%128==0, N%128==0, K%32==0 required.
// ---------------------------------------------------------------------------
#define GSTRIDE 36
#define GTILEF  (128 * GSTRIDE)       // floats per operand tile
#define GSTAGEF (2 * GTILEF)          // floats per stage
#define GSMEM   (3 * GSTAGEF * 4)     // bytes

template<bool RELU, bool RES, bool CVT>
__global__ void __launch_bounds__(256, 2) gemm3(
        const float* __restrict__ A, const float* __restrict__ W,
        const float* __restrict__ bias, float* __restrict__ C,
        int M, int N, int K) {
    extern __shared__ float sm[];
    const uint32_t sb = smem_u32(sm);

    const int t = threadIdx.x;
    const int lane = t & 31, gid = lane >> 2, tig = lane & 3;
    const int wid = t >> 5;
    const int wm = (wid & 1) * 64;
    const int wn = (wid >> 1) * 32;
    const int m0 = blockIdx.y * 128, n0 = blockIdx.x * 128;
    const int nc = K >> 5;

    auto load_chunk = [&](int c, int s) {
        int k0 = c * 32;
        uint32_t abase = sb + (s * GSTAGEF) * 4;
        uint32_t wbase = abase + GTILEF * 4;
#pragma unroll
        for (int i = 0; i < 4; i++) {
            int u = i * 256 + t;
            int r = u >> 3, q = u & 7;
            CPA16(abase + (r * GSTRIDE + q * 4) * 4, A + (size_t)(m0 + r) * K + k0 + q * 4);
            CPA16(wbase + (r * GSTRIDE + q * 4) * 4, W + (size_t)(n0 + r) * K + k0 + q * 4);
        }
    };

    load_chunk(0, 0); CPA_COMMIT();
    load_chunk(1, 1); CPA_COMMIT();   // K >= 64 always

    float acc[4][4][4];
#pragma unroll
    for (int mi = 0; mi < 4; mi++)
#pragma unroll
        for (int ni = 0; ni < 4; ni++)
#pragma unroll
            for (int j = 0; j < 4; j++) acc[mi][ni][j] = 0.f;

    for (int c = 0; c < nc; c++) {
        CPA_WAIT1();                     // chunk c's group complete (this thread)
        __syncthreads();                 // ...and visible CTA-wide

        const float* Ab = sm + (c % 3) * GSTAGEF;
        const float* Wb = Ab + GTILEF;
#pragma unroll
        for (int ks = 0; ks < 4; ks++) {
            unsigned a[4][4], b[4][2];
#pragma unroll
            for (int mi = 0; mi < 4; mi++) {
                const float* p = Ab + (wm + mi * 16 + gid) * GSTRIDE + ks * 8 + tig;
                a[mi][0] = __float_as_uint(p[0]);
                a[mi][1] = __float_as_uint(p[8 * GSTRIDE]);
                a[mi][2] = __float_as_uint(p[4]);
                a[mi][3] = __float_as_uint(p[8 * GSTRIDE + 4]);
            }
#pragma unroll
            for (int ni = 0; ni < 4; ni++) {
                const float* p = Wb + (wn + ni * 8 + gid) * GSTRIDE + ks * 8 + tig;
                b[ni][0] = __float_as_uint(p[0]);
                b[ni][1] = __float_as_uint(p[4]);
            }
#pragma unroll
            for (int mi = 0; mi < 4; mi++)
#pragma unroll
                for (int ni = 0; ni < 4; ni++)
                    mma_tf32(acc[mi][ni], a[mi], b[ni]);
        }

        if (c + 2 < nc) load_chunk(c + 2, (c + 2) % 3);
        CPA_COMMIT();                    // unconditional: keeps wait_group(1) valid
    }

#pragma unroll
    for (int mi = 0; mi < 4; mi++) {
#pragma unroll
        for (int ni = 0; ni < 4; ni++) {
            int r  = m0 + wm + mi * 16 + gid;
            int cn = n0 + wn + ni * 8 + 2 * tig;
            float b0 = bias[cn], b1 = bias[cn + 1];
            {
                float v0 = acc[mi][ni][0] + b0;
                float v1 = acc[mi][ni][1] + b1;
                float* cp = C + (size_t)r * N + cn;
                if (RES) { v0 += cp[0]; v1 += cp[1]; }
                if (RELU) { v0 = fmaxf(v0, 0.f); v1 = fmaxf(v1, 0.f); }
                if (CVT) { v0 = f2tff(v0); v1 = f2tff(v1); }
                cp[0] = v0; cp[1] = v1;
            }
            {
                float v0 = acc[mi][ni][2] + b0;
                float v1 = acc[mi][ni][3] + b1;
                float* cp = C + (size_t)(r + 8) * N + cn;
                if (RES) { v0 += cp[0]; v1 += cp[1]; }
                if (RELU) { v0 = fmaxf(v0, 0.f); v1 = fmaxf(v1, 0.f); }
                if (CVT) { v0 = f2tff(v0); v1 = f2tff(v1); }
                cp[0] = v0; cp[1] = v1;
            }
        }
    }
}

// ---------------------------------------------------------------------------
__global__ void build_tok(const float* __restrict__ cls, int B) {
    int tk = blockIdx.x;
    __shared__ int sbv;
    if (threadIdx.x == 0) {
        int lo = 0, hi = B - 1;
        while (lo < hi) {
            int mid = (lo + hi + 1) >> 1;
            if (g_start[mid] + mid <= tk) lo = mid; else hi = mid - 1;
        }
        sbv = lo;
    }
    __syncthreads();
    int b = sbv;
    int d = threadIdx.x;
    float v;
    if (tk == g_start[b] + b) v = cls[d];
    else                      v = g_att[(size_t)(tk - b - 1) * DM + d];
    g_tok[(size_t)tk * DM + d] = v;
}

// LN: reads fp32 h, writes tf32-converted output (feeds GEMM A directly)
__global__ void ln_kernel(const float* __restrict__ x, const float* __restrict__ w,
                          const float* __restrict__ bb, float* __restrict__ y) {
    int row = blockIdx.x;
    int i   = threadIdx.x;
    float v = x[(size_t)row * DM + i];
    __shared__ float red[8];
    float s = v;
#pragma unroll
    for (int o = 16; o; o >>= 1) s += __shfl_xor_sync(0xffffffffu, s, o);
    if ((i & 31) == 0) red[i >> 5] = s;
    __syncthreads();
    float tot = 0.f;
#pragma unroll
    for (int k = 0; k < 8; k++) tot += red[k];
    float mean = tot * (1.f / DM);
    float d = v - mean;
    float s2 = d * d;
#pragma unroll
    for (int o = 16; o; o >>= 1) s2 += __shfl_xor_sync(0xffffffffu, s2, o);
    __syncthreads();
    if ((i & 31) == 0) red[i >> 5] = s2;
    __syncthreads();
    float tv = 0.f;
#pragma unroll
    for (int k = 0; k < 8; k++) tv += red[k];
    float var = tv * (1.f / DM);
    y[(size_t)row * DM + i] = f2tff(d * rsqrtf(var + 1e-5f) * w[i] + bb[i]);
}

// ---------------------------------------------------------------------------
// Ragged flash attention on tf32 mma.sync. grid = (B, NH, MAXQC), 128 threads.
// __expf softmax; P stored raw fp32 (tf32 mma reads high bits — truncation of
// P in [0,1] is <= 2^-10 relative, harmless for softmax weights).
// ---------------------------------------------------------------------------
#define MAXQC 12
#define ASTR  68
#define ATT_SMEM (4 * 64 * ASTR * 4)

__global__ void __launch_bounds__(128) attn_mma() {
    extern __shared__ float asm_[];
    float* Qs = asm_;
    float* Ks = Qs + 64 * ASTR;
    float* Vt = Ks + 64 * ASTR;
    float* Ps = Vt + 64 * ASTR;

    int b  = blockIdx.x, h = blockIdx.y;
    int s0 = g_start[b];
    int L  = g_start[b + 1] - s0 + 1;
    int qc = blockIdx.z * 64;
    if (qc >= L) return;
    int t0 = s0 + b;

    int t = threadIdx.x, lane = t & 31, wid = t >> 5;
    int gid = lane >> 2, tig = lane & 3;
    int wm = wid * 16;
    int lr = t >> 1, lc = (t & 1) * 32;

    {
        bool v = (qc + lr) < L;
        const float* qp = g_qkv + (size_t)(t0 + qc + lr) * 768 + h * HDIM + lc;
        float* d = Qs + lr * ASTR + lc;
#pragma unroll
        for (int u = 0; u < 8; u++) {
            float4 q4 = v ? *(const float4*)(qp + u * 4) : make_float4(0, 0, 0, 0);
            d[u * 4 + 0] = q4.x; d[u * 4 + 1] = q4.y;
            d[u * 4 + 2] = q4.z; d[u * 4 + 3] = q4.w;
        }
    }

    float mr0 = -1e30f, mr1 = -1e30f, l0 = 0.f, l1 = 0.f;
    float O[8][4];
#pragma unroll
    for (int ni = 0; ni < 8; ni++)
#pragma unroll
        for (int j = 0; j < 4; j++) O[ni][j] = 0.f;

    const float scale = 0.125f;

    for (int kc = 0; kc < L; kc += 64) {
        __syncthreads();
        {
            bool v = (kc + lr) < L;
            const float* kp = g_qkv + (size_t)(t0 + kc + lr) * 768 + 256 + h * HDIM + lc;
            const float* vp = kp + 256;
            float* kd = Ks + lr * ASTR + lc;
#pragma unroll
            for (int u = 0; u < 8; u++) {
                float4 k4 = v ? *(const float4*)(kp + u * 4) : make_float4(0, 0, 0, 0);
                kd[u * 4 + 0] = k4.x; kd[u * 4 + 1] = k4.y;
                kd[u * 4 + 2] = k4.z; kd[u * 4 + 3] = k4.w;
                float4 v4 = v ? *(const float4*)(vp + u * 4) : make_float4(0, 0, 0, 0);
                Vt[(lc + u * 4 + 0) * ASTR + lr] = v4.x;
                Vt[(lc + u * 4 + 1) * ASTR + lr] = v4.y;
                Vt[(lc + u * 4 + 2) * ASTR + lr] = v4.z;
                Vt[(lc + u * 4 + 3) * ASTR + lr] = v4.w;
            }
        }
        __syncthreads();

        float S[8][4];
#pragma unroll
        for (int ni = 0; ni < 8; ni++)
#pragma unroll
            for (int j = 0; j < 4; j++) S[ni][j] = 0.f;
#pragma unroll
        for (int ks = 0; ks < 8; ks++) {
            unsigned a[4];
            const float* qb = Qs + (wm + gid) * ASTR + ks * 8 + tig;
            a[0] = __float_as_uint(qb[0]);
            a[1] = __float_as_uint(qb[8 * ASTR]);
            a[2] = __float_as_uint(qb[4]);
            a[3] = __float_as_uint(qb[8 * ASTR + 4]);
#pragma unroll
            for (int ni = 0; ni < 8; ni++) {
                unsigned bb[2];
                const float* kb = Ks + (ni * 8 + gid) * ASTR + ks * 8 + tig;
                bb[0] = __float_as_uint(kb[0]);
                bb[1] = __float_as_uint(kb[4]);
                mma_tf32(S[ni], a, bb);
            }
        }

        float rm0 = -1e30f, rm1 = -1e30f;
#pragma unroll
        for (int ni = 0; ni < 8; ni++) {
            int j0 = kc + ni * 8 + 2 * tig;
            bool v0 = j0 < L, v1 = (j0 + 1) < L;
            S[ni][0] = v0 ? S[ni][0] * scale : -1e30f;
            S[ni][1] = v1 ? S[ni][1] * scale : -1e30f;
            S[ni][2] = v0 ? S[ni][2] * scale : -1e30f;
            S[ni][3] = v1 ? S[ni][3] * scale : -1e30f;
            rm0 = fmaxf(rm0, fmaxf(S[ni][0], S[ni][1]));
            rm1 = fmaxf(rm1, fmaxf(S[ni][2], S[ni][3]));
        }
        rm0 = fmaxf(rm0, __shfl_xor_sync(0xffffffffu, rm0, 1));
        rm0 = fmaxf(rm0, __shfl_xor_sync(0xffffffffu, rm0, 2));
        rm1 = fmaxf(rm1, __shfl_xor_sync(0xffffffffu, rm1, 1));
        rm1 = fmaxf(rm1, __shfl_xor_sync(0xffffffffu, rm1, 2));
        float mn0 = fmaxf(mr0, rm0), mn1 = fmaxf(mr1, rm1);
        float cr0 = __expf(mr0 - mn0), cr1 = __expf(mr1 - mn1);
        float sum0 = 0.f, sum1 = 0.f;
        float* pr0 = Ps + (wm + gid) * ASTR;
        float* pr1 = Ps + (wm + gid + 8) * ASTR;
#pragma unroll
        for (int ni = 0; ni < 8; ni++) {
            int col = ni * 8 + 2 * tig;
            float p0 = __expf(S[ni][0] - mn0);
            float p1 = __expf(S[ni][1] - mn0);
            float p2 = __expf(S[ni][2] - mn1);
            float p3 = __expf(S[ni][3] - mn1);
            sum0 += p0 + p1; sum1 += p2 + p3;
            pr0[col] = p0; pr0[col + 1] = p1;   // raw fp32; mma truncates to tf32
            pr1[col] = p2; pr1[col + 1] = p3;
        }
        sum0 += __shfl_xor_sync(0xffffffffu, sum0, 1);
        sum0 += __shfl_xor_sync(0xffffffffu, sum0, 2);
        sum1 += __shfl_xor_sync(0xffffffffu, sum1, 1);
        sum1 += __shfl_xor_sync(0xffffffffu, sum1, 2);
        l0 = l0 * cr0 + sum0;
        l1 = l1 * cr1 + sum1;
        mr0 = mn0; mr1 = mn1;
#pragma unroll
        for (int ni = 0; ni < 8; ni++) {
            O[ni][0] *= cr0; O[ni][1] *= cr0;
            O[ni][2] *= cr1; O[ni][3] *= cr1;
        }
        __syncwarp();

#pragma unroll
        for (int ks = 0; ks < 8; ks++) {
            unsigned a[4];
            const float* pb = Ps + (wm + gid) * ASTR + ks * 8 + tig;
            a[0] = __float_as_uint(pb[0]);
            a[1] = __float_as_uint(pb[8 * ASTR]);
            a[2] = __float_as_uint(pb[4]);
            a[3] = __float_as_uint(pb[8 * ASTR + 4]);
#pragma unroll
            for (int ni = 0; ni < 8; ni++) {
                unsigned bb[2];
                const float* vb = Vt + (ni * 8 + gid) * ASTR + ks * 8 + tig;
                bb[0] = __float_as_uint(vb[0]);
                bb[1] = __float_as_uint(vb[4]);
                mma_tf32(O[ni], a, bb);
            }
        }
        __syncwarp();
    }

    float inv0 = 1.f / l0, inv1 = 1.f / l1;
    int q0 = qc + wm + gid, q1 = q0 + 8;
#pragma unroll
    for (int ni = 0; ni < 8; ni++) {
        int col = h * HDIM + ni * 8 + 2 * tig;
        if (q0 < L) {
            float* op = g_att + (size_t)(t0 + q0) * DM + col;
            op[0] = f2tff(O[ni][0] * inv0); op[1] = f2tff(O[ni][1] * inv0);
        }
        if (q1 < L) {
            float* op = g_att + (size_t)(t0 + q1) * DM + col;
            op[0] = f2tff(O[ni][2] * inv1); op[1] = f2tff(O[ni][3] * inv1);
        }
    }
}

// ---------------------------------------------------------------------------
__global__ void gather_cls() {
    int b = blockIdx.x, d = threadIdx.x;
    g_buf[(size_t)b * DM + d] = f2tff(g_tok[(size_t)(g_start[b] + b) * DM + d]);
}

__global__ void head2_kernel(const float* __restrict__ hid, const float* __restrict__ w2,
                             const float* __restrict__ b2, float* __restrict__ out, int B) {
    int t = blockIdx.x * blockDim.x + threadIdx.x;
    if (t >= B * 2) return;
    int b = t >> 1, j = t & 1;
    const float* hr = hid + (size_t)b * DM;
    const float* wr = w2 + (size_t)j * DM;
    float s = 0.f;
#pragma unroll 8
    for (int k = 0; k < DM; k++) s += hr[k] * wr[k];
    out[t] = s + b2[j];
}

// ---------------------------------------------------------------------------
extern "C" void kernel_launch(void* const* d_in, const int* in_sizes, int n_in,
                              void* d_out, int out_size) {
    const float* dom_emb = (const float*)d_in[0];
    const int*   ev      = (const int*)  d_in[1];
    const float* geom    = (const float*)d_in[3];
    const float* in_w    = (const float*)d_in[4];
    const float* in_b    = (const float*)d_in[5];
    const float* geo_w   = (const float*)d_in[6];
    const float* geo_b   = (const float*)d_in[7];
    const float* cls     = (const float*)d_in[8];
    const float* qkv_w   = (const float*)d_in[9];
    const float* qkv_b   = (const float*)d_in[10];
    const float* out_w   = (const float*)d_in[11];
    const float* out_b   = (const float*)d_in[12];
    const float* ln1w    = (const float*)d_in[13];
    const float* ln1b    = (const float*)d_in[14];
    const float* ln2w    = (const float*)d_in[15];
    const float* ln2b    = (const float*)d_in[16];
    const float* ffw1    = (const float*)d_in[17];
    const float* ffb1    = (const float*)d_in[18];
    const float* ffw2    = (const float*)d_in[19];
    const float* ffb2    = (const float*)d_in[20];
    const float* hw1     = (const float*)d_in[21];
    const float* hb1     = (const float*)d_in[22];
    const float* hw2     = (const float*)d_in[23];
    const float* hb2     = (const float*)d_in[24];
    float* out = (float*)d_out;

    int N  = in_sizes[0] / D_INP;
    int B  = out_size / 2;
    int NT = N + B;

    float *p_tok, *p_buf, *p_qkv, *p_att, *p_ff, *p_w;
    cudaGetSymbolAddress((void**)&p_tok, g_tok);
    cudaGetSymbolAddress((void**)&p_buf, g_buf);
    cudaGetSymbolAddress((void**)&p_qkv, g_qkv);
    cudaGetSymbolAddress((void**)&p_att, g_att);
    cudaGetSymbolAddress((void**)&p_ff,  g_ff);
    cudaGetSymbolAddress((void**)&p_w,   g_wts);

    static bool attrs_done = false;
    if (!attrs_done) {
        cudaFuncSetAttribute(gemm3<false, false, false>, cudaFuncAttributeMaxDynamicSharedMemorySize, GSMEM);
        cudaFuncSetAttribute(gemm3<false, true,  false>, cudaFuncAttributeMaxDynamicSharedMemorySize, GSMEM);
        cudaFuncSetAttribute(gemm3<false, false, true >, cudaFuncAttributeMaxDynamicSharedMemorySize, GSMEM);
        cudaFuncSetAttribute(gemm3<true,  false, true >, cudaFuncAttributeMaxDynamicSharedMemorySize, GSMEM);
        cudaFuncSetAttribute(gemm3<true,  false, false>, cudaFuncAttributeMaxDynamicSharedMemorySize, GSMEM);
        cudaFuncSetAttribute(attn_mma, cudaFuncAttributeMaxDynamicSharedMemorySize, ATT_SMEM);
        attrs_done = true;
    }

    // ---- convert weights + dom embeddings to tf32 bit patterns ----
    auto cvt = [&](const float* src, float* dst, int n) {
        cvt_kernel<<<(n + 255) / 256, 256>>>(src, dst, n);
    };
    cvt(in_w,  p_w + W_IN,   DM * D_INP);
    cvt(geo_w, p_w + W_GEO,  DM * DM);
    cvt(qkv_w, p_w + W_QKV,  NL * 3 * DM * DM);
    cvt(out_w, p_w + W_OUT,  NL * DM * DM);
    cvt(ffw1,  p_w + W_FF1,  NL * DFF * DM);
    cvt(ffw2,  p_w + W_FF2,  NL * DM * DFF);
    cvt(hw1,   p_w + W_HEAD, DM * DM);
    cvt(dom_emb, p_ff, N * D_INP);   // stage converted embeddings in g_ff

    int mg  = (NT + 127) / 128;
    int mgN = (N + 127) / 128;

    starts_kernel<<<1, 256>>>(ev, N, B);
    posenc_kernel<<<N, 256>>>(geom);
    gemm3<false, false, false><<<dim3(DM / 128, mgN), 256, GSMEM>>>(p_ff,  p_w + W_IN,  in_b,  p_att, N, DM, D_INP);
    gemm3<false, true,  false><<<dim3(DM / 128, mgN), 256, GSMEM>>>(p_buf, p_w + W_GEO, geo_b, p_att, N, DM, DM);
    build_tok<<<NT, 256>>>(cls, B);

    for (int l = 0; l < NL; l++) {
        ln_kernel<<<NT, 256>>>(p_tok, ln1w + l * DM, ln1b + l * DM, p_buf);
        gemm3<false, false, true><<<dim3(3 * DM / 128, mg), 256, GSMEM>>>(
            p_buf, p_w + W_QKV + (size_t)l * 3 * DM * DM, qkv_b + (size_t)l * 3 * DM, p_qkv, NT, 3 * DM, DM);
        attn_mma<<<dim3(B, NH, MAXQC), 128, ATT_SMEM>>>();
        gemm3<false, true, false><<<dim3(DM / 128, mg), 256, GSMEM>>>(
            p_att, p_w + W_OUT + (size_t)l * DM * DM, out_b + (size_t)l * DM, p_tok, NT, DM, DM);
        ln_kernel<<<NT, 256>>>(p_tok, ln2w + l * DM, ln2b + l * DM, p_buf);
        gemm3<true, false, true><<<dim3(DFF / 128, mg), 256, GSMEM>>>(
            p_buf, p_w + W_FF1 + (size_t)l * DFF * DM, ffb1 + (size_t)l * DFF, p_ff, NT, DFF, DM);
        gemm3<false, true, false><<<dim3(DM / 128, mg), 256, GSMEM>>>(
            p_ff, p_w + W_FF2 + (size_t)l * DM * DFF, ffb2 + (size_t)l * DM, p_tok, NT, DM, DFF);
    }

    gather_cls<<<B, 256>>>();
    gemm3<true, false, false><<<dim3(DM / 128, 1), 256, GSMEM>>>(p_buf, p_w + W_HEAD, hb1, p_att, B, DM, DM);
    head2_kernel<<<1, 256>>>(p_att, hw2, hb2, out, B);
}

// round 12
// speedup vs baseline: 1.9731x; 1.9075x over previous
#include <cuda_runtime.h>
#include <cuda_fp16.h>
#include <math.h>
#include <stdint.h>

// ============================================================================
// EventTransformer — ragged formulation; fp16 mma.sync (m16n8k16, fp32 accum)
// GEMMs + flash attention. fp16 mantissa == tf32 mantissa (10 bits) and all
// operands are far from the fp16 range limit, so precision matches the tf32
// version at half the smem/issue cost per flop. Residual stream stays fp32.
// ============================================================================

#define D_INP 128
#define DM    256
#define NH    4
#define HDIM  64
#define NL    4
#define DFF   1024
#define NMAXD 65536
#define BMAXD 128
#define NTMAX (NMAXD + BMAXD)

__device__ float  g_tok[(size_t)NTMAX * DM];      // residual h (fp32)
__device__ float  g_att[(size_t)NTMAX * DM];      // embed accum / head hidden (fp32)
__device__ __half g_bufh[(size_t)NTMAX * DM];     // LN out / posenc / attn out / cls
__device__ __half g_qkvh[(size_t)NTMAX * 3 * DM]; // QKV (fp16)
__device__ __half g_ffh [(size_t)NTMAX * DFF];    // FF hidden / staged dom_emb (fp16)
__device__ int    g_start[BMAXD + 1];

// converted weights (fp16)
#define W_IN   0
#define W_GEO  (W_IN   + DM * D_INP)
#define W_QKV  (W_GEO  + DM * DM)
#define W_OUT  (W_QKV  + NL * 3 * DM * DM)
#define W_FF1  (W_OUT  + NL * DM * DM)
#define W_FF2  (W_FF1  + NL * DFF * DM)
#define W_HEAD (W_FF2  + NL * DM * DFF)
#define W_TOT  (W_HEAD + DM * DM)
__device__ __half g_wtsh[W_TOT];

// ---------------------------------------------------------------------------
__device__ __forceinline__ uint32_t smem_u32(const void* p) {
    uint32_t a;
    asm("{ .reg .u64 t; cvta.to.shared.u64 t, %1; cvt.u32.u64 %0, t; }" : "=r"(a) : "l"(p));
    return a;
}
__device__ __forceinline__ void mma_f16(float c[4], const unsigned a[4], const unsigned b[2]) {
    asm volatile(
        "mma.sync.aligned.m16n8k16.row.col.f32.f16.f16.f32 "
        "{%0,%1,%2,%3}, {%4,%5,%6,%7}, {%8,%9}, {%0,%1,%2,%3};"
        : "+f"(c[0]), "+f"(c[1]), "+f"(c[2]), "+f"(c[3])
        : "r"(a[0]), "r"(a[1]), "r"(a[2]), "r"(a[3]), "r"(b[0]), "r"(b[1]));
}
#define CPA16(dst, src) \
    asm volatile("cp.async.cg.shared.global [%0], [%1], 16;" \
                 :: "r"(dst), "l"(src) : "memory")
#define CPA_COMMIT() asm volatile("cp.async.commit_group;" ::: "memory")
#define CPA_WAIT1()  asm volatile("cp.async.wait_group 1;" ::: "memory")

// ---------------------------------------------------------------------------
__global__ void cvt_half(const float* __restrict__ src, __half* __restrict__ dst, int n) {
    int i = blockIdx.x * 256 + threadIdx.x;
    if (i < n) dst[i] = __float2half_rn(src[i]);
}

__global__ void starts_kernel(const int* __restrict__ ev, int N, int B) {
    int b = blockIdx.x * blockDim.x + threadIdx.x;
    if (b > B) return;
    if (b == B) { g_start[B] = N; return; }
    int lo = 0, hi = N;
    while (lo < hi) {
        int mid = (lo + hi) >> 1;
        if (ev[mid] < b) lo = mid + 1; else hi = mid;
    }
    g_start[b] = lo;
}

__global__ void posenc_kernel(const float* __restrict__ geom) {
    int i = blockIdx.x;
    int c = threadIdx.x;
    float val = 0.f;
    if (c < 252) {
        int dax  = c / 84;
        int rem  = c % 84;
        int band = rem >> 1;
        int s    = rem & 1;
        float f   = exp2f((float)band * 0.08102263646065820f); // log2(10)/41
        float ang = 6.283185307179586f * geom[i * 3 + dax] * f;
        val = s ? cosf(ang) : sinf(ang);
    }
    g_bufh[(size_t)i * DM + c] = __float2half_rn(val);
}

// ---------------------------------------------------------------------------
// fp16 GEMM: out = (RES?C:0) + A[M,K] @ W[N,K]^T + bias[N], opt ReLU.
// HOUT: write __half to H; else write float to C (RES reads C).
// BM=BN=128, BK=32 halfs; 8 warps, 64x32 warp tiles, m16n8k16, 3-stage
// cp.async pipeline (wait_group(1) + barrier BEFORE compute — cp.async data
// from other threads is visible only after a barrier that follows the wait).
// Loader: per operand 128 rows x 64B = 512 16B-chunks; r=u>>2, q=u&3.
// M%128==0, N%128==0, K%32==0 required.
// ---------------------------------------------------------------------------
#define G5STR   40                         // halfs per row (32 data + 8 pad)
#define G5TILE  (128 * G5STR)              // halfs per operand tile
#define G5STAGE (2 * G5TILE)               // halfs per stage
#define G5SMEM  (3 * G5STAGE * 2)          // bytes

template<bool RELU, bool RES, bool HOUT>
__global__ void __launch_bounds__(256, 2) gemm5(
        const __half* __restrict__ A, const __half* __restrict__ W,
        const float* __restrict__ bias, float* __restrict__ C,
        __half* __restrict__ H, int M, int N, int K) {
    extern __shared__ __half smh[];
    const uint32_t sb = smem_u32(smh);

    const int t = threadIdx.x;
    const int lane = t & 31, gid = lane >> 2, tig = lane & 3;
    const int wid = t >> 5;
    const int wm = (wid & 1) * 64;
    const int wn = (wid >> 1) * 32;
    const int m0 = blockIdx.y * 128, n0 = blockIdx.x * 128;
    const int nc = K >> 5;

    auto load_chunk = [&](int c, int s) {
        int k0 = c * 32;
        uint32_t abase = sb + (s * G5STAGE) * 2;
        uint32_t wbase = abase + G5TILE * 2;
#pragma unroll
        for (int i = 0; i < 2; i++) {
            int u = i * 256 + t;            // 0..511
            int r = u >> 2, q = u & 3;      // r 0..127, q = 16B chunk (8 halfs)
            CPA16(abase + (r * G5STR + q * 8) * 2, A + (size_t)(m0 + r) * K + k0 + q * 8);
            CPA16(wbase + (r * G5STR + q * 8) * 2, W + (size_t)(n0 + r) * K + k0 + q * 8);
        }
    };

    load_chunk(0, 0); CPA_COMMIT();
    load_chunk(1, 1); CPA_COMMIT();   // K >= 64 always

    float acc[4][4][4];
#pragma unroll
    for (int mi = 0; mi < 4; mi++)
#pragma unroll
        for (int ni = 0; ni < 4; ni++)
#pragma unroll
            for (int j = 0; j < 4; j++) acc[mi][ni][j] = 0.f;

    for (int c = 0; c < nc; c++) {
        CPA_WAIT1();                     // chunk c complete (this thread)
        __syncthreads();                 // ...and visible CTA-wide

        const __half* Ab = smh + (c % 3) * G5STAGE;
        const __half* Wb = Ab + G5TILE;
#pragma unroll
        for (int ks = 0; ks < 2; ks++) {
            unsigned a[4][4], b[4][2];
#pragma unroll
            for (int mi = 0; mi < 4; mi++) {
                const __half* p = Ab + (wm + mi * 16 + gid) * G5STR + ks * 16 + tig * 2;
                a[mi][0] = *(const uint32_t*)(p);
                a[mi][1] = *(const uint32_t*)(p + 8 * G5STR);
                a[mi][2] = *(const uint32_t*)(p + 8);
                a[mi][3] = *(const uint32_t*)(p + 8 * G5STR + 8);
            }
#pragma unroll
            for (int ni = 0; ni < 4; ni++) {
                const __half* p = Wb + (wn + ni * 8 + gid) * G5STR + ks * 16 + tig * 2;
                b[ni][0] = *(const uint32_t*)(p);
                b[ni][1] = *(const uint32_t*)(p + 8);
            }
#pragma unroll
            for (int mi = 0; mi < 4; mi++)
#pragma unroll
                for (int ni = 0; ni < 4; ni++)
                    mma_f16(acc[mi][ni], a[mi], b[ni]);
        }

        if (c + 2 < nc) load_chunk(c + 2, (c + 2) % 3);
        CPA_COMMIT();                    // unconditional: keeps wait_group(1) valid
    }

#pragma unroll
    for (int mi = 0; mi < 4; mi++) {
#pragma unroll
        for (int ni = 0; ni < 4; ni++) {
            int r  = m0 + wm + mi * 16 + gid;
            int cn = n0 + wn + ni * 8 + 2 * tig;
            float b0 = bias[cn], b1 = bias[cn + 1];
#pragma unroll
            for (int hf = 0; hf < 2; hf++) {
                int rr = r + hf * 8;
                float v0 = acc[mi][ni][hf * 2 + 0] + b0;
                float v1 = acc[mi][ni][hf * 2 + 1] + b1;
                if (RES) {
                    const float* cp = C + (size_t)rr * N + cn;
                    v0 += cp[0]; v1 += cp[1];
                }
                if (RELU) { v0 = fmaxf(v0, 0.f); v1 = fmaxf(v1, 0.f); }
                if (HOUT) {
                    *(__half2*)(H + (size_t)rr * N + cn) = __floats2half2_rn(v0, v1);
                } else {
                    float* cp = C + (size_t)rr * N + cn;
                    cp[0] = v0; cp[1] = v1;
                }
            }
        }
    }
}

// ---------------------------------------------------------------------------
__global__ void build_tok(const float* __restrict__ cls, int B) {
    int tk = blockIdx.x;
    __shared__ int sbv;
    if (threadIdx.x == 0) {
        int lo = 0, hi = B - 1;
        while (lo < hi) {
            int mid = (lo + hi + 1) >> 1;
            if (g_start[mid] + mid <= tk) lo = mid; else hi = mid - 1;
        }
        sbv = lo;
    }
    __syncthreads();
    int b = sbv;
    int d = threadIdx.x;
    float v;
    if (tk == g_start[b] + b) v = cls[d];
    else                      v = g_att[(size_t)(tk - b - 1) * DM + d];
    g_tok[(size_t)tk * DM + d] = v;
}

// LN: fp32 in, fp16 out (feeds GEMM A directly)
__global__ void ln_kernel(const float* __restrict__ x, const float* __restrict__ w,
                          const float* __restrict__ bb, __half* __restrict__ y) {
    int row = blockIdx.x;
    int i   = threadIdx.x;
    float v = x[(size_t)row * DM + i];
    __shared__ float red[8];
    float s = v;
#pragma unroll
    for (int o = 16; o; o >>= 1) s += __shfl_xor_sync(0xffffffffu, s, o);
    if ((i & 31) == 0) red[i >> 5] = s;
    __syncthreads();
    float tot = 0.f;
#pragma unroll
    for (int k = 0; k < 8; k++) tot += red[k];
    float mean = tot * (1.f / DM);
    float d = v - mean;
    float s2 = d * d;
#pragma unroll
    for (int o = 16; o; o >>= 1) s2 += __shfl_xor_sync(0xffffffffu, s2, o);
    __syncthreads();
    if ((i & 31) == 0) red[i >> 5] = s2;
    __syncthreads();
    float tv = 0.f;
#pragma unroll
    for (int k = 0; k < 8; k++) tv += red[k];
    float var = tv * (1.f / DM);
    y[(size_t)row * DM + i] = __float2half_rn(d * rsqrtf(var + 1e-5f) * w[i] + bb[i]);
}

// ---------------------------------------------------------------------------
// Ragged flash attention, fp16 mma m16n8k16. grid = (B, NH, MAXQC), 128 thr.
// Warp w owns Q rows [qc+16w, qc+16w+16). Smem (halfs): Qs[q][d], Ks[k][d],
// Vt[d][k], Ps[q][j] — each 64 rows of 64 halfs, row stride ASTR=72
// (64 data + 8 pad; 144B rows keep 16B alignment). fp32 accum; __expf.
// ---------------------------------------------------------------------------
#define MAXQC 12
#define ASTR  72
#define ATT_SMEM (4 * 64 * ASTR * 2)

__global__ void __launch_bounds__(128) attn_h() {
    extern __shared__ __half ash[];
    __half* Qs = ash;
    __half* Ks = Qs + 64 * ASTR;
    __half* Vt = Ks + 64 * ASTR;
    __half* Ps = Vt + 64 * ASTR;

    int b  = blockIdx.x, h = blockIdx.y;
    int s0 = g_start[b];
    int L  = g_start[b + 1] - s0 + 1;
    int qc = blockIdx.z * 64;
    if (qc >= L) return;
    int t0 = s0 + b;

    int t = threadIdx.x, lane = t & 31, wid = t >> 5;
    int gid = lane >> 2, tig = lane & 3;
    int wm = wid * 16;
    int lr = t >> 1, lc = (t & 1) * 32;   // loader: row 0..63, half-col offset

    {
        bool v = (qc + lr) < L;
        const __half* qp = g_qkvh + (size_t)(t0 + qc + lr) * 768 + h * HDIM + lc;
        __half* d = Qs + lr * ASTR + lc;
        uint4 z = make_uint4(0, 0, 0, 0);
#pragma unroll
        for (int u = 0; u < 4; u++)
            *(uint4*)(d + u * 8) = v ? *(const uint4*)(qp + u * 8) : z;
    }

    float mr0 = -1e30f, mr1 = -1e30f, l0 = 0.f, l1 = 0.f;
    float O[8][4];
#pragma unroll
    for (int ni = 0; ni < 8; ni++)
#pragma unroll
        for (int j = 0; j < 4; j++) O[ni][j] = 0.f;

    const float scale = 0.125f;

    for (int kc = 0; kc < L; kc += 64) {
        __syncthreads();
        {
            bool v = (kc + lr) < L;
            const __half* kp = g_qkvh + (size_t)(t0 + kc + lr) * 768 + 256 + h * HDIM + lc;
            const __half* vp = kp + 256;
            __half* kd = Ks + lr * ASTR + lc;
            uint4 z = make_uint4(0, 0, 0, 0);
#pragma unroll
            for (int u = 0; u < 4; u++) {
                *(uint4*)(kd + u * 8) = v ? *(const uint4*)(kp + u * 8) : z;
                uint4 v4 = v ? *(const uint4*)(vp + u * 8) : z;
                __half hv[8];
                *(uint4*)hv = v4;
#pragma unroll
                for (int j = 0; j < 8; j++)
                    Vt[(lc + u * 8 + j) * ASTR + lr] = hv[j];
            }
        }
        __syncthreads();

        // ---- S = Q @ K^T (4 k-steps of 16 over HDIM=64) ----
        float S[8][4];
#pragma unroll
        for (int ni = 0; ni < 8; ni++)
#pragma unroll
            for (int j = 0; j < 4; j++) S[ni][j] = 0.f;
#pragma unroll
        for (int ks = 0; ks < 4; ks++) {
            unsigned a[4];
            const __half* qb = Qs + (wm + gid) * ASTR + ks * 16 + tig * 2;
            a[0] = *(const uint32_t*)(qb);
            a[1] = *(const uint32_t*)(qb + 8 * ASTR);
            a[2] = *(const uint32_t*)(qb + 8);
            a[3] = *(const uint32_t*)(qb + 8 * ASTR + 8);
#pragma unroll
            for (int ni = 0; ni < 8; ni++) {
                unsigned bb[2];
                const __half* kb = Ks + (ni * 8 + gid) * ASTR + ks * 16 + tig * 2;
                bb[0] = *(const uint32_t*)(kb);
                bb[1] = *(const uint32_t*)(kb + 8);
                mma_f16(S[ni], a, bb);
            }
        }

        // ---- online softmax (rows wm+gid, wm+gid+8) ----
        float rm0 = -1e30f, rm1 = -1e30f;
#pragma unroll
        for (int ni = 0; ni < 8; ni++) {
            int j0 = kc + ni * 8 + 2 * tig;
            bool v0 = j0 < L, v1 = (j0 + 1) < L;
            S[ni][0] = v0 ? S[ni][0] * scale : -1e30f;
            S[ni][1] = v1 ? S[ni][1] * scale : -1e30f;
            S[ni][2] = v0 ? S[ni][2] * scale : -1e30f;
            S[ni][3] = v1 ? S[ni][3] * scale : -1e30f;
            rm0 = fmaxf(rm0, fmaxf(S[ni][0], S[ni][1]));
            rm1 = fmaxf(rm1, fmaxf(S[ni][2], S[ni][3]));
        }
        rm0 = fmaxf(rm0, __shfl_xor_sync(0xffffffffu, rm0, 1));
        rm0 = fmaxf(rm0, __shfl_xor_sync(0xffffffffu, rm0, 2));
        rm1 = fmaxf(rm1, __shfl_xor_sync(0xffffffffu, rm1, 1));
        rm1 = fmaxf(rm1, __shfl_xor_sync(0xffffffffu, rm1, 2));
        float mn0 = fmaxf(mr0, rm0), mn1 = fmaxf(mr1, rm1);
        float cr0 = __expf(mr0 - mn0), cr1 = __expf(mr1 - mn1);
        float sum0 = 0.f, sum1 = 0.f;
        __half* pr0 = Ps + (wm + gid) * ASTR;
        __half* pr1 = Ps + (wm + gid + 8) * ASTR;
#pragma unroll
        for (int ni = 0; ni < 8; ni++) {
            int col = ni * 8 + 2 * tig;
            float p0 = __expf(S[ni][0] - mn0);
            float p1 = __expf(S[ni][1] - mn0);
            float p2 = __expf(S[ni][2] - mn1);
            float p3 = __expf(S[ni][3] - mn1);
            sum0 += p0 + p1; sum1 += p2 + p3;
            *(__half2*)(pr0 + col) = __floats2half2_rn(p0, p1);
            *(__half2*)(pr1 + col) = __floats2half2_rn(p2, p3);
        }
        sum0 += __shfl_xor_sync(0xffffffffu, sum0, 1);
        sum0 += __shfl_xor_sync(0xffffffffu, sum0, 2);
        sum1 += __shfl_xor_sync(0xffffffffu, sum1, 1);
        sum1 += __shfl_xor_sync(0xffffffffu, sum1, 2);
        l0 = l0 * cr0 + sum0;
        l1 = l1 * cr1 + sum1;
        mr0 = mn0; mr1 = mn1;
#pragma unroll
        for (int ni = 0; ni < 8; ni++) {
            O[ni][0] *= cr0; O[ni][1] *= cr0;
            O[ni][2] *= cr1; O[ni][3] *= cr1;
        }
        __syncwarp();   // warp-private P round-trip

        // ---- O += P @ V (4 k-steps of 16 over j=64) ----
#pragma unroll
        for (int ks = 0; ks < 4; ks++) {
            unsigned a[4];
            const __half* pb = Ps + (wm + gid) * ASTR + ks * 16 + tig * 2;
            a[0] = *(const uint32_t*)(pb);
            a[1] = *(const uint32_t*)(pb + 8 * ASTR);
            a[2] = *(const uint32_t*)(pb + 8);
            a[3] = *(const uint32_t*)(pb + 8 * ASTR + 8);
#pragma unroll
            for (int ni = 0; ni < 8; ni++) {
                unsigned bb[2];
                const __half* vb = Vt + (ni * 8 + gid) * ASTR + ks * 16 + tig * 2;
                bb[0] = *(const uint32_t*)(vb);
                bb[1] = *(const uint32_t*)(vb + 8);
                mma_f16(O[ni], a, bb);
            }
        }
        __syncwarp();   // P reads done before next chunk's softmax overwrites
    }

    float inv0 = 1.f / l0, inv1 = 1.f / l1;
    int q0 = qc + wm + gid, q1 = q0 + 8;
#pragma unroll
    for (int ni = 0; ni < 8; ni++) {
        int col = h * HDIM + ni * 8 + 2 * tig;
        if (q0 < L)
            *(__half2*)(g_bufh + (size_t)(t0 + q0) * DM + col) =
                __floats2half2_rn(O[ni][0] * inv0, O[ni][1] * inv0);
        if (q1 < L)
            *(__half2*)(g_bufh + (size_t)(t0 + q1) * DM + col) =
                __floats2half2_rn(O[ni][2] * inv1, O[ni][3] * inv1);
    }
}

// ---------------------------------------------------------------------------
__global__ void gather_cls() {
    int b = blockIdx.x, d = threadIdx.x;
    g_bufh[(size_t)b * DM + d] = __float2half_rn(g_tok[(size_t)(g_start[b] + b) * DM + d]);
}

__global__ void head2_kernel(const float* __restrict__ hid, const float* __restrict__ w2,
                             const float* __restrict__ b2, float* __restrict__ out, int B) {
    int t = blockIdx.x * blockDim.x + threadIdx.x;
    if (t >= B * 2) return;
    int b = t >> 1, j = t & 1;
    const float* hr = hid + (size_t)b * DM;
    const float* wr = w2 + (size_t)j * DM;
    float s = 0.f;
#pragma unroll 8
    for (int k = 0; k < DM; k++) s += hr[k] * wr[k];
    out[t] = s + b2[j];
}

// ---------------------------------------------------------------------------
extern "C" void kernel_launch(void* const* d_in, const int* in_sizes, int n_in,
                              void* d_out, int out_size) {
    const float* dom_emb = (const float*)d_in[0];
    const int*   ev      = (const int*)  d_in[1];
    const float* geom    = (const float*)d_in[3];
    const float* in_b    = (const float*)d_in[5];
    const float* geo_b   = (const float*)d_in[7];
    const float* cls     = (const float*)d_in[8];
    const float* qkv_b   = (const float*)d_in[10];
    const float* out_b   = (const float*)d_in[12];
    const float* ln1w    = (const float*)d_in[13];
    const float* ln1b    = (const float*)d_in[14];
    const float* ln2w    = (const float*)d_in[15];
    const float* ln2b    = (const float*)d_in[16];
    const float* ffb1    = (const float*)d_in[18];
    const float* ffb2    = (const float*)d_in[20];
    const float* hb1     = (const float*)d_in[22];
    const float* hw2     = (const float*)d_in[23];
    const float* hb2     = (const float*)d_in[24];
    float* out = (float*)d_out;

    int N  = in_sizes[0] / D_INP;
    int B  = out_size / 2;
    int NT = N + B;

    float  *p_tok, *p_att;
    __half *p_bufh, *p_qkvh, *p_ffh, *p_wh;
    cudaGetSymbolAddress((void**)&p_tok,  g_tok);
    cudaGetSymbolAddress((void**)&p_att,  g_att);
    cudaGetSymbolAddress((void**)&p_bufh, g_bufh);
    cudaGetSymbolAddress((void**)&p_qkvh, g_qkvh);
    cudaGetSymbolAddress((void**)&p_ffh,  g_ffh);
    cudaGetSymbolAddress((void**)&p_wh,   g_wtsh);

    static bool attrs_done = false;
    if (!attrs_done) {
        cudaFuncSetAttribute(gemm5<false, false, false>, cudaFuncAttributeMaxDynamicSharedMemorySize, G5SMEM);
        cudaFuncSetAttribute(gemm5<false, true,  false>, cudaFuncAttributeMaxDynamicSharedMemorySize, G5SMEM);
        cudaFuncSetAttribute(gemm5<false, false, true >, cudaFuncAttributeMaxDynamicSharedMemorySize, G5SMEM);
        cudaFuncSetAttribute(gemm5<true,  false, true >, cudaFuncAttributeMaxDynamicSharedMemorySize, G5SMEM);
        cudaFuncSetAttribute(gemm5<true,  false, false>, cudaFuncAttributeMaxDynamicSharedMemorySize, G5SMEM);
        cudaFuncSetAttribute(attn_h, cudaFuncAttributeMaxDynamicSharedMemorySize, ATT_SMEM);
        attrs_done = true;
    }

    // ---- convert weights + dom embeddings to fp16 ----
    auto cvt = [&](const float* src, __half* dst, int n) {
        cvt_half<<<(n + 255) / 256, 256>>>(src, dst, n);
    };
    cvt((const float*)d_in[4],  p_wh + W_IN,   DM * D_INP);
    cvt((const float*)d_in[6],  p_wh + W_GEO,  DM * DM);
    cvt((const float*)d_in[9],  p_wh + W_QKV,  NL * 3 * DM * DM);
    cvt((const float*)d_in[11], p_wh + W_OUT,  NL * DM * DM);
    cvt((const float*)d_in[17], p_wh + W_FF1,  NL * DFF * DM);
    cvt((const float*)d_in[19], p_wh + W_FF2,  NL * DM * DFF);
    cvt((const float*)d_in[21], p_wh + W_HEAD, DM * DM);
    cvt(dom_emb, p_ffh, N * D_INP);   // stage fp16 embeddings in g_ffh

    int mg  = NT / 128;
    int mgN = N / 128;

    starts_kernel<<<1, 256>>>(ev, N, B);
    posenc_kernel<<<N, 256>>>(geom);
    gemm5<false, false, false><<<dim3(DM / 128, mgN), 256, G5SMEM>>>(
        p_ffh,  p_wh + W_IN,  in_b,  p_att, nullptr, N, DM, D_INP);
    gemm5<false, true,  false><<<dim3(DM / 128, mgN), 256, G5SMEM>>>(
        p_bufh, p_wh + W_GEO, geo_b, p_att, nullptr, N, DM, DM);
    build_tok<<<NT, 256>>>(cls, B);

    for (int l = 0; l < NL; l++) {
        ln_kernel<<<NT, 256>>>(p_tok, ln1w + l * DM, ln1b + l * DM, p_bufh);
        gemm5<false, false, true><<<dim3(3 * DM / 128, mg), 256, G5SMEM>>>(
            p_bufh, p_wh + W_QKV + (size_t)l * 3 * DM * DM, qkv_b + (size_t)l * 3 * DM,
            nullptr, p_qkvh, NT, 3 * DM, DM);
        attn_h<<<dim3(B, NH, MAXQC), 128, ATT_SMEM>>>();
        gemm5<false, true, false><<<dim3(DM / 128, mg), 256, G5SMEM>>>(
            p_bufh, p_wh + W_OUT + (size_t)l * DM * DM, out_b + (size_t)l * DM,
            p_tok, nullptr, NT, DM, DM);
        ln_kernel<<<NT, 256>>>(p_tok, ln2w + l * DM, ln2b + l * DM, p_bufh);
        gemm5<true, false, true><<<dim3(DFF / 128, mg), 256, G5SMEM>>>(
            p_bufh, p_wh + W_FF1 + (size_t)l * DFF * DM, ffb1 + (size_t)l * DFF,
            nullptr, p_ffh, NT, DFF, DM);
        gemm5<false, true, false><<<dim3(DM / 128, mg), 256, G5SMEM>>>(
            p_ffh, p_wh + W_FF2 + (size_t)l * DM * DFF, ffb2 + (size_t)l * DM,
            p_tok, nullptr, NT, DM, DFF);
    }

    gather_cls<<<B, 256>>>();
    gemm5<true, false, false><<<dim3(DM / 128, 1), 256, G5SMEM>>>(
        p_bufh, p_wh + W_HEAD, hb1, p_att, nullptr, B, DM, DM);
    head2_kernel<<<1, 256>>>(p_att, hw2, hb2, out, B);
}

// round 13
// speedup vs baseline: 2.1552x; 1.0923x over previous
#include <cuda_runtime.h>
#include <cuda_fp16.h>
#include <math.h>
#include <stdint.h>

// ============================================================================
// EventTransformer — ragged formulation; fp16 mma.sync (m16n8k16, fp32 accum)
// GEMMs + flash attention, ldmatrix fragment loads. Residual stream fp32.
// ============================================================================

#define D_INP 128
#define DM    256
#define NH    4
#define HDIM  64
#define NL    4
#define DFF   1024
#define NMAXD 65536
#define BMAXD 128
#define NTMAX (NMAXD + BMAXD)

__device__ float  g_tok[(size_t)NTMAX * DM];      // residual h (fp32)
__device__ float  g_att[(size_t)NTMAX * DM];      // embed accum / head hidden (fp32)
__device__ __half g_bufh[(size_t)NTMAX * DM];     // LN out / posenc / attn out / cls
__device__ __half g_qkvh[(size_t)NTMAX * 3 * DM]; // QKV (fp16)
__device__ __half g_ffh [(size_t)NTMAX * DFF];    // FF hidden / staged dom_emb (fp16)
__device__ int    g_start[BMAXD + 1];

// converted weights (fp16), contiguous in this order
#define W_IN   0
#define W_GEO  (W_IN   + DM * D_INP)
#define W_QKV  (W_GEO  + DM * DM)
#define W_OUT  (W_QKV  + NL * 3 * DM * DM)
#define W_FF1  (W_OUT  + NL * DM * DM)
#define W_FF2  (W_FF1  + NL * DFF * DM)
#define W_HEAD (W_FF2  + NL * DM * DFF)
#define W_TOT  (W_HEAD + DM * DM)
__device__ __half g_wtsh[W_TOT];

// ---------------------------------------------------------------------------
__device__ __forceinline__ uint32_t smem_u32(const void* p) {
    uint32_t a;
    asm("{ .reg .u64 t; cvta.to.shared.u64 t, %1; cvt.u32.u64 %0, t; }" : "=r"(a) : "l"(p));
    return a;
}
__device__ __forceinline__ void mma_f16(float c[4], const unsigned a[4], const unsigned b[2]) {
    asm volatile(
        "mma.sync.aligned.m16n8k16.row.col.f32.f16.f16.f32 "
        "{%0,%1,%2,%3}, {%4,%5,%6,%7}, {%8,%9}, {%0,%1,%2,%3};"
        : "+f"(c[0]), "+f"(c[1]), "+f"(c[2]), "+f"(c[3])
        : "r"(a[0]), "r"(a[1]), "r"(a[2]), "r"(a[3]), "r"(b[0]), "r"(b[1]));
}
__device__ __forceinline__ void ldsm_x4(unsigned r[4], uint32_t addr) {
    asm volatile("ldmatrix.sync.aligned.m8n8.x4.shared.b16 {%0,%1,%2,%3}, [%4];"
                 : "=r"(r[0]), "=r"(r[1]), "=r"(r[2]), "=r"(r[3]) : "r"(addr));
}
__device__ __forceinline__ void ldsm_x4t(unsigned r[4], uint32_t addr) {
    asm volatile("ldmatrix.sync.aligned.m8n8.x4.trans.shared.b16 {%0,%1,%2,%3}, [%4];"
                 : "=r"(r[0]), "=r"(r[1]), "=r"(r[2]), "=r"(r[3]) : "r"(addr));
}
#define CPA16(dst, src) \
    asm volatile("cp.async.cg.shared.global [%0], [%1], 16;" \
                 :: "r"(dst), "l"(src) : "memory")
#define CPA_COMMIT() asm volatile("cp.async.commit_group;" ::: "memory")
#define CPA_WAIT1()  asm volatile("cp.async.wait_group 1;" ::: "memory")

// ---------------------------------------------------------------------------
__global__ void cvt_half(const float* __restrict__ src, __half* __restrict__ dst, int n) {
    int i = blockIdx.x * 256 + threadIdx.x;
    if (i < n) dst[i] = __float2half_rn(src[i]);
}

// batched conversion of up to 4 arrays into one contiguous fp16 region
__global__ void cvt4(const float* p0, int n0, const float* p1, int n1,
                     const float* p2, int n2, const float* p3, int n3,
                     __half* __restrict__ dst) {
    int i = blockIdx.x * 256 + threadIdx.x;
    const float* s; int off;
    if (i < n0)                     { s = p0; off = 0; }
    else if (i < n0 + n1)           { s = p1; off = n0; }
    else if (i < n0 + n1 + n2)      { s = p2; off = n0 + n1; }
    else if (i < n0 + n1 + n2 + n3) { s = p3; off = n0 + n1 + n2; }
    else return;
    dst[i] = __float2half_rn(s[i - off]);
}

__global__ void starts_kernel(const int* __restrict__ ev, int N, int B) {
    int b = blockIdx.x * blockDim.x + threadIdx.x;
    if (b > B) return;
    if (b == B) { g_start[B] = N; return; }
    int lo = 0, hi = N;
    while (lo < hi) {
        int mid = (lo + hi) >> 1;
        if (ev[mid] < b) lo = mid + 1; else hi = mid;
    }
    g_start[b] = lo;
}

__global__ void posenc_kernel(const float* __restrict__ geom) {
    int i = blockIdx.x;
    int c = threadIdx.x;
    float val = 0.f;
    if (c < 252) {
        int dax  = c / 84;
        int rem  = c % 84;
        int band = rem >> 1;
        int s    = rem & 1;
        float f   = exp2f((float)band * 0.08102263646065820f); // log2(10)/41
        float ang = 6.283185307179586f * geom[i * 3 + dax] * f;
        val = s ? cosf(ang) : sinf(ang);
    }
    g_bufh[(size_t)i * DM + c] = __float2half_rn(val);
}

// ---------------------------------------------------------------------------
// fp16 GEMM with ldmatrix fragment loads. Same geometry as R12 (BM=BN=128,
// BK=32, 8 warps 64x32, 3-stage cp.async, 2 CTAs/SM). M/N/K divisibility req.
// ---------------------------------------------------------------------------
#define G5STR   40                         // halfs per row (32 data + 8 pad)
#define G5TILE  (128 * G5STR)
#define G5STAGE (2 * G5TILE)
#define G5SMEM  (3 * G5STAGE * 2)

template<bool RELU, bool RES, bool HOUT>
__global__ void __launch_bounds__(256, 2) gemm5(
        const __half* __restrict__ A, const __half* __restrict__ W,
        const float* __restrict__ bias, float* __restrict__ C,
        __half* __restrict__ H, int M, int N, int K) {
    extern __shared__ __half smh[];
    const uint32_t sb = smem_u32(smh);

    const int t = threadIdx.x;
    const int lane = t & 31, gid = lane >> 2, tig = lane & 3;
    const int wid = t >> 5;
    const int wm = (wid & 1) * 64;
    const int wn = (wid >> 1) * 32;
    const int m0 = blockIdx.y * 128, n0 = blockIdx.x * 128;
    const int nc = K >> 5;

    // ldmatrix lane-constant tile offsets (verified mapping):
    // A/K-major x4: tiles {r0k0, r8k0, r0k8, r8k8} -> row += (lane&8), col += (lane&16)
    const int ra = ((lane & 8) ? 8 : 0) + (lane & 7);
    const int ca = (lane & 16) ? 8 : 0;
    // B x4: tiles {n0k0, n0k8, n8k0, n8k8} -> row += (lane&16), col += (lane&8)
    const int rb = ((lane & 16) ? 8 : 0) + (lane & 7);
    const int cb = (lane & 8) ? 8 : 0;

    auto load_chunk = [&](int c, int s) {
        int k0 = c * 32;
        uint32_t abase = sb + (s * G5STAGE) * 2;
        uint32_t wbase = abase + G5TILE * 2;
#pragma unroll
        for (int i = 0; i < 2; i++) {
            int u = i * 256 + t;            // 0..511
            int r = u >> 2, q = u & 3;      // r 0..127, q = 16B chunk (8 halfs)
            CPA16(abase + (r * G5STR + q * 8) * 2, A + (size_t)(m0 + r) * K + k0 + q * 8);
            CPA16(wbase + (r * G5STR + q * 8) * 2, W + (size_t)(n0 + r) * K + k0 + q * 8);
        }
    };

    load_chunk(0, 0); CPA_COMMIT();
    load_chunk(1, 1); CPA_COMMIT();   // K >= 64 always

    float acc[4][4][4];
#pragma unroll
    for (int mi = 0; mi < 4; mi++)
#pragma unroll
        for (int ni = 0; ni < 4; ni++)
#pragma unroll
            for (int j = 0; j < 4; j++) acc[mi][ni][j] = 0.f;

    for (int c = 0; c < nc; c++) {
        CPA_WAIT1();
        __syncthreads();                 // cp.async data visible CTA-wide

        uint32_t sA = sb + (c % 3) * (G5STAGE * 2);
        uint32_t sW = sA + G5TILE * 2;
#pragma unroll
        for (int ks = 0; ks < 2; ks++) {
            unsigned a[4][4], b[4][2];
#pragma unroll
            for (int mi = 0; mi < 4; mi++)
                ldsm_x4(a[mi], sA + ((wm + mi * 16 + ra) * G5STR + ks * 16 + ca) * 2);
            {
                unsigned bt[4];
                ldsm_x4(bt, sW + ((wn + rb) * G5STR + ks * 16 + cb) * 2);
                b[0][0] = bt[0]; b[0][1] = bt[1]; b[1][0] = bt[2]; b[1][1] = bt[3];
                ldsm_x4(bt, sW + ((wn + 16 + rb) * G5STR + ks * 16 + cb) * 2);
                b[2][0] = bt[0]; b[2][1] = bt[1]; b[3][0] = bt[2]; b[3][1] = bt[3];
            }
#pragma unroll
            for (int mi = 0; mi < 4; mi++)
#pragma unroll
                for (int ni = 0; ni < 4; ni++)
                    mma_f16(acc[mi][ni], a[mi], b[ni]);
        }

        if (c + 2 < nc) load_chunk(c + 2, (c + 2) % 3);
        CPA_COMMIT();                    // unconditional: keeps wait_group(1) valid
    }

#pragma unroll
    for (int mi = 0; mi < 4; mi++) {
#pragma unroll
        for (int ni = 0; ni < 4; ni++) {
            int r  = m0 + wm + mi * 16 + gid;
            int cn = n0 + wn + ni * 8 + 2 * tig;
            float b0 = bias[cn], b1 = bias[cn + 1];
#pragma unroll
            for (int hf = 0; hf < 2; hf++) {
                int rr = r + hf * 8;
                float v0 = acc[mi][ni][hf * 2 + 0] + b0;
                float v1 = acc[mi][ni][hf * 2 + 1] + b1;
                if (RES) {
                    const float* cp = C + (size_t)rr * N + cn;
                    v0 += cp[0]; v1 += cp[1];
                }
                if (RELU) { v0 = fmaxf(v0, 0.f); v1 = fmaxf(v1, 0.f); }
                if (HOUT) {
                    *(__half2*)(H + (size_t)rr * N + cn) = __floats2half2_rn(v0, v1);
                } else {
                    float* cp = C + (size_t)rr * N + cn;
                    cp[0] = v0; cp[1] = v1;
                }
            }
        }
    }
}

// ---------------------------------------------------------------------------
// build_tok fused with layer-0 ln1: writes g_tok (fp32 residual) AND
// g_bufh = fp16(LN(v; w, b)).
// ---------------------------------------------------------------------------
__global__ void build_tok_ln(const float* __restrict__ cls, int B,
                             const float* __restrict__ w, const float* __restrict__ bb) {
    int tk = blockIdx.x;
    __shared__ int sbv;
    if (threadIdx.x == 0) {
        int lo = 0, hi = B - 1;
        while (lo < hi) {
            int mid = (lo + hi + 1) >> 1;
            if (g_start[mid] + mid <= tk) lo = mid; else hi = mid - 1;
        }
        sbv = lo;
    }
    __syncthreads();
    int b = sbv;
    int i = threadIdx.x;
    float v;
    if (tk == g_start[b] + b) v = cls[i];
    else                      v = g_att[(size_t)(tk - b - 1) * DM + i];
    g_tok[(size_t)tk * DM + i] = v;

    __shared__ float red[8];
    float s = v;
#pragma unroll
    for (int o = 16; o; o >>= 1) s += __shfl_xor_sync(0xffffffffu, s, o);
    if ((i & 31) == 0) red[i >> 5] = s;
    __syncthreads();
    float tot = 0.f;
#pragma unroll
    for (int k = 0; k < 8; k++) tot += red[k];
    float mean = tot * (1.f / DM);
    float d = v - mean;
    float s2 = d * d;
#pragma unroll
    for (int o = 16; o; o >>= 1) s2 += __shfl_xor_sync(0xffffffffu, s2, o);
    __syncthreads();
    if ((i & 31) == 0) red[i >> 5] = s2;
    __syncthreads();
    float tv = 0.f;
#pragma unroll
    for (int k = 0; k < 8; k++) tv += red[k];
    float var = tv * (1.f / DM);
    g_bufh[(size_t)tk * DM + i] = __float2half_rn(d * rsqrtf(var + 1e-5f) * w[i] + bb[i]);
}

// LN: fp32 in, fp16 out
__global__ void ln_kernel(const float* __restrict__ x, const float* __restrict__ w,
                          const float* __restrict__ bb, __half* __restrict__ y) {
    int row = blockIdx.x;
    int i   = threadIdx.x;
    float v = x[(size_t)row * DM + i];
    __shared__ float red[8];
    float s = v;
#pragma unroll
    for (int o = 16; o; o >>= 1) s += __shfl_xor_sync(0xffffffffu, s, o);
    if ((i & 31) == 0) red[i >> 5] = s;
    __syncthreads();
    float tot = 0.f;
#pragma unroll
    for (int k = 0; k < 8; k++) tot += red[k];
    float mean = tot * (1.f / DM);
    float d = v - mean;
    float s2 = d * d;
#pragma unroll
    for (int o = 16; o; o >>= 1) s2 += __shfl_xor_sync(0xffffffffu, s2, o);
    __syncthreads();
    if ((i & 31) == 0) red[i >> 5] = s2;
    __syncthreads();
    float tv = 0.f;
#pragma unroll
    for (int k = 0; k < 8; k++) tv += red[k];
    float var = tv * (1.f / DM);
    y[(size_t)row * DM + i] = __float2half_rn(d * rsqrtf(var + 1e-5f) * w[i] + bb[i]);
}

// ---------------------------------------------------------------------------
// Ragged flash attention, fp16 mma + ldmatrix. grid = (B, NH, MAXQC), 128 thr.
// Smem (halfs, stride ASTR=72): Qs[q][d], Ks[k][d], Vs[j][d] (row-major; B
// fragments via ldmatrix.trans), Ps[q][j].
// ---------------------------------------------------------------------------
#define MAXQC 12
#define ASTR  72
#define AREG  (64 * ASTR)
#define ATT_SMEM (4 * AREG * 2)

__global__ void __launch_bounds__(128) attn_h() {
    extern __shared__ __half ash[];
    __half* Qs = ash;
    __half* Ks = Qs + AREG;
    __half* Vs = Ks + AREG;
    __half* Ps = Vs + AREG;
    const uint32_t sbQ = smem_u32(ash);
    const uint32_t sbK = sbQ + AREG * 2;
    const uint32_t sbV = sbK + AREG * 2;
    const uint32_t sbP = sbV + AREG * 2;

    int b  = blockIdx.x, h = blockIdx.y;
    int s0 = g_start[b];
    int L  = g_start[b + 1] - s0 + 1;
    int qc = blockIdx.z * 64;
    if (qc >= L) return;
    int t0 = s0 + b;

    int t = threadIdx.x, lane = t & 31, wid = t >> 5;
    int gid = lane >> 2, tig = lane & 3;
    int wm = wid * 16;
    int lr = t >> 1, lc = (t & 1) * 32;

    const int ra = ((lane & 8) ? 8 : 0) + (lane & 7);
    const int ca = (lane & 16) ? 8 : 0;
    const int rb = ((lane & 16) ? 8 : 0) + (lane & 7);
    const int cb = (lane & 8) ? 8 : 0;

    {
        bool v = (qc + lr) < L;
        const __half* qp = g_qkvh + (size_t)(t0 + qc + lr) * 768 + h * HDIM + lc;
        __half* d = Qs + lr * ASTR + lc;
        uint4 z = make_uint4(0, 0, 0, 0);
#pragma unroll
        for (int u = 0; u < 4; u++)
            *(uint4*)(d + u * 8) = v ? *(const uint4*)(qp + u * 8) : z;
    }

    float mr0 = -1e30f, mr1 = -1e30f, l0 = 0.f, l1 = 0.f;
    float O[8][4];
#pragma unroll
    for (int ni = 0; ni < 8; ni++)
#pragma unroll
        for (int j = 0; j < 4; j++) O[ni][j] = 0.f;

    const float scale = 0.125f;

    for (int kc = 0; kc < L; kc += 64) {
        __syncthreads();
        {
            bool v = (kc + lr) < L;
            const __half* kp = g_qkvh + (size_t)(t0 + kc + lr) * 768 + 256 + h * HDIM + lc;
            const __half* vp = kp + 256;
            __half* kd = Ks + lr * ASTR + lc;
            __half* vd = Vs + lr * ASTR + lc;   // row-major [j][d]
            uint4 z = make_uint4(0, 0, 0, 0);
#pragma unroll
            for (int u = 0; u < 4; u++) {
                *(uint4*)(kd + u * 8) = v ? *(const uint4*)(kp + u * 8) : z;
                *(uint4*)(vd + u * 8) = v ? *(const uint4*)(vp + u * 8) : z;
            }
        }
        __syncthreads();

        // ---- S = Q @ K^T ----
        float S[8][4];
#pragma unroll
        for (int ni = 0; ni < 8; ni++)
#pragma unroll
            for (int j = 0; j < 4; j++) S[ni][j] = 0.f;
#pragma unroll
        for (int ks = 0; ks < 4; ks++) {
            unsigned a[4];
            ldsm_x4(a, sbQ + ((wm + ra) * ASTR + ks * 16 + ca) * 2);
#pragma unroll
            for (int nb = 0; nb < 8; nb += 2) {
                unsigned bt[4];
                ldsm_x4(bt, sbK + ((nb * 8 + rb) * ASTR + ks * 16 + cb) * 2);
                mma_f16(S[nb],     a, bt);       // {bt[0],bt[1]}
                mma_f16(S[nb + 1], a, bt + 2);   // {bt[2],bt[3]}
            }
        }

        // ---- online softmax (rows wm+gid, wm+gid+8) ----
        float rm0 = -1e30f, rm1 = -1e30f;
#pragma unroll
        for (int ni = 0; ni < 8; ni++) {
            int j0 = kc + ni * 8 + 2 * tig;
            bool v0 = j0 < L, v1 = (j0 + 1) < L;
            S[ni][0] = v0 ? S[ni][0] * scale : -1e30f;
            S[ni][1] = v1 ? S[ni][1] * scale : -1e30f;
            S[ni][2] = v0 ? S[ni][2] * scale : -1e30f;
            S[ni][3] = v1 ? S[ni][3] * scale : -1e30f;
            rm0 = fmaxf(rm0, fmaxf(S[ni][0], S[ni][1]));
            rm1 = fmaxf(rm1, fmaxf(S[ni][2], S[ni][3]));
        }
        rm0 = fmaxf(rm0, __shfl_xor_sync(0xffffffffu, rm0, 1));
        rm0 = fmaxf(rm0, __shfl_xor_sync(0xffffffffu, rm0, 2));
        rm1 = fmaxf(rm1, __shfl_xor_sync(0xffffffffu, rm1, 1));
        rm1 = fmaxf(rm1, __shfl_xor_sync(0xffffffffu, rm1, 2));
        float mn0 = fmaxf(mr0, rm0), mn1 = fmaxf(mr1, rm1);
        float cr0 = __expf(mr0 - mn0), cr1 = __expf(mr1 - mn1);
        float sum0 = 0.f, sum1 = 0.f;
        __half* pr0 = Ps + (wm + gid) * ASTR;
        __half* pr1 = Ps + (wm + gid + 8) * ASTR;
#pragma unroll
        for (int ni = 0; ni < 8; ni++) {
            int col = ni * 8 + 2 * tig;
            float p0 = __expf(S[ni][0] - mn0);
            float p1 = __expf(S[ni][1] - mn0);
            float p2 = __expf(S[ni][2] - mn1);
            float p3 = __expf(S[ni][3] - mn1);
            sum0 += p0 + p1; sum1 += p2 + p3;
            *(__half2*)(pr0 + col) = __floats2half2_rn(p0, p1);
            *(__half2*)(pr1 + col) = __floats2half2_rn(p2, p3);
        }
        sum0 += __shfl_xor_sync(0xffffffffu, sum0, 1);
        sum0 += __shfl_xor_sync(0xffffffffu, sum0, 2);
        sum1 += __shfl_xor_sync(0xffffffffu, sum1, 1);
        sum1 += __shfl_xor_sync(0xffffffffu, sum1, 2);
        l0 = l0 * cr0 + sum0;
        l1 = l1 * cr1 + sum1;
        mr0 = mn0; mr1 = mn1;
#pragma unroll
        for (int ni = 0; ni < 8; ni++) {
            O[ni][0] *= cr0; O[ni][1] *= cr0;
            O[ni][2] *= cr1; O[ni][3] *= cr1;
        }
        __syncwarp();   // warp-private P round-trip

        // ---- O += P @ V (B frags via trans-ldmatrix of row-major V) ----
#pragma unroll
        for (int ks = 0; ks < 4; ks++) {
            unsigned a[4];
            ldsm_x4(a, sbP + ((wm + ra) * ASTR + ks * 16 + ca) * 2);
#pragma unroll
            for (int nb = 0; nb < 8; nb += 2) {
                unsigned bt[4];
                // tiles: rows j = ks*16 + (lane&8 ? 8:0) + (lane&7),
                //        cols d = nb*8 + (lane&16 ? 8:0)
                ldsm_x4t(bt, sbV + ((ks * 16 + ra) * ASTR + nb * 8 + ca) * 2);
                mma_f16(O[nb],     a, bt);
                mma_f16(O[nb + 1], a, bt + 2);
            }
        }
        __syncwarp();   // P reads done before next chunk's softmax overwrites
    }

    float inv0 = 1.f / l0, inv1 = 1.f / l1;
    int q0 = qc + wm + gid, q1 = q0 + 8;
#pragma unroll
    for (int ni = 0; ni < 8; ni++) {
        int col = h * HDIM + ni * 8 + 2 * tig;
        if (q0 < L)
            *(__half2*)(g_bufh + (size_t)(t0 + q0) * DM + col) =
                __floats2half2_rn(O[ni][0] * inv0, O[ni][1] * inv0);
        if (q1 < L)
            *(__half2*)(g_bufh + (size_t)(t0 + q1) * DM + col) =
                __floats2half2_rn(O[ni][2] * inv1, O[ni][3] * inv1);
    }
}

// ---------------------------------------------------------------------------
__global__ void gather_cls() {
    int b = blockIdx.x, d = threadIdx.x;
    g_bufh[(size_t)b * DM + d] = __float2half_rn(g_tok[(size_t)(g_start[b] + b) * DM + d]);
}

__global__ void head2_kernel(const float* __restrict__ hid, const float* __restrict__ w2,
                             const float* __restrict__ b2, float* __restrict__ out, int B) {
    int t = blockIdx.x * blockDim.x + threadIdx.x;
    if (t >= B * 2) return;
    int b = t >> 1, j = t & 1;
    const float* hr = hid + (size_t)b * DM;
    const float* wr = w2 + (size_t)j * DM;
    float s = 0.f;
#pragma unroll 8
    for (int k = 0; k < DM; k++) s += hr[k] * wr[k];
    out[t] = s + b2[j];
}

// ---------------------------------------------------------------------------
extern "C" void kernel_launch(void* const* d_in, const int* in_sizes, int n_in,
                              void* d_out, int out_size) {
    const float* dom_emb = (const float*)d_in[0];
    const int*   ev      = (const int*)  d_in[1];
    const float* geom    = (const float*)d_in[3];
    const float* in_b    = (const float*)d_in[5];
    const float* geo_b   = (const float*)d_in[7];
    const float* cls     = (const float*)d_in[8];
    const float* qkv_b   = (const float*)d_in[10];
    const float* out_b   = (const float*)d_in[12];
    const float* ln1w    = (const float*)d_in[13];
    const float* ln1b    = (const float*)d_in[14];
    const float* ln2w    = (const float*)d_in[15];
    const float* ln2b    = (const float*)d_in[16];
    const float* ffb1    = (const float*)d_in[18];
    const float* ffb2    = (const float*)d_in[20];
    const float* hb1     = (const float*)d_in[22];
    const float* hw2     = (const float*)d_in[23];
    const float* hb2     = (const float*)d_in[24];
    float* out = (float*)d_out;

    int N  = in_sizes[0] / D_INP;
    int B  = out_size / 2;
    int NT = N + B;

    float  *p_tok, *p_att;
    __half *p_bufh, *p_qkvh, *p_ffh, *p_wh;
    cudaGetSymbolAddress((void**)&p_tok,  g_tok);
    cudaGetSymbolAddress((void**)&p_att,  g_att);
    cudaGetSymbolAddress((void**)&p_bufh, g_bufh);
    cudaGetSymbolAddress((void**)&p_qkvh, g_qkvh);
    cudaGetSymbolAddress((void**)&p_ffh,  g_ffh);
    cudaGetSymbolAddress((void**)&p_wh,   g_wtsh);

    static bool attrs_done = false;
    if (!attrs_done) {
        cudaFuncSetAttribute(gemm5<false, false, false>, cudaFuncAttributeMaxDynamicSharedMemorySize, G5SMEM);
        cudaFuncSetAttribute(gemm5<false, true,  false>, cudaFuncAttributeMaxDynamicSharedMemorySize, G5SMEM);
        cudaFuncSetAttribute(gemm5<false, false, true >, cudaFuncAttributeMaxDynamicSharedMemorySize, G5SMEM);
        cudaFuncSetAttribute(gemm5<true,  false, true >, cudaFuncAttributeMaxDynamicSharedMemorySize, G5SMEM);
        cudaFuncSetAttribute(gemm5<true,  false, false>, cudaFuncAttributeMaxDynamicSharedMemorySize, G5SMEM);
        cudaFuncSetAttribute(attn_h, cudaFuncAttributeMaxDynamicSharedMemorySize, ATT_SMEM);
        attrs_done = true;
    }

    // ---- batched fp16 conversions (launch order tuned so ncu -s 5 -c 1
    //      captures the embedding gemm5 at launch #6) ----
    {
        int na0 = DM * D_INP, na1 = DM * DM, na2 = NL * 3 * DM * DM, na3 = NL * DM * DM;
        int ta = na0 + na1 + na2 + na3;
        cvt4<<<(ta + 255) / 256, 256>>>(
            (const float*)d_in[4], na0, (const float*)d_in[6], na1,
            (const float*)d_in[9], na2, (const float*)d_in[11], na3, p_wh + W_IN);     // (1)
        int nb0 = NL * DFF * DM, nb1 = NL * DM * DFF, nb2 = DM * DM;
        int tb = nb0 + nb1 + nb2;
        cvt4<<<(tb + 255) / 256, 256>>>(
            (const float*)d_in[17], nb0, (const float*)d_in[19], nb1,
            (const float*)d_in[21], nb2, nullptr, 0, p_wh + W_FF1);                    // (2)
    }
    starts_kernel<<<1, 256>>>(ev, N, B);                                               // (3)
    posenc_kernel<<<N, 256>>>(geom);                                                   // (4)
    cvt_half<<<(N * D_INP + 255) / 256, 256>>>(dom_emb, p_ffh, N * D_INP);             // (5)

    int mg  = NT / 128;
    int mgN = N / 128;

    gemm5<false, false, false><<<dim3(DM / 128, mgN), 256, G5SMEM>>>(
        p_ffh,  p_wh + W_IN,  in_b,  p_att, nullptr, N, DM, D_INP);                    // (6) profiled
    gemm5<false, true,  false><<<dim3(DM / 128, mgN), 256, G5SMEM>>>(
        p_bufh, p_wh + W_GEO, geo_b, p_att, nullptr, N, DM, DM);
    build_tok_ln<<<NT, 256>>>(cls, B, ln1w, ln1b);

    for (int l = 0; l < NL; l++) {
        if (l > 0)
            ln_kernel<<<NT, 256>>>(p_tok, ln1w + l * DM, ln1b + l * DM, p_bufh);
        gemm5<false, false, true><<<dim3(3 * DM / 128, mg), 256, G5SMEM>>>(
            p_bufh, p_wh + W_QKV + (size_t)l * 3 * DM * DM, qkv_b + (size_t)l * 3 * DM,
            nullptr, p_qkvh, NT, 3 * DM, DM);
        attn_h<<<dim3(B, NH, MAXQC), 128, ATT_SMEM>>>();
        gemm5<false, true, false><<<dim3(DM / 128, mg), 256, G5SMEM>>>(
            p_bufh, p_wh + W_OUT + (size_t)l * DM * DM, out_b + (size_t)l * DM,
            p_tok, nullptr, NT, DM, DM);
        ln_kernel<<<NT, 256>>>(p_tok, ln2w + l * DM, ln2b + l * DM, p_bufh);
        gemm5<true, false, true><<<dim3(DFF / 128, mg), 256, G5SMEM>>>(
            p_bufh, p_wh + W_FF1 + (size_t)l * DFF * DM, ffb1 + (size_t)l * DFF,
            nullptr, p_ffh, NT, DFF, DM);
        gemm5<false, true, false><<<dim3(DM / 128, mg), 256, G5SMEM>>>(
            p_ffh, p_wh + W_FF2 + (size_t)l * DM * DFF, ffb2 + (size_t)l * DM,
            p_tok, nullptr, NT, DM, DFF);
    }

    gather_cls<<<B, 256>>>();
    gemm5<true, false, false><<<dim3(DM / 128, 1), 256, G5SMEM>>>(
        p_bufh, p_wh + W_HEAD, hb1, p_att, nullptr, B, DM, DM);
    head2_kernel<<<1, 256>>>(p_att, hw2, hb2, out, B);
}

// round 14
// speedup vs baseline: 2.3701x; 1.0997x over previous
#include <cuda_runtime.h>
#include <cuda_fp16.h>
#include <math.h>
#include <stdint.h>

// ============================================================================
// EventTransformer — ragged formulation; fp16 mma.sync (m16n8k16, fp32 accum)
// GEMMs + flash attention, ldmatrix fragment loads, LayerNorm fused into the
// DM-wide GEMM epilogues (zero standalone LN launches). Residual stream fp32.
// ============================================================================

#define D_INP 128
#define DM    256
#define NH    4
#define HDIM  64
#define NL    4
#define DFF   1024
#define NMAXD 65536
#define BMAXD 128
#define NTMAX (NMAXD + BMAXD)

__device__ float  g_tok[(size_t)NTMAX * DM];      // residual h (fp32)
__device__ float  g_att[(size_t)NTMAX * DM];      // embed accum / head hidden (fp32)
__device__ __half g_bufh[(size_t)NTMAX * DM];     // LN out / posenc / attn out / cls
__device__ __half g_qkvh[(size_t)NTMAX * 3 * DM]; // QKV (fp16)
__device__ __half g_ffh [(size_t)NTMAX * DFF];    // FF hidden / staged dom_emb (fp16)
__device__ int    g_start[BMAXD + 1];

// converted weights (fp16), contiguous in this order
#define W_IN   0
#define W_GEO  (W_IN   + DM * D_INP)
#define W_QKV  (W_GEO  + DM * DM)
#define W_OUT  (W_QKV  + NL * 3 * DM * DM)
#define W_FF1  (W_OUT  + NL * DM * DM)
#define W_FF2  (W_FF1  + NL * DFF * DM)
#define W_HEAD (W_FF2  + NL * DM * DFF)
#define W_TOT  (W_HEAD + DM * DM)
__device__ __half g_wtsh[W_TOT];

// ---------------------------------------------------------------------------
__device__ __forceinline__ uint32_t smem_u32(const void* p) {
    uint32_t a;
    asm("{ .reg .u64 t; cvta.to.shared.u64 t, %1; cvt.u32.u64 %0, t; }" : "=r"(a) : "l"(p));
    return a;
}
__device__ __forceinline__ void mma_f16(float c[4], const unsigned a[4], const unsigned b[2]) {
    asm volatile(
        "mma.sync.aligned.m16n8k16.row.col.f32.f16.f16.f32 "
        "{%0,%1,%2,%3}, {%4,%5,%6,%7}, {%8,%9}, {%0,%1,%2,%3};"
        : "+f"(c[0]), "+f"(c[1]), "+f"(c[2]), "+f"(c[3])
        : "r"(a[0]), "r"(a[1]), "r"(a[2]), "r"(a[3]), "r"(b[0]), "r"(b[1]));
}
__device__ __forceinline__ void ldsm_x4(unsigned r[4], uint32_t addr) {
    asm volatile("ldmatrix.sync.aligned.m8n8.x4.shared.b16 {%0,%1,%2,%3}, [%4];"
                 : "=r"(r[0]), "=r"(r[1]), "=r"(r[2]), "=r"(r[3]) : "r"(addr));
}
__device__ __forceinline__ void ldsm_x4t(unsigned r[4], uint32_t addr) {
    asm volatile("ldmatrix.sync.aligned.m8n8.x4.trans.shared.b16 {%0,%1,%2,%3}, [%4];"
                 : "=r"(r[0]), "=r"(r[1]), "=r"(r[2]), "=r"(r[3]) : "r"(addr));
}
#define CPA16(dst, src) \
    asm volatile("cp.async.cg.shared.global [%0], [%1], 16;" \
                 :: "r"(dst), "l"(src) : "memory")
#define CPA_COMMIT() asm volatile("cp.async.commit_group;" ::: "memory")
#define CPA_WAIT1()  asm volatile("cp.async.wait_group 1;" ::: "memory")

// ---------------------------------------------------------------------------
__global__ void cvt_half(const float* __restrict__ src, __half* __restrict__ dst, int n) {
    int i = blockIdx.x * 256 + threadIdx.x;
    if (i < n) dst[i] = __float2half_rn(src[i]);
}

__global__ void cvt4(const float* p0, int n0, const float* p1, int n1,
                     const float* p2, int n2, const float* p3, int n3,
                     __half* __restrict__ dst) {
    int i = blockIdx.x * 256 + threadIdx.x;
    const float* s; int off;
    if (i < n0)                     { s = p0; off = 0; }
    else if (i < n0 + n1)           { s = p1; off = n0; }
    else if (i < n0 + n1 + n2)      { s = p2; off = n0 + n1; }
    else if (i < n0 + n1 + n2 + n3) { s = p3; off = n0 + n1 + n2; }
    else return;
    dst[i] = __float2half_rn(s[i - off]);
}

__global__ void starts_kernel(const int* __restrict__ ev, int N, int B) {
    int b = blockIdx.x * blockDim.x + threadIdx.x;
    if (b > B) return;
    if (b == B) { g_start[B] = N; return; }
    int lo = 0, hi = N;
    while (lo < hi) {
        int mid = (lo + hi) >> 1;
        if (ev[mid] < b) lo = mid + 1; else hi = mid;
    }
    g_start[b] = lo;
}

// posenc: 128 threads/row; thread c2 computes the (sin, cos) pair for cols
// 2*c2, 2*c2+1 with ONE sincosf. Pair layout: c2 = dax*42 + band.
__global__ void posenc_kernel(const float* __restrict__ geom) {
    int i  = blockIdx.x;
    int c2 = threadIdx.x;
    float v0 = 0.f, v1 = 0.f;
    if (c2 < 126) {
        int dax  = c2 / 42;
        int band = c2 % 42;
        float f   = exp2f((float)band * 0.08102263646065820f); // log2(10)/41
        float ang = 6.283185307179586f * geom[i * 3 + dax] * f;
        sincosf(ang, &v0, &v1);
    }
    *(__half2*)(g_bufh + (size_t)i * DM + 2 * c2) = __floats2half2_rn(v0, v1);
}

// ---------------------------------------------------------------------------
// gemm5 (proven R13): BM=BN=128, BK=32, 8 warps 64x32, ldmatrix, 3-stage.
// ---------------------------------------------------------------------------
#define G5STR   40
#define G5TILE  (128 * G5STR)
#define G5STAGE (2 * G5TILE)
#define G5SMEM  (3 * G5STAGE * 2)

template<bool RELU, bool RES, bool HOUT>
__global__ void __launch_bounds__(256, 2) gemm5(
        const __half* __restrict__ A, const __half* __restrict__ W,
        const float* __restrict__ bias, float* __restrict__ C,
        __half* __restrict__ H, int M, int N, int K) {
    extern __shared__ __half smh[];
    const uint32_t sb = smem_u32(smh);

    const int t = threadIdx.x;
    const int lane = t & 31, gid = lane >> 2, tig = lane & 3;
    const int wid = t >> 5;
    const int wm = (wid & 1) * 64;
    const int wn = (wid >> 1) * 32;
    const int m0 = blockIdx.y * 128, n0 = blockIdx.x * 128;
    const int nc = K >> 5;

    const int ra = ((lane & 8) ? 8 : 0) + (lane & 7);
    const int ca = (lane & 16) ? 8 : 0;
    const int rb = ((lane & 16) ? 8 : 0) + (lane & 7);
    const int cb = (lane & 8) ? 8 : 0;

    auto load_chunk = [&](int c, int s) {
        int k0 = c * 32;
        uint32_t abase = sb + (s * G5STAGE) * 2;
        uint32_t wbase = abase + G5TILE * 2;
#pragma unroll
        for (int i = 0; i < 2; i++) {
            int u = i * 256 + t;
            int r = u >> 2, q = u & 3;
            CPA16(abase + (r * G5STR + q * 8) * 2, A + (size_t)(m0 + r) * K + k0 + q * 8);
            CPA16(wbase + (r * G5STR + q * 8) * 2, W + (size_t)(n0 + r) * K + k0 + q * 8);
        }
    };

    load_chunk(0, 0); CPA_COMMIT();
    load_chunk(1, 1); CPA_COMMIT();

    float acc[4][4][4];
#pragma unroll
    for (int mi = 0; mi < 4; mi++)
#pragma unroll
        for (int ni = 0; ni < 4; ni++)
#pragma unroll
            for (int j = 0; j < 4; j++) acc[mi][ni][j] = 0.f;

    for (int c = 0; c < nc; c++) {
        CPA_WAIT1();
        __syncthreads();

        uint32_t sA = sb + (c % 3) * (G5STAGE * 2);
        uint32_t sW = sA + G5TILE * 2;
#pragma unroll
        for (int ks = 0; ks < 2; ks++) {
            unsigned a[4][4], b[4][2];
#pragma unroll
            for (int mi = 0; mi < 4; mi++)
                ldsm_x4(a[mi], sA + ((wm + mi * 16 + ra) * G5STR + ks * 16 + ca) * 2);
            {
                unsigned bt[4];
                ldsm_x4(bt, sW + ((wn + rb) * G5STR + ks * 16 + cb) * 2);
                b[0][0] = bt[0]; b[0][1] = bt[1]; b[1][0] = bt[2]; b[1][1] = bt[3];
                ldsm_x4(bt, sW + ((wn + 16 + rb) * G5STR + ks * 16 + cb) * 2);
                b[2][0] = bt[0]; b[2][1] = bt[1]; b[3][0] = bt[2]; b[3][1] = bt[3];
            }
#pragma unroll
            for (int mi = 0; mi < 4; mi++)
#pragma unroll
                for (int ni = 0; ni < 4; ni++)
                    mma_f16(acc[mi][ni], a[mi], b[ni]);
        }

        if (c + 2 < nc) load_chunk(c + 2, (c + 2) % 3);
        CPA_COMMIT();
    }

#pragma unroll
    for (int mi = 0; mi < 4; mi++) {
#pragma unroll
        for (int ni = 0; ni < 4; ni++) {
            int r  = m0 + wm + mi * 16 + gid;
            int cn = n0 + wn + ni * 8 + 2 * tig;
            float b0 = bias[cn], b1 = bias[cn + 1];
#pragma unroll
            for (int hf = 0; hf < 2; hf++) {
                int rr = r + hf * 8;
                float v0 = acc[mi][ni][hf * 2 + 0] + b0;
                float v1 = acc[mi][ni][hf * 2 + 1] + b1;
                if (RES) {
                    const float* cp = C + (size_t)rr * N + cn;
                    v0 += cp[0]; v1 += cp[1];
                }
                if (RELU) { v0 = fmaxf(v0, 0.f); v1 = fmaxf(v1, 0.f); }
                if (HOUT) {
                    *(__half2*)(H + (size_t)rr * N + cn) = __floats2half2_rn(v0, v1);
                } else {
                    float* cp = C + (size_t)rr * N + cn;
                    cp[0] = v0; cp[1] = v1;
                }
            }
        }
    }
}

// ---------------------------------------------------------------------------
// gemm6: BM=64, BN=256 (full row), BK=32; 8 warps, 32x64 warp tiles (2x4);
// same per-thread acc count (64) and LDS:MMA ratio as gemm5 -> 2 CTAs/SM.
// Epilogue: h = acc + bias (+C) -> C (fp32); if LNF, Y = fp16(LN(h)) over the
// full N=256 row (cross-warp reduction via smem). Requires N==256, grid.x==1.
// ---------------------------------------------------------------------------
#define G6STR   40
#define G6ROWS  320                        // 64 A rows + 256 W rows
#define G6STAGE (G6ROWS * G6STR)           // halfs per stage
#define G6SMEM  (3 * G6STAGE * 2)          // bytes

template<bool RES, bool LNF>
__global__ void __launch_bounds__(256, 2) gemm6(
        const __half* __restrict__ A, const __half* __restrict__ W,
        const float* __restrict__ bias, float* __restrict__ C,
        const float* __restrict__ lnw, const float* __restrict__ lnb,
        __half* __restrict__ Y, int M, int K) {
    extern __shared__ __half smh[];
    const uint32_t sb = smem_u32(smh);
    const int N = 256;

    const int t = threadIdx.x;
    const int lane = t & 31, gid = lane >> 2, tig = lane & 3;
    const int wid = t >> 5;
    const int wm = (wid & 1) * 32;
    const int wn = (wid >> 1) * 64;
    const int wcol = wid >> 1;
    const int m0 = blockIdx.y * 64;
    const int nc = K >> 5;

    const int ra = ((lane & 8) ? 8 : 0) + (lane & 7);
    const int ca = (lane & 16) ? 8 : 0;
    const int rb = ((lane & 16) ? 8 : 0) + (lane & 7);
    const int cb = (lane & 8) ? 8 : 0;

    auto load_chunk = [&](int c, int s) {
        int k0 = c * 32;
        uint32_t base = sb + (s * G6STAGE) * 2;
#pragma unroll
        for (int i = 0; i < 5; i++) {
            int u = i * 256 + t;            // 0..1279
            int r = u >> 2, q = u & 3;      // r 0..319
            const __half* src = (r < 64)
                ? A + (size_t)(m0 + r) * K + k0 + q * 8
                : W + (size_t)(r - 64) * K + k0 + q * 8;
            CPA16(base + (r * G6STR + q * 8) * 2, src);
        }
    };

    load_chunk(0, 0); CPA_COMMIT();
    load_chunk(1, 1); CPA_COMMIT();

    float acc[2][8][4];
#pragma unroll
    for (int mi = 0; mi < 2; mi++)
#pragma unroll
        for (int ni = 0; ni < 8; ni++)
#pragma unroll
            for (int j = 0; j < 4; j++) acc[mi][ni][j] = 0.f;

    for (int c = 0; c < nc; c++) {
        CPA_WAIT1();
        __syncthreads();

        uint32_t sA = sb + (c % 3) * (G6STAGE * 2);
        uint32_t sW = sA + 64 * G6STR * 2;
#pragma unroll
        for (int ks = 0; ks < 2; ks++) {
            unsigned a[2][4], b[8][2];
#pragma unroll
            for (int mi = 0; mi < 2; mi++)
                ldsm_x4(a[mi], sA + ((wm + mi * 16 + ra) * G6STR + ks * 16 + ca) * 2);
#pragma unroll
            for (int nb = 0; nb < 4; nb++) {
                unsigned bt[4];
                ldsm_x4(bt, sW + ((wn + nb * 16 + rb) * G6STR + ks * 16 + cb) * 2);
                b[2 * nb][0]     = bt[0]; b[2 * nb][1]     = bt[1];
                b[2 * nb + 1][0] = bt[2]; b[2 * nb + 1][1] = bt[3];
            }
#pragma unroll
            for (int mi = 0; mi < 2; mi++)
#pragma unroll
                for (int ni = 0; ni < 8; ni++)
                    mma_f16(acc[mi][ni], a[mi], b[ni]);
        }

        if (c + 2 < nc) load_chunk(c + 2, (c + 2) % 3);
        CPA_COMMIT();
    }

    __syncthreads();                       // all warps past last compute; smem reusable
    float* red = (float*)smh;              // [64 rows][4 wcol][2]

    float s_[2][2], q_[2][2];
#pragma unroll
    for (int mi = 0; mi < 2; mi++) { s_[mi][0] = s_[mi][1] = q_[mi][0] = q_[mi][1] = 0.f; }

#pragma unroll
    for (int mi = 0; mi < 2; mi++) {
#pragma unroll
        for (int ni = 0; ni < 8; ni++) {
            int cn = wn + ni * 8 + 2 * tig;
            float b0 = bias[cn], b1 = bias[cn + 1];
#pragma unroll
            for (int hf = 0; hf < 2; hf++) {
                int rr = m0 + wm + mi * 16 + gid + hf * 8;
                float v0 = acc[mi][ni][hf * 2 + 0] + b0;
                float v1 = acc[mi][ni][hf * 2 + 1] + b1;
                if (RES) {
                    const float* cp = C + (size_t)rr * N + cn;
                    v0 += cp[0]; v1 += cp[1];
                }
                float* cp = C + (size_t)rr * N + cn;
                cp[0] = v0; cp[1] = v1;
                acc[mi][ni][hf * 2 + 0] = v0;
                acc[mi][ni][hf * 2 + 1] = v1;
                if (LNF) {
                    s_[mi][hf] += v0 + v1;
                    q_[mi][hf] += v0 * v0 + v1 * v1;
                }
            }
        }
    }

    if (LNF) {
#pragma unroll
        for (int mi = 0; mi < 2; mi++)
#pragma unroll
            for (int hf = 0; hf < 2; hf++) {
                s_[mi][hf] += __shfl_xor_sync(0xffffffffu, s_[mi][hf], 1);
                s_[mi][hf] += __shfl_xor_sync(0xffffffffu, s_[mi][hf], 2);
                q_[mi][hf] += __shfl_xor_sync(0xffffffffu, q_[mi][hf], 1);
                q_[mi][hf] += __shfl_xor_sync(0xffffffffu, q_[mi][hf], 2);
            }
        if (tig == 0) {
#pragma unroll
            for (int mi = 0; mi < 2; mi++)
#pragma unroll
                for (int hf = 0; hf < 2; hf++) {
                    int rl = wm + mi * 16 + gid + hf * 8;
                    red[rl * 8 + wcol * 2 + 0] = s_[mi][hf];
                    red[rl * 8 + wcol * 2 + 1] = q_[mi][hf];
                }
        }
        __syncthreads();
#pragma unroll
        for (int mi = 0; mi < 2; mi++) {
#pragma unroll
            for (int hf = 0; hf < 2; hf++) {
                int rl = wm + mi * 16 + gid + hf * 8;
                float su = 0.f, sq = 0.f;
#pragma unroll
                for (int w = 0; w < 4; w++) {
                    su += red[rl * 8 + w * 2];
                    sq += red[rl * 8 + w * 2 + 1];
                }
                float mean = su * (1.f / 256.f);
                float var  = sq * (1.f / 256.f) - mean * mean;
                float rstd = rsqrtf(var + 1e-5f);
                __half* yp = Y + (size_t)(m0 + rl) * N;
#pragma unroll
                for (int ni = 0; ni < 8; ni++) {
                    int cn = wn + ni * 8 + 2 * tig;
                    float v0 = acc[mi][ni][hf * 2 + 0];
                    float v1 = acc[mi][ni][hf * 2 + 1];
                    *(__half2*)(yp + cn) = __floats2half2_rn(
                        (v0 - mean) * rstd * lnw[cn] + lnb[cn],
                        (v1 - mean) * rstd * lnw[cn + 1] + lnb[cn + 1]);
                }
            }
        }
    }
}

// ---------------------------------------------------------------------------
// build_tok fused with layer-0 ln1.
// ---------------------------------------------------------------------------
__global__ void build_tok_ln(const float* __restrict__ cls, int B,
                             const float* __restrict__ w, const float* __restrict__ bb) {
    int tk = blockIdx.x;
    __shared__ int sbv;
    if (threadIdx.x == 0) {
        int lo = 0, hi = B - 1;
        while (lo < hi) {
            int mid = (lo + hi + 1) >> 1;
            if (g_start[mid] + mid <= tk) lo = mid; else hi = mid - 1;
        }
        sbv = lo;
    }
    __syncthreads();
    int b = sbv;
    int i = threadIdx.x;
    float v;
    if (tk == g_start[b] + b) v = cls[i];
    else                      v = g_att[(size_t)(tk - b - 1) * DM + i];
    g_tok[(size_t)tk * DM + i] = v;

    __shared__ float red[8];
    float s = v;
#pragma unroll
    for (int o = 16; o; o >>= 1) s += __shfl_xor_sync(0xffffffffu, s, o);
    if ((i & 31) == 0) red[i >> 5] = s;
    __syncthreads();
    float tot = 0.f;
#pragma unroll
    for (int k = 0; k < 8; k++) tot += red[k];
    float mean = tot * (1.f / DM);
    float d = v - mean;
    float s2 = d * d;
#pragma unroll
    for (int o = 16; o; o >>= 1) s2 += __shfl_xor_sync(0xffffffffu, s2, o);
    __syncthreads();
    if ((i & 31) == 0) red[i >> 5] = s2;
    __syncthreads();
    float tv = 0.f;
#pragma unroll
    for (int k = 0; k < 8; k++) tv += red[k];
    float var = tv * (1.f / DM);
    g_bufh[(size_t)tk * DM + i] = __float2half_rn(d * rsqrtf(var + 1e-5f) * w[i] + bb[i]);
}

// ---------------------------------------------------------------------------
// Ragged flash attention (unchanged from R13).
// ---------------------------------------------------------------------------
#define MAXQC 12
#define ASTR  72
#define AREG  (64 * ASTR)
#define ATT_SMEM (4 * AREG * 2)

__global__ void __launch_bounds__(128) attn_h() {
    extern __shared__ __half ash[];
    __half* Qs = ash;
    __half* Ks = Qs + AREG;
    __half* Vs = Ks + AREG;
    __half* Ps = Vs + AREG;
    const uint32_t sbQ = smem_u32(ash);
    const uint32_t sbK = sbQ + AREG * 2;
    const uint32_t sbV = sbK + AREG * 2;
    const uint32_t sbP = sbV + AREG * 2;

    int b  = blockIdx.x, h = blockIdx.y;
    int s0 = g_start[b];
    int L  = g_start[b + 1] - s0 + 1;
    int qc = blockIdx.z * 64;
    if (qc >= L) return;
    int t0 = s0 + b;

    int t = threadIdx.x, lane = t & 31, wid = t >> 5;
    int gid = lane >> 2, tig = lane & 3;
    int wm = wid * 16;
    int lr = t >> 1, lc = (t & 1) * 32;

    const int ra = ((lane & 8) ? 8 : 0) + (lane & 7);
    const int ca = (lane & 16) ? 8 : 0;
    const int rb = ((lane & 16) ? 8 : 0) + (lane & 7);
    const int cb = (lane & 8) ? 8 : 0;

    {
        bool v = (qc + lr) < L;
        const __half* qp = g_qkvh + (size_t)(t0 + qc + lr) * 768 + h * HDIM + lc;
        __half* d = Qs + lr * ASTR + lc;
        uint4 z = make_uint4(0, 0, 0, 0);
#pragma unroll
        for (int u = 0; u < 4; u++)
            *(uint4*)(d + u * 8) = v ? *(const uint4*)(qp + u * 8) : z;
    }

    float mr0 = -1e30f, mr1 = -1e30f, l0 = 0.f, l1 = 0.f;
    float O[8][4];
#pragma unroll
    for (int ni = 0; ni < 8; ni++)
#pragma unroll
        for (int j = 0; j < 4; j++) O[ni][j] = 0.f;

    const float scale = 0.125f;

    for (int kc = 0; kc < L; kc += 64) {
        __syncthreads();
        {
            bool v = (kc + lr) < L;
            const __half* kp = g_qkvh + (size_t)(t0 + kc + lr) * 768 + 256 + h * HDIM + lc;
            const __half* vp = kp + 256;
            __half* kd = Ks + lr * ASTR + lc;
            __half* vd = Vs + lr * ASTR + lc;
            uint4 z = make_uint4(0, 0, 0, 0);
#pragma unroll
            for (int u = 0; u < 4; u++) {
                *(uint4*)(kd + u * 8) = v ? *(const uint4*)(kp + u * 8) : z;
                *(uint4*)(vd + u * 8) = v ? *(const uint4*)(vp + u * 8) : z;
            }
        }
        __syncthreads();

        float S[8][4];
#pragma unroll
        for (int ni = 0; ni < 8; ni++)
#pragma unroll
            for (int j = 0; j < 4; j++) S[ni][j] = 0.f;
#pragma unroll
        for (int ks = 0; ks < 4; ks++) {
            unsigned a[4];
            ldsm_x4(a, sbQ + ((wm + ra) * ASTR + ks * 16 + ca) * 2);
#pragma unroll
            for (int nb = 0; nb < 8; nb += 2) {
                unsigned bt[4];
                ldsm_x4(bt, sbK + ((nb * 8 + rb) * ASTR + ks * 16 + cb) * 2);
                mma_f16(S[nb],     a, bt);
                mma_f16(S[nb + 1], a, bt + 2);
            }
        }

        float rm0 = -1e30f, rm1 = -1e30f;
#pragma unroll
        for (int ni = 0; ni < 8; ni++) {
            int j0 = kc + ni * 8 + 2 * tig;
            bool v0 = j0 < L, v1 = (j0 + 1) < L;
            S[ni][0] = v0 ? S[ni][0] * scale : -1e30f;
            S[ni][1] = v1 ? S[ni][1] * scale : -1e30f;
            S[ni][2] = v0 ? S[ni][2] * scale : -1e30f;
            S[ni][3] = v1 ? S[ni][3] * scale : -1e30f;
            rm0 = fmaxf(rm0, fmaxf(S[ni][0], S[ni][1]));
            rm1 = fmaxf(rm1, fmaxf(S[ni][2], S[ni][3]));
        }
        rm0 = fmaxf(rm0, __shfl_xor_sync(0xffffffffu, rm0, 1));
        rm0 = fmaxf(rm0, __shfl_xor_sync(0xffffffffu, rm0, 2));
        rm1 = fmaxf(rm1, __shfl_xor_sync(0xffffffffu, rm1, 1));
        rm1 = fmaxf(rm1, __shfl_xor_sync(0xffffffffu, rm1, 2));
        float mn0 = fmaxf(mr0, rm0), mn1 = fmaxf(mr1, rm1);
        float cr0 = __expf(mr0 - mn0), cr1 = __expf(mr1 - mn1);
        float sum0 = 0.f, sum1 = 0.f;
        __half* pr0 = Ps + (wm + gid) * ASTR;
        __half* pr1 = Ps + (wm + gid + 8) * ASTR;
#pragma unroll
        for (int ni = 0; ni < 8; ni++) {
            int col = ni * 8 + 2 * tig;
            float p0 = __expf(S[ni][0] - mn0);
            float p1 = __expf(S[ni][1] - mn0);
            float p2 = __expf(S[ni][2] - mn1);
            float p3 = __expf(S[ni][3] - mn1);
            sum0 += p0 + p1; sum1 += p2 + p3;
            *(__half2*)(pr0 + col) = __floats2half2_rn(p0, p1);
            *(__half2*)(pr1 + col) = __floats2half2_rn(p2, p3);
        }
        sum0 += __shfl_xor_sync(0xffffffffu, sum0, 1);
        sum0 += __shfl_xor_sync(0xffffffffu, sum0, 2);
        sum1 += __shfl_xor_sync(0xffffffffu, sum1, 1);
        sum1 += __shfl_xor_sync(0xffffffffu, sum1, 2);
        l0 = l0 * cr0 + sum0;
        l1 = l1 * cr1 + sum1;
        mr0 = mn0; mr1 = mn1;
#pragma unroll
        for (int ni = 0; ni < 8; ni++) {
            O[ni][0] *= cr0; O[ni][1] *= cr0;
            O[ni][2] *= cr1; O[ni][3] *= cr1;
        }
        __syncwarp();

#pragma unroll
        for (int ks = 0; ks < 4; ks++) {
            unsigned a[4];
            ldsm_x4(a, sbP + ((wm + ra) * ASTR + ks * 16 + ca) * 2);
#pragma unroll
            for (int nb = 0; nb < 8; nb += 2) {
                unsigned bt[4];
                ldsm_x4t(bt, sbV + ((ks * 16 + ra) * ASTR + nb * 8 + ca) * 2);
                mma_f16(O[nb],     a, bt);
                mma_f16(O[nb + 1], a, bt + 2);
            }
        }
        __syncwarp();
    }

    float inv0 = 1.f / l0, inv1 = 1.f / l1;
    int q0 = qc + wm + gid, q1 = q0 + 8;
#pragma unroll
    for (int ni = 0; ni < 8; ni++) {
        int col = h * HDIM + ni * 8 + 2 * tig;
        if (q0 < L)
            *(__half2*)(g_bufh + (size_t)(t0 + q0) * DM + col) =
                __floats2half2_rn(O[ni][0] * inv0, O[ni][1] * inv0);
        if (q1 < L)
            *(__half2*)(g_bufh + (size_t)(t0 + q1) * DM + col) =
                __floats2half2_rn(O[ni][2] * inv1, O[ni][3] * inv1);
    }
}

// ---------------------------------------------------------------------------
__global__ void gather_cls() {
    int b = blockIdx.x, d = threadIdx.x;
    g_bufh[(size_t)b * DM + d] = __float2half_rn(g_tok[(size_t)(g_start[b] + b) * DM + d]);
}

__global__ void head2_kernel(const float* __restrict__ hid, const float* __restrict__ w2,
                             const float* __restrict__ b2, float* __restrict__ out, int B) {
    int t = blockIdx.x * blockDim.x + threadIdx.x;
    if (t >= B * 2) return;
    int b = t >> 1, j = t & 1;
    const float* hr = hid + (size_t)b * DM;
    const float* wr = w2 + (size_t)j * DM;
    float s = 0.f;
#pragma unroll 8
    for (int k = 0; k < DM; k++) s += hr[k] * wr[k];
    out[t] = s + b2[j];
}

// ---------------------------------------------------------------------------
extern "C" void kernel_launch(void* const* d_in, const int* in_sizes, int n_in,
                              void* d_out, int out_size) {
    const float* dom_emb = (const float*)d_in[0];
    const int*   ev      = (const int*)  d_in[1];
    const float* geom    = (const float*)d_in[3];
    const float* in_b    = (const float*)d_in[5];
    const float* geo_b   = (const float*)d_in[7];
    const float* cls     = (const float*)d_in[8];
    const float* qkv_b   = (const float*)d_in[10];
    const float* out_b   = (const float*)d_in[12];
    const float* ln1w    = (const float*)d_in[13];
    const float* ln1b    = (const float*)d_in[14];
    const float* ln2w    = (const float*)d_in[15];
    const float* ln2b    = (const float*)d_in[16];
    const float* ffb1    = (const float*)d_in[18];
    const float* ffb2    = (const float*)d_in[20];
    const float* hb1     = (const float*)d_in[22];
    const float* hw2     = (const float*)d_in[23];
    const float* hb2     = (const float*)d_in[24];
    float* out = (float*)d_out;

    int N  = in_sizes[0] / D_INP;
    int B  = out_size / 2;
    int NT = N + B;

    float  *p_tok, *p_att;
    __half *p_bufh, *p_qkvh, *p_ffh, *p_wh;
    cudaGetSymbolAddress((void**)&p_tok,  g_tok);
    cudaGetSymbolAddress((void**)&p_att,  g_att);
    cudaGetSymbolAddress((void**)&p_bufh, g_bufh);
    cudaGetSymbolAddress((void**)&p_qkvh, g_qkvh);
    cudaGetSymbolAddress((void**)&p_ffh,  g_ffh);
    cudaGetSymbolAddress((void**)&p_wh,   g_wtsh);

    static bool attrs_done = false;
    if (!attrs_done) {
        cudaFuncSetAttribute(gemm5<false, false, false>, cudaFuncAttributeMaxDynamicSharedMemorySize, G5SMEM);
        cudaFuncSetAttribute(gemm5<false, true,  false>, cudaFuncAttributeMaxDynamicSharedMemorySize, G5SMEM);
        cudaFuncSetAttribute(gemm5<false, false, true >, cudaFuncAttributeMaxDynamicSharedMemorySize, G5SMEM);
        cudaFuncSetAttribute(gemm5<true,  false, true >, cudaFuncAttributeMaxDynamicSharedMemorySize, G5SMEM);
        cudaFuncSetAttribute(gemm5<true,  false, false>, cudaFuncAttributeMaxDynamicSharedMemorySize, G5SMEM);
        cudaFuncSetAttribute(gemm6<true,  true >, cudaFuncAttributeMaxDynamicSharedMemorySize, G6SMEM);
        cudaFuncSetAttribute(gemm6<true,  false>, cudaFuncAttributeMaxDynamicSharedMemorySize, G6SMEM);
        cudaFuncSetAttribute(attn_h, cudaFuncAttributeMaxDynamicSharedMemorySize, ATT_SMEM);
        attrs_done = true;
    }

    // ---- batched fp16 conversions ----
    {
        int na0 = DM * D_INP, na1 = DM * DM, na2 = NL * 3 * DM * DM, na3 = NL * DM * DM;
        int ta = na0 + na1 + na2 + na3;
        cvt4<<<(ta + 255) / 256, 256>>>(
            (const float*)d_in[4], na0, (const float*)d_in[6], na1,
            (const float*)d_in[9], na2, (const float*)d_in[11], na3, p_wh + W_IN);
        int nb0 = NL * DFF * DM, nb1 = NL * DM * DFF, nb2 = DM * DM;
        int tb = nb0 + nb1 + nb2;
        cvt4<<<(tb + 255) / 256, 256>>>(
            (const float*)d_in[17], nb0, (const float*)d_in[19], nb1,
            (const float*)d_in[21], nb2, nullptr, 0, p_wh + W_FF1);
    }
    starts_kernel<<<1, 256>>>(ev, N, B);
    posenc_kernel<<<N, 128>>>(geom);
    cvt_half<<<(N * D_INP + 255) / 256, 256>>>(dom_emb, p_ffh, N * D_INP);

    int mg  = NT / 128;
    int mgN = N / 128;

    gemm5<false, false, false><<<dim3(DM / 128, mgN), 256, G5SMEM>>>(
        p_ffh,  p_wh + W_IN,  in_b,  p_att, nullptr, N, DM, D_INP);
    gemm5<false, true,  false><<<dim3(DM / 128, mgN), 256, G5SMEM>>>(
        p_bufh, p_wh + W_GEO, geo_b, p_att, nullptr, N, DM, DM);
    build_tok_ln<<<NT, 256>>>(cls, B, ln1w, ln1b);

    for (int l = 0; l < NL; l++) {
        gemm5<false, false, true><<<dim3(3 * DM / 128, mg), 256, G5SMEM>>>(
            p_bufh, p_wh + W_QKV + (size_t)l * 3 * DM * DM, qkv_b + (size_t)l * 3 * DM,
            nullptr, p_qkvh, NT, 3 * DM, DM);
        attn_h<<<dim3(B, NH, MAXQC), 128, ATT_SMEM>>>();
        // out-proj + residual -> g_tok, fused ln2 -> g_bufh
        gemm6<true, true><<<dim3(1, NT / 64), 256, G6SMEM>>>(
            p_bufh, p_wh + W_OUT + (size_t)l * DM * DM, out_b + (size_t)l * DM,
            p_tok, ln2w + l * DM, ln2b + l * DM, p_bufh, NT, DM);
        gemm5<true, false, true><<<dim3(DFF / 128, mg), 256, G5SMEM>>>(
            p_bufh, p_wh + W_FF1 + (size_t)l * DFF * DM, ffb1 + (size_t)l * DFF,
            nullptr, p_ffh, NT, DFF, DM);
        if (l < NL - 1) {
            // ff2 + residual -> g_tok, fused next-layer ln1 -> g_bufh
            gemm6<true, true><<<dim3(1, NT / 64), 256, G6SMEM>>>(
                p_ffh, p_wh + W_FF2 + (size_t)l * DM * DFF, ffb2 + (size_t)l * DM,
                p_tok, ln1w + (l + 1) * DM, ln1b + (l + 1) * DM, p_bufh, NT, DFF);
        } else {
            gemm6<true, false><<<dim3(1, NT / 64), 256, G6SMEM>>>(
                p_ffh, p_wh + W_FF2 + (size_t)l * DM * DFF, ffb2 + (size_t)l * DM,
                p_tok, nullptr, nullptr, nullptr, NT, DFF);
        }
    }

    gather_cls<<<B, 256>>>();
    gemm5<true, false, false><<<dim3(DM / 128, 1), 256, G5SMEM>>>(
        p_bufh, p_wh + W_HEAD, hb1, p_att, nullptr, B, DM, DM);
    head2_kernel<<<1, 256>>>(p_att, hw2, hb2, out, B);
}

// round 15
// speedup vs baseline: 2.4429x; 1.0307x over previous
#include <cuda_runtime.h>
#include <cuda_fp16.h>
#include <math.h>
#include <stdint.h>

// ============================================================================
// EventTransformer — ragged formulation; fp16 mma.sync (m16n8k16, fp32 accum)
// GEMMs + flash attention (128-row Q tiles), ldmatrix fragment loads,
// LayerNorm fused into DM-wide GEMM epilogues. Residual stream fp32.
// ============================================================================

#define D_INP 128
#define DM    256
#define NH    4
#define HDIM  64
#define NL    4
#define DFF   1024
#define NMAXD 65536
#define BMAXD 128
#define NTMAX (NMAXD + BMAXD)

__device__ float  g_tok[(size_t)NTMAX * DM];      // residual h (fp32)
__device__ float  g_att[(size_t)NTMAX * DM];      // embed accum / head hidden (fp32)
__device__ __half g_bufh[(size_t)NTMAX * DM];     // LN out / posenc / attn out / cls
__device__ __half g_qkvh[(size_t)NTMAX * 3 * DM]; // QKV (fp16)
__device__ __half g_ffh [(size_t)NTMAX * DFF];    // FF hidden / staged dom_emb (fp16)
__device__ int    g_start[BMAXD + 1];

// converted weights (fp16), contiguous in this order
#define W_IN   0
#define W_GEO  (W_IN   + DM * D_INP)
#define W_QKV  (W_GEO  + DM * DM)
#define W_OUT  (W_QKV  + NL * 3 * DM * DM)
#define W_FF1  (W_OUT  + NL * DM * DM)
#define W_FF2  (W_FF1  + NL * DFF * DM)
#define W_HEAD (W_FF2  + NL * DM * DFF)
#define W_TOT  (W_HEAD + DM * DM)
__device__ __half g_wtsh[W_TOT];

// ---------------------------------------------------------------------------
__device__ __forceinline__ uint32_t smem_u32(const void* p) {
    uint32_t a;
    asm("{ .reg .u64 t; cvta.to.shared.u64 t, %1; cvt.u32.u64 %0, t; }" : "=r"(a) : "l"(p));
    return a;
}
__device__ __forceinline__ void mma_f16(float c[4], const unsigned a[4], const unsigned b[2]) {
    asm volatile(
        "mma.sync.aligned.m16n8k16.row.col.f32.f16.f16.f32 "
        "{%0,%1,%2,%3}, {%4,%5,%6,%7}, {%8,%9}, {%0,%1,%2,%3};"
        : "+f"(c[0]), "+f"(c[1]), "+f"(c[2]), "+f"(c[3])
        : "r"(a[0]), "r"(a[1]), "r"(a[2]), "r"(a[3]), "r"(b[0]), "r"(b[1]));
}
__device__ __forceinline__ void ldsm_x4(unsigned r[4], uint32_t addr) {
    asm volatile("ldmatrix.sync.aligned.m8n8.x4.shared.b16 {%0,%1,%2,%3}, [%4];"
                 : "=r"(r[0]), "=r"(r[1]), "=r"(r[2]), "=r"(r[3]) : "r"(addr));
}
__device__ __forceinline__ void ldsm_x4t(unsigned r[4], uint32_t addr) {
    asm volatile("ldmatrix.sync.aligned.m8n8.x4.trans.shared.b16 {%0,%1,%2,%3}, [%4];"
                 : "=r"(r[0]), "=r"(r[1]), "=r"(r[2]), "=r"(r[3]) : "r"(addr));
}
#define CPA16(dst, src) \
    asm volatile("cp.async.cg.shared.global [%0], [%1], 16;" \
                 :: "r"(dst), "l"(src) : "memory")
#define CPA_COMMIT() asm volatile("cp.async.commit_group;" ::: "memory")
#define CPA_WAIT1()  asm volatile("cp.async.wait_group 1;" ::: "memory")

// ---------------------------------------------------------------------------
__global__ void cvt_half(const float* __restrict__ src, __half* __restrict__ dst, int n) {
    int i = blockIdx.x * 256 + threadIdx.x;
    if (i < n) dst[i] = __float2half_rn(src[i]);
}

__global__ void cvt4(const float* p0, int n0, const float* p1, int n1,
                     const float* p2, int n2, const float* p3, int n3,
                     __half* __restrict__ dst) {
    int i = blockIdx.x * 256 + threadIdx.x;
    const float* s; int off;
    if (i < n0)                     { s = p0; off = 0; }
    else if (i < n0 + n1)           { s = p1; off = n0; }
    else if (i < n0 + n1 + n2)      { s = p2; off = n0 + n1; }
    else if (i < n0 + n1 + n2 + n3) { s = p3; off = n0 + n1 + n2; }
    else return;
    dst[i] = __float2half_rn(s[i - off]);
}

__global__ void starts_kernel(const int* __restrict__ ev, int N, int B) {
    int b = blockIdx.x * blockDim.x + threadIdx.x;
    if (b > B) return;
    if (b == B) { g_start[B] = N; return; }
    int lo = 0, hi = N;
    while (lo < hi) {
        int mid = (lo + hi) >> 1;
        if (ev[mid] < b) lo = mid + 1; else hi = mid;
    }
    g_start[b] = lo;
}

__global__ void posenc_kernel(const float* __restrict__ geom) {
    int i  = blockIdx.x;
    int c2 = threadIdx.x;
    float v0 = 0.f, v1 = 0.f;
    if (c2 < 126) {
        int dax  = c2 / 42;
        int band = c2 % 42;
        float f   = exp2f((float)band * 0.08102263646065820f); // log2(10)/41
        float ang = 6.283185307179586f * geom[i * 3 + dax] * f;
        sincosf(ang, &v0, &v1);
    }
    *(__half2*)(g_bufh + (size_t)i * DM + 2 * c2) = __floats2half2_rn(v0, v1);
}

// ---------------------------------------------------------------------------
// gemm5 (proven R13): BM=BN=128, BK=32, 8 warps 64x32, ldmatrix, 3-stage.
// ---------------------------------------------------------------------------
#define G5STR   40
#define G5TILE  (128 * G5STR)
#define G5STAGE (2 * G5TILE)
#define G5SMEM  (3 * G5STAGE * 2)

template<bool RELU, bool RES, bool HOUT>
__global__ void __launch_bounds__(256, 2) gemm5(
        const __half* __restrict__ A, const __half* __restrict__ W,
        const float* __restrict__ bias, float* __restrict__ C,
        __half* __restrict__ H, int M, int N, int K) {
    extern __shared__ __half smh[];
    const uint32_t sb = smem_u32(smh);

    const int t = threadIdx.x;
    const int lane = t & 31, gid = lane >> 2, tig = lane & 3;
    const int wid = t >> 5;
    const int wm = (wid & 1) * 64;
    const int wn = (wid >> 1) * 32;
    const int m0 = blockIdx.y * 128, n0 = blockIdx.x * 128;
    const int nc = K >> 5;

    const int ra = ((lane & 8) ? 8 : 0) + (lane & 7);
    const int ca = (lane & 16) ? 8 : 0;
    const int rb = ((lane & 16) ? 8 : 0) + (lane & 7);
    const int cb = (lane & 8) ? 8 : 0;

    auto load_chunk = [&](int c, int s) {
        int k0 = c * 32;
        uint32_t abase = sb + (s * G5STAGE) * 2;
        uint32_t wbase = abase + G5TILE * 2;
#pragma unroll
        for (int i = 0; i < 2; i++) {
            int u = i * 256 + t;
            int r = u >> 2, q = u & 3;
            CPA16(abase + (r * G5STR + q * 8) * 2, A + (size_t)(m0 + r) * K + k0 + q * 8);
            CPA16(wbase + (r * G5STR + q * 8) * 2, W + (size_t)(n0 + r) * K + k0 + q * 8);
        }
    };

    load_chunk(0, 0); CPA_COMMIT();
    load_chunk(1, 1); CPA_COMMIT();

    float acc[4][4][4];
#pragma unroll
    for (int mi = 0; mi < 4; mi++)
#pragma unroll
        for (int ni = 0; ni < 4; ni++)
#pragma unroll
            for (int j = 0; j < 4; j++) acc[mi][ni][j] = 0.f;

    for (int c = 0; c < nc; c++) {
        CPA_WAIT1();
        __syncthreads();

        uint32_t sA = sb + (c % 3) * (G5STAGE * 2);
        uint32_t sW = sA + G5TILE * 2;
#pragma unroll
        for (int ks = 0; ks < 2; ks++) {
            unsigned a[4][4], b[4][2];
#pragma unroll
            for (int mi = 0; mi < 4; mi++)
                ldsm_x4(a[mi], sA + ((wm + mi * 16 + ra) * G5STR + ks * 16 + ca) * 2);
            {
                unsigned bt[4];
                ldsm_x4(bt, sW + ((wn + rb) * G5STR + ks * 16 + cb) * 2);
                b[0][0] = bt[0]; b[0][1] = bt[1]; b[1][0] = bt[2]; b[1][1] = bt[3];
                ldsm_x4(bt, sW + ((wn + 16 + rb) * G5STR + ks * 16 + cb) * 2);
                b[2][0] = bt[0]; b[2][1] = bt[1]; b[3][0] = bt[2]; b[3][1] = bt[3];
            }
#pragma unroll
            for (int mi = 0; mi < 4; mi++)
#pragma unroll
                for (int ni = 0; ni < 4; ni++)
                    mma_f16(acc[mi][ni], a[mi], b[ni]);
        }

        if (c + 2 < nc) load_chunk(c + 2, (c + 2) % 3);
        CPA_COMMIT();
    }

#pragma unroll
    for (int mi = 0; mi < 4; mi++) {
#pragma unroll
        for (int ni = 0; ni < 4; ni++) {
            int r  = m0 + wm + mi * 16 + gid;
            int cn = n0 + wn + ni * 8 + 2 * tig;
            float b0 = bias[cn], b1 = bias[cn + 1];
#pragma unroll
            for (int hf = 0; hf < 2; hf++) {
                int rr = r + hf * 8;
                float v0 = acc[mi][ni][hf * 2 + 0] + b0;
                float v1 = acc[mi][ni][hf * 2 + 1] + b1;
                if (RES) {
                    const float* cp = C + (size_t)rr * N + cn;
                    v0 += cp[0]; v1 += cp[1];
                }
                if (RELU) { v0 = fmaxf(v0, 0.f); v1 = fmaxf(v1, 0.f); }
                if (HOUT) {
                    *(__half2*)(H + (size_t)rr * N + cn) = __floats2half2_rn(v0, v1);
                } else {
                    float* cp = C + (size_t)rr * N + cn;
                    cp[0] = v0; cp[1] = v1;
                }
            }
        }
    }
}

// ---------------------------------------------------------------------------
// gemm6 (proven R14): BM=64, BN=256, LN fused epilogue. N==256, grid.x==1.
// ---------------------------------------------------------------------------
#define G6STR   40
#define G6ROWS  320
#define G6STAGE (G6ROWS * G6STR)
#define G6SMEM  (3 * G6STAGE * 2)

template<bool RES, bool LNF>
__global__ void __launch_bounds__(256, 2) gemm6(
        const __half* __restrict__ A, const __half* __restrict__ W,
        const float* __restrict__ bias, float* __restrict__ C,
        const float* __restrict__ lnw, const float* __restrict__ lnb,
        __half* __restrict__ Y, int M, int K) {
    extern __shared__ __half smh[];
    const uint32_t sb = smem_u32(smh);
    const int N = 256;

    const int t = threadIdx.x;
    const int lane = t & 31, gid = lane >> 2, tig = lane & 3;
    const int wid = t >> 5;
    const int wm = (wid & 1) * 32;
    const int wn = (wid >> 1) * 64;
    const int wcol = wid >> 1;
    const int m0 = blockIdx.y * 64;
    const int nc = K >> 5;

    const int ra = ((lane & 8) ? 8 : 0) + (lane & 7);
    const int ca = (lane & 16) ? 8 : 0;
    const int rb = ((lane & 16) ? 8 : 0) + (lane & 7);
    const int cb = (lane & 8) ? 8 : 0;

    auto load_chunk = [&](int c, int s) {
        int k0 = c * 32;
        uint32_t base = sb + (s * G6STAGE) * 2;
#pragma unroll
        for (int i = 0; i < 5; i++) {
            int u = i * 256 + t;
            int r = u >> 2, q = u & 3;
            const __half* src = (r < 64)
                ? A + (size_t)(m0 + r) * K + k0 + q * 8
                : W + (size_t)(r - 64) * K + k0 + q * 8;
            CPA16(base + (r * G6STR + q * 8) * 2, src);
        }
    };

    load_chunk(0, 0); CPA_COMMIT();
    load_chunk(1, 1); CPA_COMMIT();

    float acc[2][8][4];
#pragma unroll
    for (int mi = 0; mi < 2; mi++)
#pragma unroll
        for (int ni = 0; ni < 8; ni++)
#pragma unroll
            for (int j = 0; j < 4; j++) acc[mi][ni][j] = 0.f;

    for (int c = 0; c < nc; c++) {
        CPA_WAIT1();
        __syncthreads();

        uint32_t sA = sb + (c % 3) * (G6STAGE * 2);
        uint32_t sW = sA + 64 * G6STR * 2;
#pragma unroll
        for (int ks = 0; ks < 2; ks++) {
            unsigned a[2][4], b[8][2];
#pragma unroll
            for (int mi = 0; mi < 2; mi++)
                ldsm_x4(a[mi], sA + ((wm + mi * 16 + ra) * G6STR + ks * 16 + ca) * 2);
#pragma unroll
            for (int nb = 0; nb < 4; nb++) {
                unsigned bt[4];
                ldsm_x4(bt, sW + ((wn + nb * 16 + rb) * G6STR + ks * 16 + cb) * 2);
                b[2 * nb][0]     = bt[0]; b[2 * nb][1]     = bt[1];
                b[2 * nb + 1][0] = bt[2]; b[2 * nb + 1][1] = bt[3];
            }
#pragma unroll
            for (int mi = 0; mi < 2; mi++)
#pragma unroll
                for (int ni = 0; ni < 8; ni++)
                    mma_f16(acc[mi][ni], a[mi], b[ni]);
        }

        if (c + 2 < nc) load_chunk(c + 2, (c + 2) % 3);
        CPA_COMMIT();
    }

    __syncthreads();
    float* red = (float*)smh;

    float s_[2][2], q_[2][2];
#pragma unroll
    for (int mi = 0; mi < 2; mi++) { s_[mi][0] = s_[mi][1] = q_[mi][0] = q_[mi][1] = 0.f; }

#pragma unroll
    for (int mi = 0; mi < 2; mi++) {
#pragma unroll
        for (int ni = 0; ni < 8; ni++) {
            int cn = wn + ni * 8 + 2 * tig;
            float b0 = bias[cn], b1 = bias[cn + 1];
#pragma unroll
            for (int hf = 0; hf < 2; hf++) {
                int rr = m0 + wm + mi * 16 + gid + hf * 8;
                float v0 = acc[mi][ni][hf * 2 + 0] + b0;
                float v1 = acc[mi][ni][hf * 2 + 1] + b1;
                if (RES) {
                    const float* cp = C + (size_t)rr * N + cn;
                    v0 += cp[0]; v1 += cp[1];
                }
                float* cp = C + (size_t)rr * N + cn;
                cp[0] = v0; cp[1] = v1;
                acc[mi][ni][hf * 2 + 0] = v0;
                acc[mi][ni][hf * 2 + 1] = v1;
                if (LNF) {
                    s_[mi][hf] += v0 + v1;
                    q_[mi][hf] += v0 * v0 + v1 * v1;
                }
            }
        }
    }

    if (LNF) {
#pragma unroll
        for (int mi = 0; mi < 2; mi++)
#pragma unroll
            for (int hf = 0; hf < 2; hf++) {
                s_[mi][hf] += __shfl_xor_sync(0xffffffffu, s_[mi][hf], 1);
                s_[mi][hf] += __shfl_xor_sync(0xffffffffu, s_[mi][hf], 2);
                q_[mi][hf] += __shfl_xor_sync(0xffffffffu, q_[mi][hf], 1);
                q_[mi][hf] += __shfl_xor_sync(0xffffffffu, q_[mi][hf], 2);
            }
        if (tig == 0) {
#pragma unroll
            for (int mi = 0; mi < 2; mi++)
#pragma unroll
                for (int hf = 0; hf < 2; hf++) {
                    int rl = wm + mi * 16 + gid + hf * 8;
                    red[rl * 8 + wcol * 2 + 0] = s_[mi][hf];
                    red[rl * 8 + wcol * 2 + 1] = q_[mi][hf];
                }
        }
        __syncthreads();
#pragma unroll
        for (int mi = 0; mi < 2; mi++) {
#pragma unroll
            for (int hf = 0; hf < 2; hf++) {
                int rl = wm + mi * 16 + gid + hf * 8;
                float su = 0.f, sq = 0.f;
#pragma unroll
                for (int w = 0; w < 4; w++) {
                    su += red[rl * 8 + w * 2];
                    sq += red[rl * 8 + w * 2 + 1];
                }
                float mean = su * (1.f / 256.f);
                float var  = sq * (1.f / 256.f) - mean * mean;
                float rstd = rsqrtf(var + 1e-5f);
                __half* yp = Y + (size_t)(m0 + rl) * N;
#pragma unroll
                for (int ni = 0; ni < 8; ni++) {
                    int cn = wn + ni * 8 + 2 * tig;
                    float v0 = acc[mi][ni][hf * 2 + 0];
                    float v1 = acc[mi][ni][hf * 2 + 1];
                    *(__half2*)(yp + cn) = __floats2half2_rn(
                        (v0 - mean) * rstd * lnw[cn] + lnb[cn],
                        (v1 - mean) * rstd * lnw[cn + 1] + lnb[cn + 1]);
                }
            }
        }
    }
}

// ---------------------------------------------------------------------------
__global__ void build_tok_ln(const float* __restrict__ cls, int B,
                             const float* __restrict__ w, const float* __restrict__ bb) {
    int tk = blockIdx.x;
    __shared__ int sbv;
    if (threadIdx.x == 0) {
        int lo = 0, hi = B - 1;
        while (lo < hi) {
            int mid = (lo + hi + 1) >> 1;
            if (g_start[mid] + mid <= tk) lo = mid; else hi = mid - 1;
        }
        sbv = lo;
    }
    __syncthreads();
    int b = sbv;
    int i = threadIdx.x;
    float v;
    if (tk == g_start[b] + b) v = cls[i];
    else                      v = g_att[(size_t)(tk - b - 1) * DM + i];
    g_tok[(size_t)tk * DM + i] = v;

    __shared__ float red[8];
    float s = v;
#pragma unroll
    for (int o = 16; o; o >>= 1) s += __shfl_xor_sync(0xffffffffu, s, o);
    if ((i & 31) == 0) red[i >> 5] = s;
    __syncthreads();
    float tot = 0.f;
#pragma unroll
    for (int k = 0; k < 8; k++) tot += red[k];
    float mean = tot * (1.f / DM);
    float d = v - mean;
    float s2 = d * d;
#pragma unroll
    for (int o = 16; o; o >>= 1) s2 += __shfl_xor_sync(0xffffffffu, s2, o);
    __syncthreads();
    if ((i & 31) == 0) red[i >> 5] = s2;
    __syncthreads();
    float tv = 0.f;
#pragma unroll
    for (int k = 0; k < 8; k++) tv += red[k];
    float var = tv * (1.f / DM);
    g_bufh[(size_t)tk * DM + i] = __float2half_rn(d * rsqrtf(var + 1e-5f) * w[i] + bb[i]);
}

// ---------------------------------------------------------------------------
// Ragged flash attention, 128-row Q tiles. grid = (B, NH, MAXQC2), 256 thr
// (8 warps; warp w owns Q rows [qc+16w, qc+16w+16)). Smem (halfs, stride 72):
// Qs[128][d], Ks[64][d], Vs[64][d] (row-major; trans-ldmatrix), Ps[128][j].
// Each K/V chunk load now serves 128 Q rows (2x reuse vs R14).
// ---------------------------------------------------------------------------
#define MAXQC2 6
#define ASTR  72
#define AQ_REG (128 * ASTR)
#define AK_REG (64 * ASTR)
#define ATT_SMEM ((AQ_REG + 2 * AK_REG + AQ_REG) * 2)

__global__ void __launch_bounds__(256) attn_h() {
    extern __shared__ __half ash[];
    __half* Qs = ash;
    __half* Ks = Qs + AQ_REG;
    __half* Vs = Ks + AK_REG;
    __half* Ps = Vs + AK_REG;
    const uint32_t sbQ = smem_u32(ash);
    const uint32_t sbK = sbQ + AQ_REG * 2;
    const uint32_t sbV = sbK + AK_REG * 2;
    const uint32_t sbP = sbV + AK_REG * 2;

    int b  = blockIdx.x, h = blockIdx.y;
    int s0 = g_start[b];
    int L  = g_start[b + 1] - s0 + 1;
    int qc = blockIdx.z * 128;
    if (qc >= L) return;
    int t0 = s0 + b;

    int t = threadIdx.x, lane = t & 31, wid = t >> 5;
    int gid = lane >> 2, tig = lane & 3;
    int wm = wid * 16;                    // 0..112

    const int ra = ((lane & 8) ? 8 : 0) + (lane & 7);
    const int ca = (lane & 16) ? 8 : 0;
    const int rb = ((lane & 16) ? 8 : 0) + (lane & 7);
    const int cb = (lane & 8) ? 8 : 0;

    // ---- load Q tile: 128 rows, 2 threads/row, 32 halfs each ----
    {
        int lr = t >> 1, lc = (t & 1) * 32;
        bool v = (qc + lr) < L;
        const __half* qp = g_qkvh + (size_t)(t0 + qc + lr) * 768 + h * HDIM + lc;
        __half* d = Qs + lr * ASTR + lc;
        uint4 z = make_uint4(0, 0, 0, 0);
#pragma unroll
        for (int u = 0; u < 4; u++)
            *(uint4*)(d + u * 8) = v ? *(const uint4*)(qp + u * 8) : z;
    }

    float mr0 = -1e30f, mr1 = -1e30f, l0 = 0.f, l1 = 0.f;
    float O[8][4];
#pragma unroll
    for (int ni = 0; ni < 8; ni++)
#pragma unroll
        for (int j = 0; j < 4; j++) O[ni][j] = 0.f;

    const float scale = 0.125f;

    for (int kc = 0; kc < L; kc += 64) {
        __syncthreads();
        // ---- load K/V chunk: 64 rows, 4 threads/row, 16 halfs each ----
        {
            int lr = t >> 2, lc = (t & 3) * 16;
            bool v = (kc + lr) < L;
            const __half* kp = g_qkvh + (size_t)(t0 + kc + lr) * 768 + 256 + h * HDIM + lc;
            const __half* vp = kp + 256;
            __half* kd = Ks + lr * ASTR + lc;
            __half* vd = Vs + lr * ASTR + lc;
            uint4 z = make_uint4(0, 0, 0, 0);
#pragma unroll
            for (int u = 0; u < 2; u++) {
                *(uint4*)(kd + u * 8) = v ? *(const uint4*)(kp + u * 8) : z;
                *(uint4*)(vd + u * 8) = v ? *(const uint4*)(vp + u * 8) : z;
            }
        }
        __syncthreads();

        // ---- S = Q @ K^T ----
        float S[8][4];
#pragma unroll
        for (int ni = 0; ni < 8; ni++)
#pragma unroll
            for (int j = 0; j < 4; j++) S[ni][j] = 0.f;
#pragma unroll
        for (int ks = 0; ks < 4; ks++) {
            unsigned a[4];
            ldsm_x4(a, sbQ + ((wm + ra) * ASTR + ks * 16 + ca) * 2);
#pragma unroll
            for (int nb = 0; nb < 8; nb += 2) {
                unsigned bt[4];
                ldsm_x4(bt, sbK + ((nb * 8 + rb) * ASTR + ks * 16 + cb) * 2);
                mma_f16(S[nb],     a, bt);
                mma_f16(S[nb + 1], a, bt + 2);
            }
        }

        // ---- online softmax (rows wm+gid, wm+gid+8) ----
        float rm0 = -1e30f, rm1 = -1e30f;
#pragma unroll
        for (int ni = 0; ni < 8; ni++) {
            int j0 = kc + ni * 8 + 2 * tig;
            bool v0 = j0 < L, v1 = (j0 + 1) < L;
            S[ni][0] = v0 ? S[ni][0] * scale : -1e30f;
            S[ni][1] = v1 ? S[ni][1] * scale : -1e30f;
            S[ni][2] = v0 ? S[ni][2] * scale : -1e30f;
            S[ni][3] = v1 ? S[ni][3] * scale : -1e30f;
            rm0 = fmaxf(rm0, fmaxf(S[ni][0], S[ni][1]));
            rm1 = fmaxf(rm1, fmaxf(S[ni][2], S[ni][3]));
        }
        rm0 = fmaxf(rm0, __shfl_xor_sync(0xffffffffu, rm0, 1));
        rm0 = fmaxf(rm0, __shfl_xor_sync(0xffffffffu, rm0, 2));
        rm1 = fmaxf(rm1, __shfl_xor_sync(0xffffffffu, rm1, 1));
        rm1 = fmaxf(rm1, __shfl_xor_sync(0xffffffffu, rm1, 2));
        float mn0 = fmaxf(mr0, rm0), mn1 = fmaxf(mr1, rm1);
        float cr0 = __expf(mr0 - mn0), cr1 = __expf(mr1 - mn1);
        float sum0 = 0.f, sum1 = 0.f;
        __half* pr0 = Ps + (wm + gid) * ASTR;
        __half* pr1 = Ps + (wm + gid + 8) * ASTR;
#pragma unroll
        for (int ni = 0; ni < 8; ni++) {
            int col = ni * 8 + 2 * tig;
            float p0 = __expf(S[ni][0] - mn0);
            float p1 = __expf(S[ni][1] - mn0);
            float p2 = __expf(S[ni][2] - mn1);
            float p3 = __expf(S[ni][3] - mn1);
            sum0 += p0 + p1; sum1 += p2 + p3;
            *(__half2*)(pr0 + col) = __floats2half2_rn(p0, p1);
            *(__half2*)(pr1 + col) = __floats2half2_rn(p2, p3);
        }
        sum0 += __shfl_xor_sync(0xffffffffu, sum0, 1);
        sum0 += __shfl_xor_sync(0xffffffffu, sum0, 2);
        sum1 += __shfl_xor_sync(0xffffffffu, sum1, 1);
        sum1 += __shfl_xor_sync(0xffffffffu, sum1, 2);
        l0 = l0 * cr0 + sum0;
        l1 = l1 * cr1 + sum1;
        mr0 = mn0; mr1 = mn1;
#pragma unroll
        for (int ni = 0; ni < 8; ni++) {
            O[ni][0] *= cr0; O[ni][1] *= cr0;
            O[ni][2] *= cr1; O[ni][3] *= cr1;
        }
        __syncwarp();   // warp-private P round-trip (rows wm..wm+15)

        // ---- O += P @ V ----
#pragma unroll
        for (int ks = 0; ks < 4; ks++) {
            unsigned a[4];
            ldsm_x4(a, sbP + ((wm + ra) * ASTR + ks * 16 + ca) * 2);
#pragma unroll
            for (int nb = 0; nb < 8; nb += 2) {
                unsigned bt[4];
                ldsm_x4t(bt, sbV + ((ks * 16 + ra) * ASTR + nb * 8 + ca) * 2);
                mma_f16(O[nb],     a, bt);
                mma_f16(O[nb + 1], a, bt + 2);
            }
        }
        __syncwarp();
    }

    float inv0 = 1.f / l0, inv1 = 1.f / l1;
    int q0 = qc + wm + gid, q1 = q0 + 8;
#pragma unroll
    for (int ni = 0; ni < 8; ni++) {
        int col = h * HDIM + ni * 8 + 2 * tig;
        if (q0 < L)
            *(__half2*)(g_bufh + (size_t)(t0 + q0) * DM + col) =
                __floats2half2_rn(O[ni][0] * inv0, O[ni][1] * inv0);
        if (q1 < L)
            *(__half2*)(g_bufh + (size_t)(t0 + q1) * DM + col) =
                __floats2half2_rn(O[ni][2] * inv1, O[ni][3] * inv1);
    }
}

// ---------------------------------------------------------------------------
__global__ void gather_cls() {
    int b = blockIdx.x, d = threadIdx.x;
    g_bufh[(size_t)b * DM + d] = __float2half_rn(g_tok[(size_t)(g_start[b] + b) * DM + d]);
}

__global__ void head2_kernel(const float* __restrict__ hid, const float* __restrict__ w2,
                             const float* __restrict__ b2, float* __restrict__ out, int B) {
    int t = blockIdx.x * blockDim.x + threadIdx.x;
    if (t >= B * 2) return;
    int b = t >> 1, j = t & 1;
    const float* hr = hid + (size_t)b * DM;
    const float* wr = w2 + (size_t)j * DM;
    float s = 0.f;
#pragma unroll 8
    for (int k = 0; k < DM; k++) s += hr[k] * wr[k];
    out[t] = s + b2[j];
}

// ---------------------------------------------------------------------------
extern "C" void kernel_launch(void* const* d_in, const int* in_sizes, int n_in,
                              void* d_out, int out_size) {
    const float* dom_emb = (const float*)d_in[0];
    const int*   ev      = (const int*)  d_in[1];
    const float* geom    = (const float*)d_in[3];
    const float* in_b    = (const float*)d_in[5];
    const float* geo_b   = (const float*)d_in[7];
    const float* cls     = (const float*)d_in[8];
    const float* qkv_b   = (const float*)d_in[10];
    const float* out_b   = (const float*)d_in[12];
    const float* ln1w    = (const float*)d_in[13];
    const float* ln1b    = (const float*)d_in[14];
    const float* ln2w    = (const float*)d_in[15];
    const float* ln2b    = (const float*)d_in[16];
    const float* ffb1    = (const float*)d_in[18];
    const float* ffb2    = (const float*)d_in[20];
    const float* hb1     = (const float*)d_in[22];
    const float* hw2     = (const float*)d_in[23];
    const float* hb2     = (const float*)d_in[24];
    float* out = (float*)d_out;

    int N  = in_sizes[0] / D_INP;
    int B  = out_size / 2;
    int NT = N + B;

    float  *p_tok, *p_att;
    __half *p_bufh, *p_qkvh, *p_ffh, *p_wh;
    cudaGetSymbolAddress((void**)&p_tok,  g_tok);
    cudaGetSymbolAddress((void**)&p_att,  g_att);
    cudaGetSymbolAddress((void**)&p_bufh, g_bufh);
    cudaGetSymbolAddress((void**)&p_qkvh, g_qkvh);
    cudaGetSymbolAddress((void**)&p_ffh,  g_ffh);
    cudaGetSymbolAddress((void**)&p_wh,   g_wtsh);

    static bool attrs_done = false;
    if (!attrs_done) {
        cudaFuncSetAttribute(gemm5<false, false, false>, cudaFuncAttributeMaxDynamicSharedMemorySize, G5SMEM);
        cudaFuncSetAttribute(gemm5<false, true,  false>, cudaFuncAttributeMaxDynamicSharedMemorySize, G5SMEM);
        cudaFuncSetAttribute(gemm5<false, false, true >, cudaFuncAttributeMaxDynamicSharedMemorySize, G5SMEM);
        cudaFuncSetAttribute(gemm5<true,  false, true >, cudaFuncAttributeMaxDynamicSharedMemorySize, G5SMEM);
        cudaFuncSetAttribute(gemm5<true,  false, false>, cudaFuncAttributeMaxDynamicSharedMemorySize, G5SMEM);
        cudaFuncSetAttribute(gemm6<true,  true >, cudaFuncAttributeMaxDynamicSharedMemorySize, G6SMEM);
        cudaFuncSetAttribute(gemm6<true,  false>, cudaFuncAttributeMaxDynamicSharedMemorySize, G6SMEM);
        cudaFuncSetAttribute(attn_h, cudaFuncAttributeMaxDynamicSharedMemorySize, ATT_SMEM);
        attrs_done = true;
    }

    // ---- batched fp16 conversions ----
    {
        int na0 = DM * D_INP, na1 = DM * DM, na2 = NL * 3 * DM * DM, na3 = NL * DM * DM;
        int ta = na0 + na1 + na2 + na3;
        cvt4<<<(ta + 255) / 256, 256>>>(
            (const float*)d_in[4], na0, (const float*)d_in[6], na1,
            (const float*)d_in[9], na2, (const float*)d_in[11], na3, p_wh + W_IN);
        int nb0 = NL * DFF * DM, nb1 = NL * DM * DFF, nb2 = DM * DM;
        int tb = nb0 + nb1 + nb2;
        cvt4<<<(tb + 255) / 256, 256>>>(
            (const float*)d_in[17], nb0, (const float*)d_in[19], nb1,
            (const float*)d_in[21], nb2, nullptr, 0, p_wh + W_FF1);
    }
    starts_kernel<<<1, 256>>>(ev, N, B);
    posenc_kernel<<<N, 128>>>(geom);
    cvt_half<<<(N * D_INP + 255) / 256, 256>>>(dom_emb, p_ffh, N * D_INP);

    int mg  = NT / 128;
    int mgN = N / 128;

    gemm5<false, false, false><<<dim3(DM / 128, mgN), 256, G5SMEM>>>(
        p_ffh,  p_wh + W_IN,  in_b,  p_att, nullptr, N, DM, D_INP);
    gemm5<false, true,  false><<<dim3(DM / 128, mgN), 256, G5SMEM>>>(
        p_bufh, p_wh + W_GEO, geo_b, p_att, nullptr, N, DM, DM);
    build_tok_ln<<<NT, 256>>>(cls, B, ln1w, ln1b);

    for (int l = 0; l < NL; l++) {
        gemm5<false, false, true><<<dim3(3 * DM / 128, mg), 256, G5SMEM>>>(
            p_bufh, p_wh + W_QKV + (size_t)l * 3 * DM * DM, qkv_b + (size_t)l * 3 * DM,
            nullptr, p_qkvh, NT, 3 * DM, DM);
        attn_h<<<dim3(B, NH, MAXQC2), 256, ATT_SMEM>>>();
        gemm6<true, true><<<dim3(1, NT / 64), 256, G6SMEM>>>(
            p_bufh, p_wh + W_OUT + (size_t)l * DM * DM, out_b + (size_t)l * DM,
            p_tok, ln2w + l * DM, ln2b + l * DM, p_bufh, NT, DM);
        gemm5<true, false, true><<<dim3(DFF / 128, mg), 256, G5SMEM>>>(
            p_bufh, p_wh + W_FF1 + (size_t)l * DFF * DM, ffb1 + (size_t)l * DFF,
            nullptr, p_ffh, NT, DFF, DM);
        if (l < NL - 1) {
            gemm6<true, true><<<dim3(1, NT / 64), 256, G6SMEM>>>(
                p_ffh, p_wh + W_FF2 + (size_t)l * DM * DFF, ffb2 + (size_t)l * DM,
                p_tok, ln1w + (l + 1) * DM, ln1b + (l + 1) * DM, p_bufh, NT, DFF);
        } else {
            gemm6<true, false><<<dim3(1, NT / 64), 256, G6SMEM>>>(
                p_ffh, p_wh + W_FF2 + (size_t)l * DM * DFF, ffb2 + (size_t)l * DM,
                p_tok, nullptr, nullptr, nullptr, NT, DFF);
        }
    }

    gather_cls<<<B, 256>>>();
    gemm5<true, false, false><<<dim3(DM / 128, 1), 256, G5SMEM>>>(
        p_bufh, p_wh + W_HEAD, hb1, p_att, nullptr, B, DM, DM);
    head2_kernel<<<1, 256>>>(p_att, hw2, hb2, out, B);
}

// round 16
// speedup vs baseline: 2.5296x; 1.0355x over previous
#include <cuda_runtime.h>
#include <cuda_fp16.h>
#include <math.h>
#include <stdint.h>

// ============================================================================
// EventTransformer — ragged formulation; fp16 mma.sync (m16n8k16, fp32 accum)
// GEMMs (BK=64) + flash attention (128-row Q tiles), ldmatrix everywhere,
// LayerNorm fused into DM-wide GEMM epilogues, fused embedding GEMM.
// ============================================================================

#define D_INP 128
#define DM    256
#define NH    4
#define HDIM  64
#define NL    4
#define DFF   1024
#define NMAXD 65536
#define BMAXD 128
#define NTMAX (NMAXD + BMAXD)

__device__ float  g_tok[(size_t)NTMAX * DM];      // residual h (fp32)
__device__ float  g_att[(size_t)NTMAX * DM];      // embed accum / head hidden (fp32)
__device__ __half g_bufh[(size_t)NTMAX * DM];     // LN out / posenc / attn out / cls
__device__ __half g_qkvh[(size_t)NTMAX * 3 * DM]; // QKV (fp16)
__device__ __half g_ffh [(size_t)NTMAX * DFF];    // FF hidden / staged dom_emb (fp16)
__device__ int    g_start[BMAXD + 1];
__device__ float  g_bias2[DM];                    // fused embed bias

// converted weights (fp16)
#define W_QKV  0
#define W_OUT  (W_QKV  + NL * 3 * DM * DM)
#define W_FF1  (W_OUT  + NL * DM * DM)
#define W_FF2  (W_FF1  + NL * DFF * DM)
#define W_HEAD (W_FF2  + NL * DM * DFF)
#define W_EMB  (W_HEAD + DM * DM)                 // fused [DM][384]
#define W_TOT  (W_EMB  + DM * 384)
__device__ __half g_wtsh[W_TOT];

// ---------------------------------------------------------------------------
__device__ __forceinline__ uint32_t smem_u32(const void* p) {
    uint32_t a;
    asm("{ .reg .u64 t; cvta.to.shared.u64 t, %1; cvt.u32.u64 %0, t; }" : "=r"(a) : "l"(p));
    return a;
}
__device__ __forceinline__ void mma_f16(float c[4], const unsigned a[4], const unsigned b[2]) {
    asm volatile(
        "mma.sync.aligned.m16n8k16.row.col.f32.f16.f16.f32 "
        "{%0,%1,%2,%3}, {%4,%5,%6,%7}, {%8,%9}, {%0,%1,%2,%3};"
        : "+f"(c[0]), "+f"(c[1]), "+f"(c[2]), "+f"(c[3])
        : "r"(a[0]), "r"(a[1]), "r"(a[2]), "r"(a[3]), "r"(b[0]), "r"(b[1]));
}
__device__ __forceinline__ void ldsm_x4(unsigned r[4], uint32_t addr) {
    asm volatile("ldmatrix.sync.aligned.m8n8.x4.shared.b16 {%0,%1,%2,%3}, [%4];"
                 : "=r"(r[0]), "=r"(r[1]), "=r"(r[2]), "=r"(r[3]) : "r"(addr));
}
__device__ __forceinline__ void ldsm_x4t(unsigned r[4], uint32_t addr) {
    asm volatile("ldmatrix.sync.aligned.m8n8.x4.trans.shared.b16 {%0,%1,%2,%3}, [%4];"
                 : "=r"(r[0]), "=r"(r[1]), "=r"(r[2]), "=r"(r[3]) : "r"(addr));
}
#define CPA16(dst, src) \
    asm volatile("cp.async.cg.shared.global [%0], [%1], 16;" \
                 :: "r"(dst), "l"(src) : "memory")
#define CPA_COMMIT() asm volatile("cp.async.commit_group;" ::: "memory")
#define CPA_WAIT1()  asm volatile("cp.async.wait_group 1;" ::: "memory")

// ---------------------------------------------------------------------------
__global__ void cvt_half(const float* __restrict__ src, __half* __restrict__ dst, int n) {
    int i = blockIdx.x * 256 + threadIdx.x;
    if (i < n) dst[i] = __float2half_rn(src[i]);
}

__global__ void cvt4(const float* p0, int n0, const float* p1, int n1,
                     const float* p2, int n2, const float* p3, int n3,
                     __half* __restrict__ dst) {
    int i = blockIdx.x * 256 + threadIdx.x;
    const float* s; int off;
    if (i < n0)                     { s = p0; off = 0; }
    else if (i < n0 + n1)           { s = p1; off = n0; }
    else if (i < n0 + n1 + n2)      { s = p2; off = n0 + n1; }
    else if (i < n0 + n1 + n2 + n3) { s = p3; off = n0 + n1 + n2; }
    else return;
    dst[i] = __float2half_rn(s[i - off]);
}

// fused embed weight [DM][384] = [in_w | geo_w], and fused bias
__global__ void repack_emb(const float* __restrict__ in_w, const float* __restrict__ geo_w,
                           const float* __restrict__ in_b, const float* __restrict__ geo_b,
                           __half* __restrict__ dst) {
    int i = blockIdx.x * 256 + threadIdx.x;
    if (i >= DM * 384) return;
    int n = i / 384, k = i % 384;
    float v = (k < 128) ? in_w[n * 128 + k] : geo_w[n * 256 + (k - 128)];
    dst[i] = __float2half_rn(v);
    if (i < DM) g_bias2[i] = in_b[i] + geo_b[i];
}

__global__ void starts_kernel(const int* __restrict__ ev, int N, int B) {
    int b = blockIdx.x * blockDim.x + threadIdx.x;
    if (b > B) return;
    if (b == B) { g_start[B] = N; return; }
    int lo = 0, hi = N;
    while (lo < hi) {
        int mid = (lo + hi) >> 1;
        if (ev[mid] < b) lo = mid + 1; else hi = mid;
    }
    g_start[b] = lo;
}

__global__ void posenc_kernel(const float* __restrict__ geom) {
    int i  = blockIdx.x;
    int c2 = threadIdx.x;
    float v0 = 0.f, v1 = 0.f;
    if (c2 < 126) {
        int dax  = c2 / 42;
        int band = c2 % 42;
        float f   = exp2f((float)band * 0.08102263646065820f); // log2(10)/41
        float ang = 6.283185307179586f * geom[i * 3 + dax] * f;
        sincosf(ang, &v0, &v1);
    }
    *(__half2*)(g_bufh + (size_t)i * DM + 2 * c2) = __floats2half2_rn(v0, v1);
}

// ---------------------------------------------------------------------------
// gemm7: BM=BN=128, BK=64, 8 warps (64x32 warp tiles), ldmatrix, 3-stage
// cp.async pipeline (wait_group(1) + barrier BEFORE compute). Fragment layout
// identical to the verified attention Q/K pattern (stride 72, ks 0..3).
// SPLIT: A is [emb(128-stride) | posenc(256-stride)] with K==384 (W pre-fused).
// M%128==0, N%128==0, K%64==0 required.
// ---------------------------------------------------------------------------
#define G7STR   72
#define G7TILE  (128 * G7STR)
#define G7STAGE (2 * G7TILE)
#define G7SMEM  (3 * G7STAGE * 2)      // 110592 B

template<bool RELU, bool RES, bool HOUT, bool SPLIT>
__global__ void __launch_bounds__(256, 2) gemm7(
        const __half* __restrict__ A, const __half* __restrict__ A2,
        const __half* __restrict__ W,
        const float* __restrict__ bias, float* __restrict__ C,
        __half* __restrict__ H, int M, int N, int K) {
    extern __shared__ __half smh[];
    const uint32_t sb = smem_u32(smh);

    const int t = threadIdx.x;
    const int lane = t & 31, gid = lane >> 2, tig = lane & 3;
    const int wid = t >> 5;
    const int wm = (wid & 1) * 64;
    const int wn = (wid >> 1) * 32;
    const int m0 = blockIdx.y * 128, n0 = blockIdx.x * 128;
    const int nc = K >> 6;

    const int ra = ((lane & 8) ? 8 : 0) + (lane & 7);
    const int ca = (lane & 16) ? 8 : 0;
    const int rb = ((lane & 16) ? 8 : 0) + (lane & 7);
    const int cb = (lane & 8) ? 8 : 0;

    auto load_chunk = [&](int c, int s) {
        int k0 = c * 64;
        uint32_t abase = sb + (s * G7STAGE) * 2;
        uint32_t wbase = abase + G7TILE * 2;
#pragma unroll
        for (int i = 0; i < 4; i++) {
            int u = i * 256 + t;            // 0..1023
            int r = u >> 3, q = u & 7;      // r 0..127, q 0..7 (16B chunk)
            int k = k0 + q * 8;
            const __half* asrc;
            if (SPLIT) {
                asrc = (k < 128)
                    ? A  + (size_t)(m0 + r) * 128 + k
                    : A2 + (size_t)(m0 + r) * 256 + (k - 128);
            } else {
                asrc = A + (size_t)(m0 + r) * K + k;
            }
            CPA16(abase + (r * G7STR + q * 8) * 2, asrc);
            CPA16(wbase + (r * G7STR + q * 8) * 2, W + (size_t)(n0 + r) * K + k);
        }
    };

    load_chunk(0, 0); CPA_COMMIT();
    load_chunk(1, 1); CPA_COMMIT();   // nc >= 2 always (K >= 128)

    float acc[4][4][4];
#pragma unroll
    for (int mi = 0; mi < 4; mi++)
#pragma unroll
        for (int ni = 0; ni < 4; ni++)
#pragma unroll
            for (int j = 0; j < 4; j++) acc[mi][ni][j] = 0.f;

    for (int c = 0; c < nc; c++) {
        CPA_WAIT1();                     // chunk c complete (this thread)
        __syncthreads();                 // ...and visible CTA-wide

        uint32_t sA = sb + (c % 3) * (G7STAGE * 2);
        uint32_t sW = sA + G7TILE * 2;
#pragma unroll
        for (int ks = 0; ks < 4; ks++) {
            unsigned a[4][4], b[4][2];
#pragma unroll
            for (int mi = 0; mi < 4; mi++)
                ldsm_x4(a[mi], sA + ((wm + mi * 16 + ra) * G7STR + ks * 16 + ca) * 2);
            {
                unsigned bt[4];
                ldsm_x4(bt, sW + ((wn + rb) * G7STR + ks * 16 + cb) * 2);
                b[0][0] = bt[0]; b[0][1] = bt[1]; b[1][0] = bt[2]; b[1][1] = bt[3];
                ldsm_x4(bt, sW + ((wn + 16 + rb) * G7STR + ks * 16 + cb) * 2);
                b[2][0] = bt[0]; b[2][1] = bt[1]; b[3][0] = bt[2]; b[3][1] = bt[3];
            }
#pragma unroll
            for (int mi = 0; mi < 4; mi++)
#pragma unroll
                for (int ni = 0; ni < 4; ni++)
                    mma_f16(acc[mi][ni], a[mi], b[ni]);
        }

        if (c + 2 < nc) load_chunk(c + 2, (c + 2) % 3);
        CPA_COMMIT();                    // unconditional: keeps wait_group(1) valid
    }

#pragma unroll
    for (int mi = 0; mi < 4; mi++) {
#pragma unroll
        for (int ni = 0; ni < 4; ni++) {
            int r  = m0 + wm + mi * 16 + gid;
            int cn = n0 + wn + ni * 8 + 2 * tig;
            float b0 = bias[cn], b1 = bias[cn + 1];
#pragma unroll
            for (int hf = 0; hf < 2; hf++) {
                int rr = r + hf * 8;
                float v0 = acc[mi][ni][hf * 2 + 0] + b0;
                float v1 = acc[mi][ni][hf * 2 + 1] + b1;
                if (RES) {
                    const float* cp = C + (size_t)rr * N + cn;
                    v0 += cp[0]; v1 += cp[1];
                }
                if (RELU) { v0 = fmaxf(v0, 0.f); v1 = fmaxf(v1, 0.f); }
                if (HOUT) {
                    *(__half2*)(H + (size_t)rr * N + cn) = __floats2half2_rn(v0, v1);
                } else {
                    float* cp = C + (size_t)rr * N + cn;
                    cp[0] = v0; cp[1] = v1;
                }
            }
        }
    }
}

// ---------------------------------------------------------------------------
// gemm6 (proven R14): BM=64, BN=256, BK=32, LN fused epilogue. grid.x==1.
// ---------------------------------------------------------------------------
#define G6STR   40
#define G6ROWS  320
#define G6STAGE (G6ROWS * G6STR)
#define G6SMEM  (3 * G6STAGE * 2)

template<bool RES, bool LNF>
__global__ void __launch_bounds__(256, 2) gemm6(
        const __half* __restrict__ A, const __half* __restrict__ W,
        const float* __restrict__ bias, float* __restrict__ C,
        const float* __restrict__ lnw, const float* __restrict__ lnb,
        __half* __restrict__ Y, int M, int K) {
    extern __shared__ __half smh[];
    const uint32_t sb = smem_u32(smh);
    const int N = 256;

    const int t = threadIdx.x;
    const int lane = t & 31, gid = lane >> 2, tig = lane & 3;
    const int wid = t >> 5;
    const int wm = (wid & 1) * 32;
    const int wn = (wid >> 1) * 64;
    const int wcol = wid >> 1;
    const int m0 = blockIdx.y * 64;
    const int nc = K >> 5;

    const int ra = ((lane & 8) ? 8 : 0) + (lane & 7);
    const int ca = (lane & 16) ? 8 : 0;
    const int rb = ((lane & 16) ? 8 : 0) + (lane & 7);
    const int cb = (lane & 8) ? 8 : 0;

    auto load_chunk = [&](int c, int s) {
        int k0 = c * 32;
        uint32_t base = sb + (s * G6STAGE) * 2;
#pragma unroll
        for (int i = 0; i < 5; i++) {
            int u = i * 256 + t;
            int r = u >> 2, q = u & 3;
            const __half* src = (r < 64)
                ? A + (size_t)(m0 + r) * K + k0 + q * 8
                : W + (size_t)(r - 64) * K + k0 + q * 8;
            CPA16(base + (r * G6STR + q * 8) * 2, src);
        }
    };

    load_chunk(0, 0); CPA_COMMIT();
    load_chunk(1, 1); CPA_COMMIT();

    float acc[2][8][4];
#pragma unroll
    for (int mi = 0; mi < 2; mi++)
#pragma unroll
        for (int ni = 0; ni < 8; ni++)
#pragma unroll
            for (int j = 0; j < 4; j++) acc[mi][ni][j] = 0.f;

    for (int c = 0; c < nc; c++) {
        CPA_WAIT1();
        __syncthreads();

        uint32_t sA = sb + (c % 3) * (G6STAGE * 2);
        uint32_t sW = sA + 64 * G6STR * 2;
#pragma unroll
        for (int ks = 0; ks < 2; ks++) {
            unsigned a[2][4], b[8][2];
#pragma unroll
            for (int mi = 0; mi < 2; mi++)
                ldsm_x4(a[mi], sA + ((wm + mi * 16 + ra) * G6STR + ks * 16 + ca) * 2);
#pragma unroll
            for (int nb = 0; nb < 4; nb++) {
                unsigned bt[4];
                ldsm_x4(bt, sW + ((wn + nb * 16 + rb) * G6STR + ks * 16 + cb) * 2);
                b[2 * nb][0]     = bt[0]; b[2 * nb][1]     = bt[1];
                b[2 * nb + 1][0] = bt[2]; b[2 * nb + 1][1] = bt[3];
            }
#pragma unroll
            for (int mi = 0; mi < 2; mi++)
#pragma unroll
                for (int ni = 0; ni < 8; ni++)
                    mma_f16(acc[mi][ni], a[mi], b[ni]);
        }

        if (c + 2 < nc) load_chunk(c + 2, (c + 2) % 3);
        CPA_COMMIT();
    }

    __syncthreads();
    float* red = (float*)smh;

    float s_[2][2], q_[2][2];
#pragma unroll
    for (int mi = 0; mi < 2; mi++) { s_[mi][0] = s_[mi][1] = q_[mi][0] = q_[mi][1] = 0.f; }

#pragma unroll
    for (int mi = 0; mi < 2; mi++) {
#pragma unroll
        for (int ni = 0; ni < 8; ni++) {
            int cn = wn + ni * 8 + 2 * tig;
            float b0 = bias[cn], b1 = bias[cn + 1];
#pragma unroll
            for (int hf = 0; hf < 2; hf++) {
                int rr = m0 + wm + mi * 16 + gid + hf * 8;
                float v0 = acc[mi][ni][hf * 2 + 0] + b0;
                float v1 = acc[mi][ni][hf * 2 + 1] + b1;
                if (RES) {
                    const float* cp = C + (size_t)rr * N + cn;
                    v0 += cp[0]; v1 += cp[1];
                }
                float* cp = C + (size_t)rr * N + cn;
                cp[0] = v0; cp[1] = v1;
                acc[mi][ni][hf * 2 + 0] = v0;
                acc[mi][ni][hf * 2 + 1] = v1;
                if (LNF) {
                    s_[mi][hf] += v0 + v1;
                    q_[mi][hf] += v0 * v0 + v1 * v1;
                }
            }
        }
    }

    if (LNF) {
#pragma unroll
        for (int mi = 0; mi < 2; mi++)
#pragma unroll
            for (int hf = 0; hf < 2; hf++) {
                s_[mi][hf] += __shfl_xor_sync(0xffffffffu, s_[mi][hf], 1);
                s_[mi][hf] += __shfl_xor_sync(0xffffffffu, s_[mi][hf], 2);
                q_[mi][hf] += __shfl_xor_sync(0xffffffffu, q_[mi][hf], 1);
                q_[mi][hf] += __shfl_xor_sync(0xffffffffu, q_[mi][hf], 2);
            }
        if (tig == 0) {
#pragma unroll
            for (int mi = 0; mi < 2; mi++)
#pragma unroll
                for (int hf = 0; hf < 2; hf++) {
                    int rl = wm + mi * 16 + gid + hf * 8;
                    red[rl * 8 + wcol * 2 + 0] = s_[mi][hf];
                    red[rl * 8 + wcol * 2 + 1] = q_[mi][hf];
                }
        }
        __syncthreads();
#pragma unroll
        for (int mi = 0; mi < 2; mi++) {
#pragma unroll
            for (int hf = 0; hf < 2; hf++) {
                int rl = wm + mi * 16 + gid + hf * 8;
                float su = 0.f, sq = 0.f;
#pragma unroll
                for (int w = 0; w < 4; w++) {
                    su += red[rl * 8 + w * 2];
                    sq += red[rl * 8 + w * 2 + 1];
                }
                float mean = su * (1.f / 256.f);
                float var  = sq * (1.f / 256.f) - mean * mean;
                float rstd = rsqrtf(var + 1e-5f);
                __half* yp = Y + (size_t)(m0 + rl) * N;
#pragma unroll
                for (int ni = 0; ni < 8; ni++) {
                    int cn = wn + ni * 8 + 2 * tig;
                    float v0 = acc[mi][ni][hf * 2 + 0];
                    float v1 = acc[mi][ni][hf * 2 + 1];
                    *(__half2*)(yp + cn) = __floats2half2_rn(
                        (v0 - mean) * rstd * lnw[cn] + lnb[cn],
                        (v1 - mean) * rstd * lnw[cn + 1] + lnb[cn + 1]);
                }
            }
        }
    }
}

// ---------------------------------------------------------------------------
__global__ void build_tok_ln(const float* __restrict__ cls, int B,
                             const float* __restrict__ w, const float* __restrict__ bb) {
    int tk = blockIdx.x;
    __shared__ int sbv;
    if (threadIdx.x == 0) {
        int lo = 0, hi = B - 1;
        while (lo < hi) {
            int mid = (lo + hi + 1) >> 1;
            if (g_start[mid] + mid <= tk) lo = mid; else hi = mid - 1;
        }
        sbv = lo;
    }
    __syncthreads();
    int b = sbv;
    int i = threadIdx.x;
    float v;
    if (tk == g_start[b] + b) v = cls[i];
    else                      v = g_att[(size_t)(tk - b - 1) * DM + i];
    g_tok[(size_t)tk * DM + i] = v;

    __shared__ float red[8];
    float s = v;
#pragma unroll
    for (int o = 16; o; o >>= 1) s += __shfl_xor_sync(0xffffffffu, s, o);
    if ((i & 31) == 0) red[i >> 5] = s;
    __syncthreads();
    float tot = 0.f;
#pragma unroll
    for (int k = 0; k < 8; k++) tot += red[k];
    float mean = tot * (1.f / DM);
    float d = v - mean;
    float s2 = d * d;
#pragma unroll
    for (int o = 16; o; o >>= 1) s2 += __shfl_xor_sync(0xffffffffu, s2, o);
    __syncthreads();
    if ((i & 31) == 0) red[i >> 5] = s2;
    __syncthreads();
    float tv = 0.f;
#pragma unroll
    for (int k = 0; k < 8; k++) tv += red[k];
    float var = tv * (1.f / DM);
    g_bufh[(size_t)tk * DM + i] = __float2half_rn(d * rsqrtf(var + 1e-5f) * w[i] + bb[i]);
}

// ---------------------------------------------------------------------------
// Ragged flash attention (proven R15): 128-row Q tiles, 256 threads.
// ---------------------------------------------------------------------------
#define MAXQC2 6
#define ASTR  72
#define AQ_REG (128 * ASTR)
#define AK_REG (64 * ASTR)
#define ATT_SMEM ((AQ_REG + 2 * AK_REG + AQ_REG) * 2)

__global__ void __launch_bounds__(256) attn_h() {
    extern __shared__ __half ash[];
    __half* Qs = ash;
    __half* Ks = Qs + AQ_REG;
    __half* Vs = Ks + AK_REG;
    __half* Ps = Vs + AK_REG;
    const uint32_t sbQ = smem_u32(ash);
    const uint32_t sbK = sbQ + AQ_REG * 2;
    const uint32_t sbV = sbK + AK_REG * 2;
    const uint32_t sbP = sbV + AK_REG * 2;

    int b  = blockIdx.x, h = blockIdx.y;
    int s0 = g_start[b];
    int L  = g_start[b + 1] - s0 + 1;
    int qc = blockIdx.z * 128;
    if (qc >= L) return;
    int t0 = s0 + b;

    int t = threadIdx.x, lane = t & 31, wid = t >> 5;
    int gid = lane >> 2, tig = lane & 3;
    int wm = wid * 16;

    const int ra = ((lane & 8) ? 8 : 0) + (lane & 7);
    const int ca = (lane & 16) ? 8 : 0;
    const int rb = ((lane & 16) ? 8 : 0) + (lane & 7);
    const int cb = (lane & 8) ? 8 : 0;

    {
        int lr = t >> 1, lc = (t & 1) * 32;
        bool v = (qc + lr) < L;
        const __half* qp = g_qkvh + (size_t)(t0 + qc + lr) * 768 + h * HDIM + lc;
        __half* d = Qs + lr * ASTR + lc;
        uint4 z = make_uint4(0, 0, 0, 0);
#pragma unroll
        for (int u = 0; u < 4; u++)
            *(uint4*)(d + u * 8) = v ? *(const uint4*)(qp + u * 8) : z;
    }

    float mr0 = -1e30f, mr1 = -1e30f, l0 = 0.f, l1 = 0.f;
    float O[8][4];
#pragma unroll
    for (int ni = 0; ni < 8; ni++)
#pragma unroll
        for (int j = 0; j < 4; j++) O[ni][j] = 0.f;

    const float scale = 0.125f;

    for (int kc = 0; kc < L; kc += 64) {
        __syncthreads();
        {
            int lr = t >> 2, lc = (t & 3) * 16;
            bool v = (kc + lr) < L;
            const __half* kp = g_qkvh + (size_t)(t0 + kc + lr) * 768 + 256 + h * HDIM + lc;
            const __half* vp = kp + 256;
            __half* kd = Ks + lr * ASTR + lc;
            __half* vd = Vs + lr * ASTR + lc;
            uint4 z = make_uint4(0, 0, 0, 0);
#pragma unroll
            for (int u = 0; u < 2; u++) {
                *(uint4*)(kd + u * 8) = v ? *(const uint4*)(kp + u * 8) : z;
                *(uint4*)(vd + u * 8) = v ? *(const uint4*)(vp + u * 8) : z;
            }
        }
        __syncthreads();

        float S[8][4];
#pragma unroll
        for (int ni = 0; ni < 8; ni++)
#pragma unroll
            for (int j = 0; j < 4; j++) S[ni][j] = 0.f;
#pragma unroll
        for (int ks = 0; ks < 4; ks++) {
            unsigned a[4];
            ldsm_x4(a, sbQ + ((wm + ra) * ASTR + ks * 16 + ca) * 2);
#pragma unroll
            for (int nb = 0; nb < 8; nb += 2) {
                unsigned bt[4];
                ldsm_x4(bt, sbK + ((nb * 8 + rb) * ASTR + ks * 16 + cb) * 2);
                mma_f16(S[nb],     a, bt);
                mma_f16(S[nb + 1], a, bt + 2);
            }
        }

        float rm0 = -1e30f, rm1 = -1e30f;
#pragma unroll
        for (int ni = 0; ni < 8; ni++) {
            int j0 = kc + ni * 8 + 2 * tig;
            bool v0 = j0 < L, v1 = (j0 + 1) < L;
            S[ni][0] = v0 ? S[ni][0] * scale : -1e30f;
            S[ni][1] = v1 ? S[ni][1] * scale : -1e30f;
            S[ni][2] = v0 ? S[ni][2] * scale : -1e30f;
            S[ni][3] = v1 ? S[ni][3] * scale : -1e30f;
            rm0 = fmaxf(rm0, fmaxf(S[ni][0], S[ni][1]));
            rm1 = fmaxf(rm1, fmaxf(S[ni][2], S[ni][3]));
        }
        rm0 = fmaxf(rm0, __shfl_xor_sync(0xffffffffu, rm0, 1));
        rm0 = fmaxf(rm0, __shfl_xor_sync(0xffffffffu, rm0, 2));
        rm1 = fmaxf(rm1, __shfl_xor_sync(0xffffffffu, rm1, 1));
        rm1 = fmaxf(rm1, __shfl_xor_sync(0xffffffffu, rm1, 2));
        float mn0 = fmaxf(mr0, rm0), mn1 = fmaxf(mr1, rm1);
        float cr0 = __expf(mr0 - mn0), cr1 = __expf(mr1 - mn1);
        float sum0 = 0.f, sum1 = 0.f;
        __half* pr0 = Ps + (wm + gid) * ASTR;
        __half* pr1 = Ps + (wm + gid + 8) * ASTR;
#pragma unroll
        for (int ni = 0; ni < 8; ni++) {
            int col = ni * 8 + 2 * tig;
            float p0 = __expf(S[ni][0] - mn0);
            float p1 = __expf(S[ni][1] - mn0);
            float p2 = __expf(S[ni][2] - mn1);
            float p3 = __expf(S[ni][3] - mn1);
            sum0 += p0 + p1; sum1 += p2 + p3;
            *(__half2*)(pr0 + col) = __floats2half2_rn(p0, p1);
            *(__half2*)(pr1 + col) = __floats2half2_rn(p2, p3);
        }
        sum0 += __shfl_xor_sync(0xffffffffu, sum0, 1);
        sum0 += __shfl_xor_sync(0xffffffffu, sum0, 2);
        sum1 += __shfl_xor_sync(0xffffffffu, sum1, 1);
        sum1 += __shfl_xor_sync(0xffffffffu, sum1, 2);
        l0 = l0 * cr0 + sum0;
        l1 = l1 * cr1 + sum1;
        mr0 = mn0; mr1 = mn1;
#pragma unroll
        for (int ni = 0; ni < 8; ni++) {
            O[ni][0] *= cr0; O[ni][1] *= cr0;
            O[ni][2] *= cr1; O[ni][3] *= cr1;
        }
        __syncwarp();

#pragma unroll
        for (int ks = 0; ks < 4; ks++) {
            unsigned a[4];
            ldsm_x4(a, sbP + ((wm + ra) * ASTR + ks * 16 + ca) * 2);
#pragma unroll
            for (int nb = 0; nb < 8; nb += 2) {
                unsigned bt[4];
                ldsm_x4t(bt, sbV + ((ks * 16 + ra) * ASTR + nb * 8 + ca) * 2);
                mma_f16(O[nb],     a, bt);
                mma_f16(O[nb + 1], a, bt + 2);
            }
        }
        __syncwarp();
    }

    float inv0 = 1.f / l0, inv1 = 1.f / l1;
    int q0 = qc + wm + gid, q1 = q0 + 8;
#pragma unroll
    for (int ni = 0; ni < 8; ni++) {
        int col = h * HDIM + ni * 8 + 2 * tig;
        if (q0 < L)
            *(__half2*)(g_bufh + (size_t)(t0 + q0) * DM + col) =
                __floats2half2_rn(O[ni][0] * inv0, O[ni][1] * inv0);
        if (q1 < L)
            *(__half2*)(g_bufh + (size_t)(t0 + q1) * DM + col) =
                __floats2half2_rn(O[ni][2] * inv1, O[ni][3] * inv1);
    }
}

// ---------------------------------------------------------------------------
__global__ void gather_cls() {
    int b = blockIdx.x, d = threadIdx.x;
    g_bufh[(size_t)b * DM + d] = __float2half_rn(g_tok[(size_t)(g_start[b] + b) * DM + d]);
}

__global__ void head2_kernel(const float* __restrict__ hid, const float* __restrict__ w2,
                             const float* __restrict__ b2, float* __restrict__ out, int B) {
    int t = blockIdx.x * blockDim.x + threadIdx.x;
    if (t >= B * 2) return;
    int b = t >> 1, j = t & 1;
    const float* hr = hid + (size_t)b * DM;
    const float* wr = w2 + (size_t)j * DM;
    float s = 0.f;
#pragma unroll 8
    for (int k = 0; k < DM; k++) s += hr[k] * wr[k];
    out[t] = s + b2[j];
}

// ---------------------------------------------------------------------------
extern "C" void kernel_launch(void* const* d_in, const int* in_sizes, int n_in,
                              void* d_out, int out_size) {
    const float* dom_emb = (const float*)d_in[0];
    const int*   ev      = (const int*)  d_in[1];
    const float* geom    = (const float*)d_in[3];
    const float* in_b    = (const float*)d_in[5];
    const float* geo_b   = (const float*)d_in[7];
    const float* cls     = (const float*)d_in[8];
    const float* qkv_b   = (const float*)d_in[10];
    const float* out_b   = (const float*)d_in[12];
    const float* ln1w    = (const float*)d_in[13];
    const float* ln1b    = (const float*)d_in[14];
    const float* ln2w    = (const float*)d_in[15];
    const float* ln2b    = (const float*)d_in[16];
    const float* ffb1    = (const float*)d_in[18];
    const float* ffb2    = (const float*)d_in[20];
    const float* hb1     = (const float*)d_in[22];
    const float* hw2     = (const float*)d_in[23];
    const float* hb2     = (const float*)d_in[24];
    float* out = (float*)d_out;

    int N  = in_sizes[0] / D_INP;
    int B  = out_size / 2;
    int NT = N + B;

    float  *p_tok, *p_att, *p_b2;
    __half *p_bufh, *p_qkvh, *p_ffh, *p_wh;
    cudaGetSymbolAddress((void**)&p_tok,  g_tok);
    cudaGetSymbolAddress((void**)&p_att,  g_att);
    cudaGetSymbolAddress((void**)&p_bufh, g_bufh);
    cudaGetSymbolAddress((void**)&p_qkvh, g_qkvh);
    cudaGetSymbolAddress((void**)&p_ffh,  g_ffh);
    cudaGetSymbolAddress((void**)&p_wh,   g_wtsh);
    cudaGetSymbolAddress((void**)&p_b2,   g_bias2);

    static bool attrs_done = false;
    if (!attrs_done) {
        cudaFuncSetAttribute(gemm7<false, false, true,  false>, cudaFuncAttributeMaxDynamicSharedMemorySize, G7SMEM);
        cudaFuncSetAttribute(gemm7<true,  false, true,  false>, cudaFuncAttributeMaxDynamicSharedMemorySize, G7SMEM);
        cudaFuncSetAttribute(gemm7<false, false, false, true >, cudaFuncAttributeMaxDynamicSharedMemorySize, G7SMEM);
        cudaFuncSetAttribute(gemm7<true,  false, false, false>, cudaFuncAttributeMaxDynamicSharedMemorySize, G7SMEM);
        cudaFuncSetAttribute(gemm6<true,  true >, cudaFuncAttributeMaxDynamicSharedMemorySize, G6SMEM);
        cudaFuncSetAttribute(gemm6<true,  false>, cudaFuncAttributeMaxDynamicSharedMemorySize, G6SMEM);
        cudaFuncSetAttribute(attn_h, cudaFuncAttributeMaxDynamicSharedMemorySize, ATT_SMEM);
        attrs_done = true;
    }

    // ---- fp16 weight conversions ----
    {
        int na0 = NL * 3 * DM * DM, na1 = NL * DM * DM, na2 = NL * DFF * DM, na3 = NL * DM * DFF;
        int ta = na0 + na1 + na2 + na3;
        cvt4<<<(ta + 255) / 256, 256>>>(
            (const float*)d_in[9],  na0, (const float*)d_in[11], na1,
            (const float*)d_in[17], na2, (const float*)d_in[19], na3, p_wh + W_QKV);
        cvt_half<<<(DM * DM + 255) / 256, 256>>>((const float*)d_in[21], p_wh + W_HEAD, DM * DM);
        repack_emb<<<(DM * 384 + 255) / 256, 256>>>(
            (const float*)d_in[4], (const float*)d_in[6], in_b, geo_b, p_wh + W_EMB);
    }
    starts_kernel<<<1, 256>>>(ev, N, B);
    posenc_kernel<<<N, 128>>>(geom);
    cvt_half<<<(N * D_INP + 255) / 256, 256>>>(dom_emb, p_ffh, N * D_INP);

    int mg  = NT / 128;
    int mgN = N / 128;

    // fused embedding: [emb|posenc] @ [in_w|geo_w]^T + (in_b+geo_b) -> g_att
    gemm7<false, false, false, true><<<dim3(DM / 128, mgN), 256, G7SMEM>>>(
        p_ffh, p_bufh, p_wh + W_EMB, p_b2, p_att, nullptr, N, DM, 384);
    build_tok_ln<<<NT, 256>>>(cls, B, ln1w, ln1b);

    for (int l = 0; l < NL; l++) {
        gemm7<false, false, true, false><<<dim3(3 * DM / 128, mg), 256, G7SMEM>>>(
            p_bufh, nullptr, p_wh + W_QKV + (size_t)l * 3 * DM * DM,
            qkv_b + (size_t)l * 3 * DM, nullptr, p_qkvh, NT, 3 * DM, DM);
        attn_h<<<dim3(B, NH, MAXQC2), 256, ATT_SMEM>>>();
        gemm6<true, true><<<dim3(1, NT / 64), 256, G6SMEM>>>(
            p_bufh, p_wh + W_OUT + (size_t)l * DM * DM, out_b + (size_t)l * DM,
            p_tok, ln2w + l * DM, ln2b + l * DM, p_bufh, NT, DM);
        gemm7<true, false, true, false><<<dim3(DFF / 128, mg), 256, G7SMEM>>>(
            p_bufh, nullptr, p_wh + W_FF1 + (size_t)l * DFF * DM,
            ffb1 + (size_t)l * DFF, nullptr, p_ffh, NT, DFF, DM);
        if (l < NL - 1) {
            gemm6<true, true><<<dim3(1, NT / 64), 256, G6SMEM>>>(
                p_ffh, p_wh + W_FF2 + (size_t)l * DM * DFF, ffb2 + (size_t)l * DM,
                p_tok, ln1w + (l + 1) * DM, ln1b + (l + 1) * DM, p_bufh, NT, DFF);
        } else {
            gemm6<true, false><<<dim3(1, NT / 64), 256, G6SMEM>>>(
                p_ffh, p_wh + W_FF2 + (size_t)l * DM * DFF, ffb2 + (size_t)l * DM,
                p_tok, nullptr, nullptr, nullptr, NT, DFF);
        }
    }

    gather_cls<<<B, 256>>>();
    gemm7<true, false, false, false><<<dim3(DM / 128, 1), 256, G7SMEM>>>(
        p_bufh, nullptr, p_wh + W_HEAD, hb1, p_att, nullptr, B, DM, DM);
    head2_kernel<<<1, 256>>>(p_att, hw2, hb2, out, B);
}

// round 17
// speedup vs baseline: 2.5512x; 1.0085x over previous
#include <cuda_runtime.h>
#include <cuda_fp16.h>
#include <math.h>
#include <stdint.h>

// ============================================================================
// EventTransformer — ragged formulation; fp16 mma.sync (m16n8k16, fp32 accum)
// GEMMs (BK=64) + flash attention (128-row Q tiles), ldmatrix everywhere,
// LayerNorm fused into DM-wide GEMM epilogues, fused embedding GEMM.
// ============================================================================

#define D_INP 128
#define DM    256
#define NH    4
#define HDIM  64
#define NL    4
#define DFF   1024
#define NMAXD 65536
#define BMAXD 128
#define NTMAX (NMAXD + BMAXD)

__device__ float  g_tok[(size_t)NTMAX * DM];      // residual h (fp32)
__device__ float  g_att[(size_t)NTMAX * DM];      // embed accum / head hidden (fp32)
__device__ __half g_bufh[(size_t)NTMAX * DM];     // LN out / posenc / attn out / cls
__device__ __half g_qkvh[(size_t)NTMAX * 3 * DM]; // QKV (fp16)
__device__ __half g_ffh [(size_t)NTMAX * DFF];    // FF hidden / staged dom_emb (fp16)
__device__ int    g_start[BMAXD + 1];
__device__ float  g_bias2[DM];                    // fused embed bias

// converted weights (fp16)
#define W_QKV  0
#define W_OUT  (W_QKV  + NL * 3 * DM * DM)
#define W_FF1  (W_OUT  + NL * DM * DM)
#define W_FF2  (W_FF1  + NL * DFF * DM)
#define W_HEAD (W_FF2  + NL * DM * DFF)
#define W_EMB  (W_HEAD + DM * DM)                 // fused [DM][384]
#define W_TOT  (W_EMB  + DM * 384)
__device__ __half g_wtsh[W_TOT];

// ---------------------------------------------------------------------------
__device__ __forceinline__ uint32_t smem_u32(const void* p) {
    uint32_t a;
    asm("{ .reg .u64 t; cvta.to.shared.u64 t, %1; cvt.u32.u64 %0, t; }" : "=r"(a) : "l"(p));
    return a;
}
__device__ __forceinline__ void mma_f16(float c[4], const unsigned a[4], const unsigned b[2]) {
    asm volatile(
        "mma.sync.aligned.m16n8k16.row.col.f32.f16.f16.f32 "
        "{%0,%1,%2,%3}, {%4,%5,%6,%7}, {%8,%9}, {%0,%1,%2,%3};"
        : "+f"(c[0]), "+f"(c[1]), "+f"(c[2]), "+f"(c[3])
        : "r"(a[0]), "r"(a[1]), "r"(a[2]), "r"(a[3]), "r"(b[0]), "r"(b[1]));
}
__device__ __forceinline__ void ldsm_x4(unsigned r[4], uint32_t addr) {
    asm volatile("ldmatrix.sync.aligned.m8n8.x4.shared.b16 {%0,%1,%2,%3}, [%4];"
                 : "=r"(r[0]), "=r"(r[1]), "=r"(r[2]), "=r"(r[3]) : "r"(addr));
}
__device__ __forceinline__ void ldsm_x4t(unsigned r[4], uint32_t addr) {
    asm volatile("ldmatrix.sync.aligned.m8n8.x4.trans.shared.b16 {%0,%1,%2,%3}, [%4];"
                 : "=r"(r[0]), "=r"(r[1]), "=r"(r[2]), "=r"(r[3]) : "r"(addr));
}
#define CPA16(dst, src) \
    asm volatile("cp.async.cg.shared.global [%0], [%1], 16;" \
                 :: "r"(dst), "l"(src) : "memory")
#define CPA_COMMIT() asm volatile("cp.async.commit_group;" ::: "memory")
#define CPA_WAIT1()  asm volatile("cp.async.wait_group 1;" ::: "memory")

// ---------------------------------------------------------------------------
__global__ void cvt_half(const float* __restrict__ src, __half* __restrict__ dst, int n) {
    int i = blockIdx.x * 256 + threadIdx.x;
    if (i < n) dst[i] = __float2half_rn(src[i]);
}

__global__ void cvt4(const float* p0, int n0, const float* p1, int n1,
                     const float* p2, int n2, const float* p3, int n3,
                     __half* __restrict__ dst) {
    int i = blockIdx.x * 256 + threadIdx.x;
    const float* s; int off;
    if (i < n0)                     { s = p0; off = 0; }
    else if (i < n0 + n1)           { s = p1; off = n0; }
    else if (i < n0 + n1 + n2)      { s = p2; off = n0 + n1; }
    else if (i < n0 + n1 + n2 + n3) { s = p3; off = n0 + n1 + n2; }
    else return;
    dst[i] = __float2half_rn(s[i - off]);
}

// fused embed weight [DM][384] = [in_w | geo_w], and fused bias
__global__ void repack_emb(const float* __restrict__ in_w, const float* __restrict__ geo_w,
                           const float* __restrict__ in_b, const float* __restrict__ geo_b,
                           __half* __restrict__ dst) {
    int i = blockIdx.x * 256 + threadIdx.x;
    if (i >= DM * 384) return;
    int n = i / 384, k = i % 384;
    float v = (k < 128) ? in_w[n * 128 + k] : geo_w[n * 256 + (k - 128)];
    dst[i] = __float2half_rn(v);
    if (i < DM) g_bias2[i] = in_b[i] + geo_b[i];
}

// parallel starts: boundary detection on sorted ev (replaces serial search)
__global__ void starts_kernel(const int* __restrict__ ev, int N, int B) {
    int i = blockIdx.x * 256 + threadIdx.x;
    if (i >= N) return;
    int e    = ev[i];
    int prev = (i == 0) ? -1 : ev[i - 1];
    for (int b = prev + 1; b <= e; b++) g_start[b] = i;   // handles empty events
    if (i == N - 1)
        for (int b = e + 1; b <= B; b++) g_start[b] = N;
}

// posenc + dom_emb fp16 staging fused (both indexed by row i)
__global__ void posenc_kernel(const float* __restrict__ geom,
                              const float* __restrict__ emb) {
    int i  = blockIdx.x;
    int c  = threadIdx.x;           // 0..127
    float v0 = 0.f, v1 = 0.f;
    if (c < 126) {
        int dax  = c / 42;
        int band = c % 42;
        float f   = exp2f((float)band * 0.08102263646065820f); // log2(10)/41
        float ang = 6.283185307179586f * geom[i * 3 + dax] * f;
        sincosf(ang, &v0, &v1);
    }
    *(__half2*)(g_bufh + (size_t)i * DM + 2 * c) = __floats2half2_rn(v0, v1);
    g_ffh[(size_t)i * D_INP + c] = __float2half_rn(emb[(size_t)i * D_INP + c]);
}

// ---------------------------------------------------------------------------
// gemm7: BM=BN=128, BK=64, 8 warps (64x32 warp tiles), ldmatrix, 3-stage
// cp.async pipeline. SPLIT: A = [emb(128-stride) | posenc(256-stride)], K=384.
// ---------------------------------------------------------------------------
#define G7STR   72
#define G7TILE  (128 * G7STR)
#define G7STAGE (2 * G7TILE)
#define G7SMEM  (3 * G7STAGE * 2)      // 110592 B

template<bool RELU, bool RES, bool HOUT, bool SPLIT>
__global__ void __launch_bounds__(256, 2) gemm7(
        const __half* __restrict__ A, const __half* __restrict__ A2,
        const __half* __restrict__ W,
        const float* __restrict__ bias, float* __restrict__ C,
        __half* __restrict__ H, int M, int N, int K) {
    extern __shared__ __half smh[];
    const uint32_t sb = smem_u32(smh);

    const int t = threadIdx.x;
    const int lane = t & 31, gid = lane >> 2, tig = lane & 3;
    const int wid = t >> 5;
    const int wm = (wid & 1) * 64;
    const int wn = (wid >> 1) * 32;
    const int m0 = blockIdx.y * 128, n0 = blockIdx.x * 128;
    const int nc = K >> 6;

    const int ra = ((lane & 8) ? 8 : 0) + (lane & 7);
    const int ca = (lane & 16) ? 8 : 0;
    const int rb = ((lane & 16) ? 8 : 0) + (lane & 7);
    const int cb = (lane & 8) ? 8 : 0;

    auto load_chunk = [&](int c, int s) {
        int k0 = c * 64;
        uint32_t abase = sb + (s * G7STAGE) * 2;
        uint32_t wbase = abase + G7TILE * 2;
#pragma unroll
        for (int i = 0; i < 4; i++) {
            int u = i * 256 + t;            // 0..1023
            int r = u >> 3, q = u & 7;      // r 0..127, q 0..7 (16B chunk)
            int k = k0 + q * 8;
            const __half* asrc;
            if (SPLIT) {
                asrc = (k < 128)
                    ? A  + (size_t)(m0 + r) * 128 + k
                    : A2 + (size_t)(m0 + r) * 256 + (k - 128);
            } else {
                asrc = A + (size_t)(m0 + r) * K + k;
            }
            CPA16(abase + (r * G7STR + q * 8) * 2, asrc);
            CPA16(wbase + (r * G7STR + q * 8) * 2, W + (size_t)(n0 + r) * K + k);
        }
    };

    load_chunk(0, 0); CPA_COMMIT();
    load_chunk(1, 1); CPA_COMMIT();   // nc >= 2 always (K >= 128)

    float acc[4][4][4];
#pragma unroll
    for (int mi = 0; mi < 4; mi++)
#pragma unroll
        for (int ni = 0; ni < 4; ni++)
#pragma unroll
            for (int j = 0; j < 4; j++) acc[mi][ni][j] = 0.f;

    for (int c = 0; c < nc; c++) {
        CPA_WAIT1();                     // chunk c complete (this thread)
        __syncthreads();                 // ...and visible CTA-wide

        uint32_t sA = sb + (c % 3) * (G7STAGE * 2);
        uint32_t sW = sA + G7TILE * 2;
#pragma unroll
        for (int ks = 0; ks < 4; ks++) {
            unsigned a[4][4], b[4][2];
#pragma unroll
            for (int mi = 0; mi < 4; mi++)
                ldsm_x4(a[mi], sA + ((wm + mi * 16 + ra) * G7STR + ks * 16 + ca) * 2);
            {
                unsigned bt[4];
                ldsm_x4(bt, sW + ((wn + rb) * G7STR + ks * 16 + cb) * 2);
                b[0][0] = bt[0]; b[0][1] = bt[1]; b[1][0] = bt[2]; b[1][1] = bt[3];
                ldsm_x4(bt, sW + ((wn + 16 + rb) * G7STR + ks * 16 + cb) * 2);
                b[2][0] = bt[0]; b[2][1] = bt[1]; b[3][0] = bt[2]; b[3][1] = bt[3];
            }
#pragma unroll
            for (int mi = 0; mi < 4; mi++)
#pragma unroll
                for (int ni = 0; ni < 4; ni++)
                    mma_f16(acc[mi][ni], a[mi], b[ni]);
        }

        if (c + 2 < nc) load_chunk(c + 2, (c + 2) % 3);
        CPA_COMMIT();                    // unconditional: keeps wait_group(1) valid
    }

#pragma unroll
    for (int mi = 0; mi < 4; mi++) {
#pragma unroll
        for (int ni = 0; ni < 4; ni++) {
            int r  = m0 + wm + mi * 16 + gid;
            int cn = n0 + wn + ni * 8 + 2 * tig;
            float b0 = bias[cn], b1 = bias[cn + 1];
#pragma unroll
            for (int hf = 0; hf < 2; hf++) {
                int rr = r + hf * 8;
                float v0 = acc[mi][ni][hf * 2 + 0] + b0;
                float v1 = acc[mi][ni][hf * 2 + 1] + b1;
                if (RES) {
                    const float* cp = C + (size_t)rr * N + cn;
                    v0 += cp[0]; v1 += cp[1];
                }
                if (RELU) { v0 = fmaxf(v0, 0.f); v1 = fmaxf(v1, 0.f); }
                if (HOUT) {
                    *(__half2*)(H + (size_t)rr * N + cn) = __floats2half2_rn(v0, v1);
                } else {
                    float* cp = C + (size_t)rr * N + cn;
                    cp[0] = v0; cp[1] = v1;
                }
            }
        }
    }
}

// ---------------------------------------------------------------------------
// gemm6 (proven R14): BM=64, BN=256, BK=32, LN fused epilogue. grid.x==1.
// ---------------------------------------------------------------------------
#define G6STR   40
#define G6ROWS  320
#define G6STAGE (G6ROWS * G6STR)
#define G6SMEM  (3 * G6STAGE * 2)

template<bool RES, bool LNF>
__global__ void __launch_bounds__(256, 2) gemm6(
        const __half* __restrict__ A, const __half* __restrict__ W,
        const float* __restrict__ bias, float* __restrict__ C,
        const float* __restrict__ lnw, const float* __restrict__ lnb,
        __half* __restrict__ Y, int M, int K) {
    extern __shared__ __half smh[];
    const uint32_t sb = smem_u32(smh);
    const int N = 256;

    const int t = threadIdx.x;
    const int lane = t & 31, gid = lane >> 2, tig = lane & 3;
    const int wid = t >> 5;
    const int wm = (wid & 1) * 32;
    const int wn = (wid >> 1) * 64;
    const int wcol = wid >> 1;
    const int m0 = blockIdx.y * 64;
    const int nc = K >> 5;

    const int ra = ((lane & 8) ? 8 : 0) + (lane & 7);
    const int ca = (lane & 16) ? 8 : 0;
    const int rb = ((lane & 16) ? 8 : 0) + (lane & 7);
    const int cb = (lane & 8) ? 8 : 0;

    auto load_chunk = [&](int c, int s) {
        int k0 = c * 32;
        uint32_t base = sb + (s * G6STAGE) * 2;
#pragma unroll
        for (int i = 0; i < 5; i++) {
            int u = i * 256 + t;
            int r = u >> 2, q = u & 3;
            const __half* src = (r < 64)
                ? A + (size_t)(m0 + r) * K + k0 + q * 8
                : W + (size_t)(r - 64) * K + k0 + q * 8;
            CPA16(base + (r * G6STR + q * 8) * 2, src);
        }
    };

    load_chunk(0, 0); CPA_COMMIT();
    load_chunk(1, 1); CPA_COMMIT();

    float acc[2][8][4];
#pragma unroll
    for (int mi = 0; mi < 2; mi++)
#pragma unroll
        for (int ni = 0; ni < 8; ni++)
#pragma unroll
            for (int j = 0; j < 4; j++) acc[mi][ni][j] = 0.f;

    for (int c = 0; c < nc; c++) {
        CPA_WAIT1();
        __syncthreads();

        uint32_t sA = sb + (c % 3) * (G6STAGE * 2);
        uint32_t sW = sA + 64 * G6STR * 2;
#pragma unroll
        for (int ks = 0; ks < 2; ks++) {
            unsigned a[2][4], b[8][2];
#pragma unroll
            for (int mi = 0; mi < 2; mi++)
                ldsm_x4(a[mi], sA + ((wm + mi * 16 + ra) * G6STR + ks * 16 + ca) * 2);
#pragma unroll
            for (int nb = 0; nb < 4; nb++) {
                unsigned bt[4];
                ldsm_x4(bt, sW + ((wn + nb * 16 + rb) * G6STR + ks * 16 + cb) * 2);
                b[2 * nb][0]     = bt[0]; b[2 * nb][1]     = bt[1];
                b[2 * nb + 1][0] = bt[2]; b[2 * nb + 1][1] = bt[3];
            }
#pragma unroll
            for (int mi = 0; mi < 2; mi++)
#pragma unroll
                for (int ni = 0; ni < 8; ni++)
                    mma_f16(acc[mi][ni], a[mi], b[ni]);
        }

        if (c + 2 < nc) load_chunk(c + 2, (c + 2) % 3);
        CPA_COMMIT();
    }

    __syncthreads();
    float* red = (float*)smh;

    float s_[2][2], q_[2][2];
#pragma unroll
    for (int mi = 0; mi < 2; mi++) { s_[mi][0] = s_[mi][1] = q_[mi][0] = q_[mi][1] = 0.f; }

#pragma unroll
    for (int mi = 0; mi < 2; mi++) {
#pragma unroll
        for (int ni = 0; ni < 8; ni++) {
            int cn = wn + ni * 8 + 2 * tig;
            float b0 = bias[cn], b1 = bias[cn + 1];
#pragma unroll
            for (int hf = 0; hf < 2; hf++) {
                int rr = m0 + wm + mi * 16 + gid + hf * 8;
                float v0 = acc[mi][ni][hf * 2 + 0] + b0;
                float v1 = acc[mi][ni][hf * 2 + 1] + b1;
                if (RES) {
                    const float* cp = C + (size_t)rr * N + cn;
                    v0 += cp[0]; v1 += cp[1];
                }
                float* cp = C + (size_t)rr * N + cn;
                cp[0] = v0; cp[1] = v1;
                acc[mi][ni][hf * 2 + 0] = v0;
                acc[mi][ni][hf * 2 + 1] = v1;
                if (LNF) {
                    s_[mi][hf] += v0 + v1;
                    q_[mi][hf] += v0 * v0 + v1 * v1;
                }
            }
        }
    }

    if (LNF) {
#pragma unroll
        for (int mi = 0; mi < 2; mi++)
#pragma unroll
            for (int hf = 0; hf < 2; hf++) {
                s_[mi][hf] += __shfl_xor_sync(0xffffffffu, s_[mi][hf], 1);
                s_[mi][hf] += __shfl_xor_sync(0xffffffffu, s_[mi][hf], 2);
                q_[mi][hf] += __shfl_xor_sync(0xffffffffu, q_[mi][hf], 1);
                q_[mi][hf] += __shfl_xor_sync(0xffffffffu, q_[mi][hf], 2);
            }
        if (tig == 0) {
#pragma unroll
            for (int mi = 0; mi < 2; mi++)
#pragma unroll
                for (int hf = 0; hf < 2; hf++) {
                    int rl = wm + mi * 16 + gid + hf * 8;
                    red[rl * 8 + wcol * 2 + 0] = s_[mi][hf];
                    red[rl * 8 + wcol * 2 + 1] = q_[mi][hf];
                }
        }
        __syncthreads();
#pragma unroll
        for (int mi = 0; mi < 2; mi++) {
#pragma unroll
            for (int hf = 0; hf < 2; hf++) {
                int rl = wm + mi * 16 + gid + hf * 8;
                float su = 0.f, sq = 0.f;
#pragma unroll
                for (int w = 0; w < 4; w++) {
                    su += red[rl * 8 + w * 2];
                    sq += red[rl * 8 + w * 2 + 1];
                }
                float mean = su * (1.f / 256.f);
                float var  = sq * (1.f / 256.f) - mean * mean;
                float rstd = rsqrtf(var + 1e-5f);
                __half* yp = Y + (size_t)(m0 + rl) * N;
#pragma unroll
                for (int ni = 0; ni < 8; ni++) {
                    int cn = wn + ni * 8 + 2 * tig;
                    float v0 = acc[mi][ni][hf * 2 + 0];
                    float v1 = acc[mi][ni][hf * 2 + 1];
                    *(__half2*)(yp + cn) = __floats2half2_rn(
                        (v0 - mean) * rstd * lnw[cn] + lnb[cn],
                        (v1 - mean) * rstd * lnw[cn + 1] + lnb[cn + 1]);
                }
            }
        }
    }
}

// ---------------------------------------------------------------------------
__global__ void build_tok_ln(const float* __restrict__ cls, int B,
                             const float* __restrict__ w, const float* __restrict__ bb) {
    int tk = blockIdx.x;
    __shared__ int sbv;
    if (threadIdx.x == 0) {
        int lo = 0, hi = B - 1;
        while (lo < hi) {
            int mid = (lo + hi + 1) >> 1;
            if (g_start[mid] + mid <= tk) lo = mid; else hi = mid - 1;
        }
        sbv = lo;
    }
    __syncthreads();
    int b = sbv;
    int i = threadIdx.x;
    float v;
    if (tk == g_start[b] + b) v = cls[i];
    else                      v = g_att[(size_t)(tk - b - 1) * DM + i];
    g_tok[(size_t)tk * DM + i] = v;

    __shared__ float red[8];
    float s = v;
#pragma unroll
    for (int o = 16; o; o >>= 1) s += __shfl_xor_sync(0xffffffffu, s, o);
    if ((i & 31) == 0) red[i >> 5] = s;
    __syncthreads();
    float tot = 0.f;
#pragma unroll
    for (int k = 0; k < 8; k++) tot += red[k];
    float mean = tot * (1.f / DM);
    float d = v - mean;
    float s2 = d * d;
#pragma unroll
    for (int o = 16; o; o >>= 1) s2 += __shfl_xor_sync(0xffffffffu, s2, o);
    __syncthreads();
    if ((i & 31) == 0) red[i >> 5] = s2;
    __syncthreads();
    float tv = 0.f;
#pragma unroll
    for (int k = 0; k < 8; k++) tv += red[k];
    float var = tv * (1.f / DM);
    g_bufh[(size_t)tk * DM + i] = __float2half_rn(d * rsqrtf(var + 1e-5f) * w[i] + bb[i]);
}

// ---------------------------------------------------------------------------
// Ragged flash attention (proven R15): 128-row Q tiles, 256 threads.
// ---------------------------------------------------------------------------
#define MAXQC2 6
#define ASTR  72
#define AQ_REG (128 * ASTR)
#define AK_REG (64 * ASTR)
#define ATT_SMEM ((AQ_REG + 2 * AK_REG + AQ_REG) * 2)

__global__ void __launch_bounds__(256) attn_h() {
    extern __shared__ __half ash[];
    __half* Qs = ash;
    __half* Ks = Qs + AQ_REG;
    __half* Vs = Ks + AK_REG;
    __half* Ps = Vs + AK_REG;
    const uint32_t sbQ = smem_u32(ash);
    const uint32_t sbK = sbQ + AQ_REG * 2;
    const uint32_t sbV = sbK + AK_REG * 2;
    const uint32_t sbP = sbV + AK_REG * 2;

    int b  = blockIdx.x, h = blockIdx.y;
    int s0 = g_start[b];
    int L  = g_start[b + 1] - s0 + 1;
    int qc = blockIdx.z * 128;
    if (qc >= L) return;
    int t0 = s0 + b;

    int t = threadIdx.x, lane = t & 31, wid = t >> 5;
    int gid = lane >> 2, tig = lane & 3;
    int wm = wid * 16;

    const int ra = ((lane & 8) ? 8 : 0) + (lane & 7);
    const int ca = (lane & 16) ? 8 : 0;
    const int rb = ((lane & 16) ? 8 : 0) + (lane & 7);
    const int cb = (lane & 8) ? 8 : 0;

    {
        int lr = t >> 1, lc = (t & 1) * 32;
        bool v = (qc + lr) < L;
        const __half* qp = g_qkvh + (size_t)(t0 + qc + lr) * 768 + h * HDIM + lc;
        __half* d = Qs + lr * ASTR + lc;
        uint4 z = make_uint4(0, 0, 0, 0);
#pragma unroll
        for (int u = 0; u < 4; u++)
            *(uint4*)(d + u * 8) = v ? *(const uint4*)(qp + u * 8) : z;
    }

    float mr0 = -1e30f, mr1 = -1e30f, l0 = 0.f, l1 = 0.f;
    float O[8][4];
#pragma unroll
    for (int ni = 0; ni < 8; ni++)
#pragma unroll
        for (int j = 0; j < 4; j++) O[ni][j] = 0.f;

    const float scale = 0.125f;

    for (int kc = 0; kc < L; kc += 64) {
        __syncthreads();
        {
            int lr = t >> 2, lc = (t & 3) * 16;
            bool v = (kc + lr) < L;
            const __half* kp = g_qkvh + (size_t)(t0 + kc + lr) * 768 + 256 + h * HDIM + lc;
            const __half* vp = kp + 256;
            __half* kd = Ks + lr * ASTR + lc;
            __half* vd = Vs + lr * ASTR + lc;
            uint4 z = make_uint4(0, 0, 0, 0);
#pragma unroll
            for (int u = 0; u < 2; u++) {
                *(uint4*)(kd + u * 8) = v ? *(const uint4*)(kp + u * 8) : z;
                *(uint4*)(vd + u * 8) = v ? *(const uint4*)(vp + u * 8) : z;
            }
        }
        __syncthreads();

        float S[8][4];
#pragma unroll
        for (int ni = 0; ni < 8; ni++)
#pragma unroll
            for (int j = 0; j < 4; j++) S[ni][j] = 0.f;
#pragma unroll
        for (int ks = 0; ks < 4; ks++) {
            unsigned a[4];
            ldsm_x4(a, sbQ + ((wm + ra) * ASTR + ks * 16 + ca) * 2);
#pragma unroll
            for (int nb = 0; nb < 8; nb += 2) {
                unsigned bt[4];
                ldsm_x4(bt, sbK + ((nb * 8 + rb) * ASTR + ks * 16 + cb) * 2);
                mma_f16(S[nb],     a, bt);
                mma_f16(S[nb + 1], a, bt + 2);
            }
        }

        float rm0 = -1e30f, rm1 = -1e30f;
#pragma unroll
        for (int ni = 0; ni < 8; ni++) {
            int j0 = kc + ni * 8 + 2 * tig;
            bool v0 = j0 < L, v1 = (j0 + 1) < L;
            S[ni][0] = v0 ? S[ni][0] * scale : -1e30f;
            S[ni][1] = v1 ? S[ni][1] * scale : -1e30f;
            S[ni][2] = v0 ? S[ni][2] * scale : -1e30f;
            S[ni][3] = v1 ? S[ni][3] * scale : -1e30f;
            rm0 = fmaxf(rm0, fmaxf(S[ni][0], S[ni][1]));
            rm1 = fmaxf(rm1, fmaxf(S[ni][2], S[ni][3]));
        }
        rm0 = fmaxf(rm0, __shfl_xor_sync(0xffffffffu, rm0, 1));
        rm0 = fmaxf(rm0, __shfl_xor_sync(0xffffffffu, rm0, 2));
        rm1 = fmaxf(rm1, __shfl_xor_sync(0xffffffffu, rm1, 1));
        rm1 = fmaxf(rm1, __shfl_xor_sync(0xffffffffu, rm1, 2));
        float mn0 = fmaxf(mr0, rm0), mn1 = fmaxf(mr1, rm1);
        float cr0 = __expf(mr0 - mn0), cr1 = __expf(mr1 - mn1);
        float sum0 = 0.f, sum1 = 0.f;
        __half* pr0 = Ps + (wm + gid) * ASTR;
        __half* pr1 = Ps + (wm + gid + 8) * ASTR;
#pragma unroll
        for (int ni = 0; ni < 8; ni++) {
            int col = ni * 8 + 2 * tig;
            float p0 = __expf(S[ni][0] - mn0);
            float p1 = __expf(S[ni][1] - mn0);
            float p2 = __expf(S[ni][2] - mn1);
            float p3 = __expf(S[ni][3] - mn1);
            sum0 += p0 + p1; sum1 += p2 + p3;
            *(__half2*)(pr0 + col) = __floats2half2_rn(p0, p1);
            *(__half2*)(pr1 + col) = __floats2half2_rn(p2, p3);
        }
        sum0 += __shfl_xor_sync(0xffffffffu, sum0, 1);
        sum0 += __shfl_xor_sync(0xffffffffu, sum0, 2);
        sum1 += __shfl_xor_sync(0xffffffffu, sum1, 1);
        sum1 += __shfl_xor_sync(0xffffffffu, sum1, 2);
        l0 = l0 * cr0 + sum0;
        l1 = l1 * cr1 + sum1;
        mr0 = mn0; mr1 = mn1;
#pragma unroll
        for (int ni = 0; ni < 8; ni++) {
            O[ni][0] *= cr0; O[ni][1] *= cr0;
            O[ni][2] *= cr1; O[ni][3] *= cr1;
        }
        __syncwarp();

#pragma unroll
        for (int ks = 0; ks < 4; ks++) {
            unsigned a[4];
            ldsm_x4(a, sbP + ((wm + ra) * ASTR + ks * 16 + ca) * 2);
#pragma unroll
            for (int nb = 0; nb < 8; nb += 2) {
                unsigned bt[4];
                ldsm_x4t(bt, sbV + ((ks * 16 + ra) * ASTR + nb * 8 + ca) * 2);
                mma_f16(O[nb],     a, bt);
                mma_f16(O[nb + 1], a, bt + 2);
            }
        }
        __syncwarp();
    }

    float inv0 = 1.f / l0, inv1 = 1.f / l1;
    int q0 = qc + wm + gid, q1 = q0 + 8;
#pragma unroll
    for (int ni = 0; ni < 8; ni++) {
        int col = h * HDIM + ni * 8 + 2 * tig;
        if (q0 < L)
            *(__half2*)(g_bufh + (size_t)(t0 + q0) * DM + col) =
                __floats2half2_rn(O[ni][0] * inv0, O[ni][1] * inv0);
        if (q1 < L)
            *(__half2*)(g_bufh + (size_t)(t0 + q1) * DM + col) =
                __floats2half2_rn(O[ni][2] * inv1, O[ni][3] * inv1);
    }
}

// ---------------------------------------------------------------------------
__global__ void gather_cls() {
    int b = blockIdx.x, d = threadIdx.x;
    g_bufh[(size_t)b * DM + d] = __float2half_rn(g_tok[(size_t)(g_start[b] + b) * DM + d]);
}

__global__ void head2_kernel(const float* __restrict__ hid, const float* __restrict__ w2,
                             const float* __restrict__ b2, float* __restrict__ out, int B) {
    int t = blockIdx.x * blockDim.x + threadIdx.x;
    if (t >= B * 2) return;
    int b = t >> 1, j = t & 1;
    const float* hr = hid + (size_t)b * DM;
    const float* wr = w2 + (size_t)j * DM;
    float s = 0.f;
#pragma unroll 8
    for (int k = 0; k < DM; k++) s += hr[k] * wr[k];
    out[t] = s + b2[j];
}

// ---------------------------------------------------------------------------
extern "C" void kernel_launch(void* const* d_in, const int* in_sizes, int n_in,
                              void* d_out, int out_size) {
    const float* dom_emb = (const float*)d_in[0];
    const int*   ev      = (const int*)  d_in[1];
    const float* geom    = (const float*)d_in[3];
    const float* in_b    = (const float*)d_in[5];
    const float* geo_b   = (const float*)d_in[7];
    const float* cls     = (const float*)d_in[8];
    const float* qkv_b   = (const float*)d_in[10];
    const float* out_b   = (const float*)d_in[12];
    const float* ln1w    = (const float*)d_in[13];
    const float* ln1b    = (const float*)d_in[14];
    const float* ln2w    = (const float*)d_in[15];
    const float* ln2b    = (const float*)d_in[16];
    const float* ffb1    = (const float*)d_in[18];
    const float* ffb2    = (const float*)d_in[20];
    const float* hb1     = (const float*)d_in[22];
    const float* hw2     = (const float*)d_in[23];
    const float* hb2     = (const float*)d_in[24];
    float* out = (float*)d_out;

    int N  = in_sizes[0] / D_INP;
    int B  = out_size / 2;
    int NT = N + B;

    float  *p_tok, *p_att, *p_b2;
    __half *p_bufh, *p_qkvh, *p_ffh, *p_wh;
    cudaGetSymbolAddress((void**)&p_tok,  g_tok);
    cudaGetSymbolAddress((void**)&p_att,  g_att);
    cudaGetSymbolAddress((void**)&p_bufh, g_bufh);
    cudaGetSymbolAddress((void**)&p_qkvh, g_qkvh);
    cudaGetSymbolAddress((void**)&p_ffh,  g_ffh);
    cudaGetSymbolAddress((void**)&p_wh,   g_wtsh);
    cudaGetSymbolAddress((void**)&p_b2,   g_bias2);

    static bool attrs_done = false;
    if (!attrs_done) {
        cudaFuncSetAttribute(gemm7<false, false, true,  false>, cudaFuncAttributeMaxDynamicSharedMemorySize, G7SMEM);
        cudaFuncSetAttribute(gemm7<true,  false, true,  false>, cudaFuncAttributeMaxDynamicSharedMemorySize, G7SMEM);
        cudaFuncSetAttribute(gemm7<false, false, false, true >, cudaFuncAttributeMaxDynamicSharedMemorySize, G7SMEM);
        cudaFuncSetAttribute(gemm7<true,  false, false, false>, cudaFuncAttributeMaxDynamicSharedMemorySize, G7SMEM);
        cudaFuncSetAttribute(gemm6<true,  true >, cudaFuncAttributeMaxDynamicSharedMemorySize, G6SMEM);
        cudaFuncSetAttribute(gemm6<true,  false>, cudaFuncAttributeMaxDynamicSharedMemorySize, G6SMEM);
        cudaFuncSetAttribute(attn_h, cudaFuncAttributeMaxDynamicSharedMemorySize, ATT_SMEM);
        attrs_done = true;
    }

    // ---- setup: exactly 5 launches, so #6 = embedding gemm7 (profiled) ----
    {
        int na0 = NL * 3 * DM * DM, na1 = NL * DM * DM, na2 = NL * DFF * DM, na3 = NL * DM * DFF;
        int ta = na0 + na1 + na2 + na3;
        cvt4<<<(ta + 255) / 256, 256>>>(
            (const float*)d_in[9],  na0, (const float*)d_in[11], na1,
            (const float*)d_in[17], na2, (const float*)d_in[19], na3, p_wh + W_QKV);   // (1)
        cvt_half<<<(DM * DM + 255) / 256, 256>>>((const float*)d_in[21], p_wh + W_HEAD, DM * DM); // (2)
        repack_emb<<<(DM * 384 + 255) / 256, 256>>>(
            (const float*)d_in[4], (const float*)d_in[6], in_b, geo_b, p_wh + W_EMB);  // (3)
    }
    starts_kernel<<<(N + 255) / 256, 256>>>(ev, N, B);                                 // (4)
    posenc_kernel<<<N, 128>>>(geom, dom_emb);                                          // (5)

    int mg  = NT / 128;
    int mgN = N / 128;

    // fused embedding: [emb|posenc] @ [in_w|geo_w]^T + (in_b+geo_b) -> g_att
    gemm7<false, false, false, true><<<dim3(DM / 128, mgN), 256, G7SMEM>>>(
        p_ffh, p_bufh, p_wh + W_EMB, p_b2, p_att, nullptr, N, DM, 384);                // (6) profiled
    build_tok_ln<<<NT, 256>>>(cls, B, ln1w, ln1b);

    for (int l = 0; l < NL; l++) {
        gemm7<false, false, true, false><<<dim3(3 * DM / 128, mg), 256, G7SMEM>>>(
            p_bufh, nullptr, p_wh + W_QKV + (size_t)l * 3 * DM * DM,
            qkv_b + (size_t)l * 3 * DM, nullptr, p_qkvh, NT, 3 * DM, DM);
        attn_h<<<dim3(B, NH, MAXQC2), 256, ATT_SMEM>>>();
        gemm6<true, true><<<dim3(1, NT / 64), 256, G6SMEM>>>(
            p_bufh, p_wh + W_OUT + (size_t)l * DM * DM, out_b + (size_t)l * DM,
            p_tok, ln2w + l * DM, ln2b + l * DM, p_bufh, NT, DM);
        gemm7<true, false, true, false><<<dim3(DFF / 128, mg), 256, G7SMEM>>>(
            p_bufh, nullptr, p_wh + W_FF1 + (size_t)l * DFF * DM,
            ffb1 + (size_t)l * DFF, nullptr, p_ffh, NT, DFF, DM);
        if (l < NL - 1) {
            gemm6<true, true><<<dim3(1, NT / 64), 256, G6SMEM>>>(
                p_ffh, p_wh + W_FF2 + (size_t)l * DM * DFF, ffb2 + (size_t)l * DM,
                p_tok, ln1w + (l + 1) * DM, ln1b + (l + 1) * DM, p_bufh, NT, DFF);
        } else {
            gemm6<true, false><<<dim3(1, NT / 64), 256, G6SMEM>>>(
                p_ffh, p_wh + W_FF2 + (size_t)l * DM * DFF, ffb2 + (size_t)l * DM,
                p_tok, nullptr, nullptr, nullptr, NT, DFF);
        }
    }

    gather_cls<<<B, 256>>>();
    gemm7<true, false, false, false><<<dim3(DM / 128, 1), 256, G7SMEM>>>(
        p_bufh, nullptr, p_wh + W_HEAD, hb1, p_att, nullptr, B, DM, DM);
    head2_kernel<<<1, 256>>>(p_att, hw2, hb2, out, B);
}